// round 11
// baseline (speedup 1.0000x reference)
#include <cuda_runtime.h>
#include <cuda_bf16.h>
#include <math.h>
#include <stdint.h>

// ---------------------------------------------------------------------------
// Problem constants
// ---------------------------------------------------------------------------
#define TOK   50176      // 2*8*56*56
#define CDIM  128
#define CH    512
#define NWIN  512        // 2 * 4*8*8
#define NTOK  98         // 2*7*7
#define NH    4
#define HD    32
#define QKVN  384

typedef __nv_bfloat16  bf16;
typedef __nv_bfloat162 bf162;

// ---------------------------------------------------------------------------
// Scratch (device globals: allocation-free, graph-capture safe)
// ---------------------------------------------------------------------------
__device__ bf16  g_xw  [(size_t)TOK * CDIM];   // LN2 out (spatial, bf16)
__device__ bf16  g_qkv [(size_t)TOK * QKVN];   // qkv, window order
__device__ bf16  g_attn[(size_t)TOK * CDIM];   // attention out, window order
__device__ float g_x2  [(size_t)TOK * CDIM];   // x + proj (spatial, fp32)
__device__ bf16  g_h   [(size_t)TOK * CH];     // fc1 output
__device__ float g_bias[NH * NTOK * NTOK];     // gathered attention bias (fp32)
// bf16 weights
__device__ bf16  g_wq[QKVN * CDIM];
__device__ bf16  g_wp[CDIM * CDIM];
__device__ bf16  g_w1[CH * CDIM];
__device__ bf16  g_w2[CDIM * CH];

// ---------------------------------------------------------------------------
// index helpers
// ---------------------------------------------------------------------------
__device__ __forceinline__ long win_to_spatial(long row) {
    int w = (int)(row / NTOK);
    int n = (int)(row % NTOK);
    int b   = w >> 8;
    int rem = w & 255;
    int wdi = rem >> 6, whi = (rem >> 3) & 7, wwi = rem & 7;
    int zd = n / 49; int r2 = n % 49; int zh = r2 / 7, zw = r2 % 7;
    int d  = wdi * 2 + zd;
    int hh = whi * 7 + zh;
    int xx = wwi * 7 + zw;
    return (((long)(b * 8 + d) * 56) + hh) * 56 + xx;
}

// ---------------------------------------------------------------------------
// async copy + ldmatrix + mma helpers
// ---------------------------------------------------------------------------
__device__ __forceinline__ void cp_async16(bf16* smem_dst, const bf16* gmem_src) {
    uint32_t s = (uint32_t)__cvta_generic_to_shared(smem_dst);
    asm volatile("cp.async.cg.shared.global [%0], [%1], 16;\n" :: "r"(s), "l"(gmem_src));
}
__device__ __forceinline__ void cp_commit() { asm volatile("cp.async.commit_group;\n"); }
template<int N>
__device__ __forceinline__ void cp_wait() { asm volatile("cp.async.wait_group %0;\n" :: "n"(N)); }

__device__ __forceinline__ void ldsm_x4(uint32_t r[4], const bf16* p) {
    uint32_t a = (uint32_t)__cvta_generic_to_shared(p);
    asm volatile("ldmatrix.sync.aligned.m8n8.x4.shared.b16 {%0,%1,%2,%3}, [%4];\n"
                 : "=r"(r[0]), "=r"(r[1]), "=r"(r[2]), "=r"(r[3]) : "r"(a));
}
__device__ __forceinline__ void ldsm_x4_t(uint32_t r[4], const bf16* p) {
    uint32_t a = (uint32_t)__cvta_generic_to_shared(p);
    asm volatile("ldmatrix.sync.aligned.m8n8.x4.trans.shared.b16 {%0,%1,%2,%3}, [%4];\n"
                 : "=r"(r[0]), "=r"(r[1]), "=r"(r[2]), "=r"(r[3]) : "r"(a));
}
__device__ __forceinline__ void mma_bf16(float c[4], const uint32_t a[4], const uint32_t b[2]) {
    asm volatile(
        "mma.sync.aligned.m16n8k16.row.col.f32.bf16.bf16.f32 "
        "{%0,%1,%2,%3}, {%4,%5,%6,%7}, {%8,%9}, {%0,%1,%2,%3};\n"
        : "+f"(c[0]), "+f"(c[1]), "+f"(c[2]), "+f"(c[3])
        : "r"(a[0]), "r"(a[1]), "r"(a[2]), "r"(a[3]), "r"(b[0]), "r"(b[1]));
}

__device__ __forceinline__ uint32_t pack_bf2(float a, float b) {
    bf162 p = __float22bfloat162_rn(make_float2(a, b));
    return *(uint32_t*)&p;
}

// ---------------------------------------------------------------------------
// merged setup: weight conversion fp32->bf16 (float4 units 0..49151)
//               + bias gather (units 49152..49152+38415)
// ---------------------------------------------------------------------------
#define CVT_UNITS  49152
#define BIAS_UNITS (NH * NTOK * NTOK)   // 38416
__global__ void setup_kernel(const float* __restrict__ wq,
                             const float* __restrict__ wp,
                             const float* __restrict__ w1,
                             const float* __restrict__ w2,
                             const float* __restrict__ bias_table,
                             const int* __restrict__ rel_index) {
    int i = blockIdx.x * blockDim.x + threadIdx.x;
    if (i < CVT_UNITS) {
        const float* src; bf16* dst; int off;
        if (i < 12288)      { src = wq; dst = g_wq; off = i; }
        else if (i < 16384) { src = wp; dst = g_wp; off = i - 12288; }
        else if (i < 32768) { src = w1; dst = g_w1; off = i - 16384; }
        else                { src = w2; dst = g_w2; off = i - 32768; }
        float4 v = *(const float4*)(src + off * 4);
        uint2 u = make_uint2(pack_bf2(v.x, v.y), pack_bf2(v.z, v.w));
        *(uint2*)(dst + off * 4) = u;
    } else {
        int j = i - CVT_UNITS;
        if (j < BIAS_UNITS) {
            int h = j / (NTOK * NTOK);
            int r = j % (NTOK * NTOK);
            g_bias[j] = bias_table[rel_index[r] * NH + h];
        }
    }
}

// ---------------------------------------------------------------------------
// QKV GEMM with FUSED LN1 + window-partition prologue.
// C[M,384] = LN1(x[perm])[M,128] @ Wq[384,128]^T, q-part scaled.
// A tile resident in smem ([128][136] bf16, built by LN prologue);
// W pipelined 3-stage (BK=32). 256 threads, 8 warps (2x4), warp 64x32.
// ---------------------------------------------------------------------------
#define GS  40                  // W stage row stride (halves): 32 + 8 pad
#define QGS 136                 // A resident row stride (halves): 128 + 8 pad
#define QKV_SMEM ((128 * QGS + 3 * 128 * GS) * 2)   // 65536 B

__global__ __launch_bounds__(256, 2)
void qkv_ln_kernel(const float* __restrict__ x,
                   const bf16* __restrict__ Wt,
                   const float* __restrict__ gam,
                   const float* __restrict__ bet,
                   const float* __restrict__ bias,
                   bf16* __restrict__ C) {
    extern __shared__ bf16 sm[];
    bf16* As = sm;                                   // [128][136]
    bf16* Wsb[3] = { sm + 128 * QGS,
                     sm + 128 * QGS + 128 * GS,
                     sm + 128 * QGS + 2 * 128 * GS };

    const int tid  = threadIdx.x;
    const int lane = tid & 31;
    const int warp = tid >> 5;
    const int warpM = warp >> 2;        // 0..1
    const int warpN = warp & 3;         // 0..3
    const int gid = lane >> 2;          // 0..7
    const int tig = lane & 3;           // 0..3

    const long rowBase = (long)blockIdx.y * 128;
    const int  colBase = blockIdx.x * 128;

    // W loader: 4 threads per row pair-chunk (same mapping as R5 gemm)
    const int ld_row = tid >> 2;        // 0..63
    const int ld_kq  = (tid & 3) * 8;
    auto load_w = [&](int buf, int k0) {
        #pragma unroll
        for (int r = 0; r < 2; r++) {
            int n = ld_row + r * 64;
            cp_async16(&Wsb[buf][n * GS + ld_kq], Wt + (long)(colBase + n) * CDIM + k0 + ld_kq);
        }
    };
    load_w(0, 0);  cp_commit();
    load_w(1, 32); cp_commit();

    // ---- LN1 prologue: 2 threads per row (half = 64 channels each) ----
    {
        int row  = tid >> 1;
        int half = tid & 1;
        long s = win_to_spatial(rowBase + row);
        const float* xr = x + s * CDIM + half * 64;
        float sum = 0.f, sq = 0.f;
        #pragma unroll
        for (int j = 0; j < 16; j++) {
            float4 v = *(const float4*)(xr + j * 4);
            sum += (v.x + v.y) + (v.z + v.w);
            sq  += v.x * v.x + v.y * v.y + v.z * v.z + v.w * v.w;
        }
        sum += __shfl_xor_sync(0xffffffffu, sum, 1);
        sq  += __shfl_xor_sync(0xffffffffu, sq,  1);
        float mean = sum * (1.0f / CDIM);
        float rstd = rsqrtf(sq * (1.0f / CDIM) - mean * mean + 1e-5f);
        #pragma unroll
        for (int j = 0; j < 16; j++) {
            float4 v = *(const float4*)(xr + j * 4);     // L1 hit (2nd pass)
            int col = half * 64 + j * 4;
            float4 g = *(const float4*)(gam + col);
            float4 b = *(const float4*)(bet + col);
            uint2 u = make_uint2(
                pack_bf2((v.x - mean) * rstd * g.x + b.x, (v.y - mean) * rstd * g.y + b.y),
                pack_bf2((v.z - mean) * rstd * g.z + b.z, (v.w - mean) * rstd * g.w + b.w));
            *(uint2*)(As + row * QGS + col) = u;
        }
    }

    float cc[4][4][4];
    #pragma unroll
    for (int mi = 0; mi < 4; mi++)
        #pragma unroll
        for (int ni = 0; ni < 4; ni++)
            #pragma unroll
            for (int e = 0; e < 4; e++) cc[mi][ni][e] = 0.f;

    const int a_r = (lane & 7) + ((lane >> 3) & 1) * 8;
    const int a_k = (lane >> 4) * 8;
    const int b_n = (lane & 7) + (lane >> 4) * 8;
    const int b_k = ((lane >> 3) & 1) * 8;

    #pragma unroll
    for (int it = 0; it < 4; it++) {
        if (it < 3) cp_wait<1>(); else cp_wait<0>();
        __syncthreads();    // first iter also publishes LN prologue As writes
        if (it + 2 < 4) { load_w((it + 2) % 3, (it + 2) * 32); cp_commit(); }

        const bf16* Ws = Wsb[it % 3];
        const int kbase = it * 32;
        #pragma unroll
        for (int ks = 0; ks < 2; ks++) {
            const int ak = kbase + ks * 16;   // A offset within full K
            const int wk = ks * 16;           // W offset within stage
            uint32_t af[4][4];
            uint32_t bf[4][2];
            #pragma unroll
            for (int mi = 0; mi < 4; mi++)
                ldsm_x4(af[mi], As + (warpM * 64 + mi * 16 + a_r) * QGS + ak + a_k);
            #pragma unroll
            for (int np = 0; np < 2; np++) {
                uint32_t r4[4];
                ldsm_x4(r4, Ws + (warpN * 32 + np * 16 + b_n) * GS + wk + b_k);
                bf[2 * np][0] = r4[0]; bf[2 * np][1] = r4[1];
                bf[2 * np + 1][0] = r4[2]; bf[2 * np + 1][1] = r4[3];
            }
            #pragma unroll
            for (int mi = 0; mi < 4; mi++)
                #pragma unroll
                for (int ni = 0; ni < 4; ni++)
                    mma_bf16(cc[mi][ni], af[mi], bf[ni]);
        }
    }

    // epilogue: +bias, scale q-part (colBase==0), bf16 out
    #pragma unroll
    for (int mi = 0; mi < 4; mi++) {
        #pragma unroll
        for (int half = 0; half < 2; half++) {
            long row = rowBase + warpM * 64 + mi * 16 + gid + half * 8;
            #pragma unroll
            for (int ni = 0; ni < 4; ni++) {
                int col = colBase + warpN * 32 + ni * 8 + 2 * tig;
                float v0 = cc[mi][ni][half * 2 + 0] + bias[col];
                float v1 = cc[mi][ni][half * 2 + 1] + bias[col + 1];
                if (colBase == 0) { v0 *= 0.17677669529663687f; v1 *= 0.17677669529663687f; }
                *(uint32_t*)(C + row * (long)QKVN + col) = pack_bf2(v0, v1);
            }
        }
    }
}

// ---------------------------------------------------------------------------
// BF16 GEMM (R5 exact): 128x128 block, BK=32, 3-stage cp.async, warp 64x32.
// MODE 1: proj -> +bias; permute; += resid(x); fp32 g_x2  AND fused LN2 -> bf16 g_xw
// MODE 2: fc1  -> +bias; exact GELU; bf16 out [M,512]
// MODE 3: fc2  -> +bias; += resid(g_x2); fp32 out d_out
// ---------------------------------------------------------------------------
#define G_STAGE (256 * GS)     // As(128)+Ws(128) rows per stage
template<int MODE, int KT>
__global__ __launch_bounds__(256, 2)
void gemm_kernel(const bf16* __restrict__ A,
                 const bf16* __restrict__ Wt,
                 const float* __restrict__ bias,
                 const float* __restrict__ resid,
                 const float* __restrict__ gam,
                 const float* __restrict__ bet,
                 void* __restrict__ Cv,
                 int N) {
    extern __shared__ bf16 sm[];
    bf16* Asb[3] = { sm, sm + G_STAGE, sm + 2 * G_STAGE };
    bf16* Wsb[3] = { sm + 128 * GS, sm + G_STAGE + 128 * GS, sm + 2 * G_STAGE + 128 * GS };

    const int tid  = threadIdx.x;
    const int lane = tid & 31;
    const int warp = tid >> 5;
    const int warpM = warp >> 2;        // 0..1
    const int warpN = warp & 3;         // 0..3
    const int gid = lane >> 2;          // 0..7
    const int tig = lane & 3;           // 0..3

    const long rowBase = (long)blockIdx.y * 128;
    const int  colBase = blockIdx.x * 128;
    const int  K = KT;

    float cc[4][4][4];
    #pragma unroll
    for (int mi = 0; mi < 4; mi++)
        #pragma unroll
        for (int ni = 0; ni < 4; ni++)
            #pragma unroll
            for (int e = 0; e < 4; e++) cc[mi][ni][e] = 0.f;

    const int ld_row = tid >> 2;        // 0..63
    const int ld_kq  = (tid & 3) * 8;   // halves

    auto load_tile = [&](int buf, int k0) {
        #pragma unroll
        for (int r = 0; r < 2; r++) {
            int m = ld_row + r * 64;
            cp_async16(&Asb[buf][m * GS + ld_kq], A + (rowBase + m) * K + k0 + ld_kq);
        }
        #pragma unroll
        for (int r = 0; r < 2; r++) {
            int n = ld_row + r * 64;
            cp_async16(&Wsb[buf][n * GS + ld_kq], Wt + (long)(colBase + n) * K + k0 + ld_kq);
        }
    };

    constexpr int nk = KT / 32;
    load_tile(0, 0);  cp_commit();
    load_tile(1, 32); cp_commit();

    const int a_r = (lane & 7) + ((lane >> 3) & 1) * 8;
    const int a_k = (lane >> 4) * 8;
    const int b_n = (lane & 7) + (lane >> 4) * 8;
    const int b_k = ((lane >> 3) & 1) * 8;

    #pragma unroll
    for (int it = 0; it < nk; it++) {
        if (it < nk - 1) cp_wait<1>(); else cp_wait<0>();
        __syncthreads();
        if (it + 2 < nk) { load_tile((it + 2) % 3, (it + 2) * 32); cp_commit(); }

        const bf16* As = Asb[it % 3];
        const bf16* Ws = Wsb[it % 3];
        #pragma unroll
        for (int ks = 0; ks < 2; ks++) {
            const int kk = ks * 16;
            uint32_t af[4][4];
            uint32_t bf[4][2];
            #pragma unroll
            for (int mi = 0; mi < 4; mi++)
                ldsm_x4(af[mi], As + (warpM * 64 + mi * 16 + a_r) * GS + kk + a_k);
            #pragma unroll
            for (int np = 0; np < 2; np++) {
                uint32_t r4[4];
                ldsm_x4(r4, Ws + (warpN * 32 + np * 16 + b_n) * GS + kk + b_k);
                bf[2 * np][0] = r4[0]; bf[2 * np][1] = r4[1];
                bf[2 * np + 1][0] = r4[2]; bf[2 * np + 1][1] = r4[3];
            }
            #pragma unroll
            for (int mi = 0; mi < 4; mi++)
                #pragma unroll
                for (int ni = 0; ni < 4; ni++)
                    mma_bf16(cc[mi][ni], af[mi], bf[ni]);
        }
    }

    if (MODE == 1) {
        // fused: x2 = resid + proj_out (+bias), write fp32 g_x2;
        // then LayerNorm(x2) over full 128-col rows -> bf16 g_xw.
        __syncthreads();                 // all warps done with smem stages
        float* red = (float*)sm;         // [128][2] row sums
        if (tid < 128) { red[2 * tid] = 0.f; red[2 * tid + 1] = 0.f; }
        __syncthreads();

        long orows[4][2];
        float* C = (float*)Cv;
        #pragma unroll
        for (int mi = 0; mi < 4; mi++) {
            #pragma unroll
            for (int half = 0; half < 2; half++) {
                int rloc = warpM * 64 + mi * 16 + gid + half * 8;
                long orow = win_to_spatial(rowBase + rloc);
                orows[mi][half] = orow;
                float s = 0.f, sq = 0.f;
                #pragma unroll
                for (int ni = 0; ni < 4; ni++) {
                    int col = warpN * 32 + ni * 8 + 2 * tig;
                    const float2 r = *(const float2*)(resid + orow * CDIM + col);
                    float v0 = cc[mi][ni][half * 2 + 0] + bias[col]     + r.x;
                    float v1 = cc[mi][ni][half * 2 + 1] + bias[col + 1] + r.y;
                    cc[mi][ni][half * 2 + 0] = v0;
                    cc[mi][ni][half * 2 + 1] = v1;
                    *(float2*)(C + orow * CDIM + col) = make_float2(v0, v1);
                    s += v0 + v1; sq += v0 * v0 + v1 * v1;
                }
                s  += __shfl_xor_sync(0xffffffffu, s, 1);
                sq += __shfl_xor_sync(0xffffffffu, sq, 1);
                s  += __shfl_xor_sync(0xffffffffu, s, 2);
                sq += __shfl_xor_sync(0xffffffffu, sq, 2);
                if (tig == 0) {
                    atomicAdd(&red[2 * rloc],     s);
                    atomicAdd(&red[2 * rloc + 1], sq);
                }
            }
        }
        __syncthreads();
        #pragma unroll
        for (int mi = 0; mi < 4; mi++) {
            #pragma unroll
            for (int half = 0; half < 2; half++) {
                int rloc = warpM * 64 + mi * 16 + gid + half * 8;
                long orow = orows[mi][half];
                float mean = red[2 * rloc] * (1.0f / CDIM);
                float var  = red[2 * rloc + 1] * (1.0f / CDIM) - mean * mean;
                float rstd = rsqrtf(var + 1e-5f);
                #pragma unroll
                for (int ni = 0; ni < 4; ni++) {
                    int col = warpN * 32 + ni * 8 + 2 * tig;
                    float v0 = cc[mi][ni][half * 2 + 0];
                    float v1 = cc[mi][ni][half * 2 + 1];
                    float y0 = (v0 - mean) * rstd * gam[col]     + bet[col];
                    float y1 = (v1 - mean) * rstd * gam[col + 1] + bet[col + 1];
                    *(uint32_t*)(g_xw + orow * CDIM + col) = pack_bf2(y0, y1);
                }
            }
        }
        return;
    }

    // epilogue (MODE 2/3)
    #pragma unroll
    for (int mi = 0; mi < 4; mi++) {
        #pragma unroll
        for (int half = 0; half < 2; half++) {
            long row = rowBase + warpM * 64 + mi * 16 + gid + half * 8;
            #pragma unroll
            for (int ni = 0; ni < 4; ni++) {
                int col = colBase + warpN * 32 + ni * 8 + 2 * tig;
                float v0 = cc[mi][ni][half * 2 + 0] + bias[col];
                float v1 = cc[mi][ni][half * 2 + 1] + bias[col + 1];
                if (MODE == 2) {
                    v0 = 0.5f * v0 * (1.0f + erff(v0 * 0.70710678118654752f));
                    v1 = 0.5f * v1 * (1.0f + erff(v1 * 0.70710678118654752f));
                }
                if (MODE == 3) {
                    float* C = (float*)Cv;
                    const float2 r = *(const float2*)(resid + row * CDIM + col);
                    *(float2*)(C + row * CDIM + col) = make_float2(v0 + r.x, v1 + r.y);
                } else {
                    bf16* C = (bf16*)Cv;
                    *(uint32_t*)(C + row * (long)N + col) = pack_bf2(v0, v1);
                }
            }
        }
    }
}

// ---------------------------------------------------------------------------
// BF16 tensor-core window attention (aliased smem, 4 CTAs/SM)
// ---------------------------------------------------------------------------
#define AQS 40
#define PSS 120
#define NPAD 112
#define ATTN_ELEMS (128 * PSS + NPAD * AQS)   // 19840 bf16 = 39680 B
__global__ __launch_bounds__(128, 4)
void attn_kernel() {
    extern __shared__ bf16 asm_[];
    bf16* qs  = asm_;                          // [128][40]   (aliased by ps later)
    bf16* ks  = asm_ + 128 * AQS;              // [112][40]   (aliased by ps later)
    bf16* ps  = asm_;                          // [128][120]
    bf16* vsr = asm_ + 128 * PSS;              // [112][40]

    const int w = blockIdx.x;
    const int h = blockIdx.y;
    const int tid  = threadIdx.x;
    const int warp = tid >> 5;
    const int lane = tid & 31;
    const int gid = lane >> 2;
    const int tig = lane & 3;

    const bf16* base = g_qkv + (size_t)w * NTOK * QKVN + h * HD;

    for (int i = tid; i < NTOK * 4; i += 128) {
        int m = i >> 2, c = (i & 3) * 8;
        *(uint4*)&qs [m * AQS + c] = *(const uint4*)(base + m * QKVN + c);
        *(uint4*)&ks [m * AQS + c] = *(const uint4*)(base + m * QKVN + CDIM + c);
        *(uint4*)&vsr[m * AQS + c] = *(const uint4*)(base + m * QKVN + 2 * CDIM + c);
    }
    const uint4 z4 = make_uint4(0, 0, 0, 0);
    for (int i = tid; i < 30 * 4; i += 128) {
        int m = 98 + (i >> 2), c = (i & 3) * 8;
        *(uint4*)&qs[m * AQS + c] = z4;
        if (m < NPAD) {
            *(uint4*)&ks [m * AQS + c] = z4;
            *(uint4*)&vsr[m * AQS + c] = z4;
        }
    }
    __syncthreads();

    const int a_r = (lane & 7) + ((lane >> 3) & 1) * 8;
    const int a_k = (lane >> 4) * 8;
    const int b_n = (lane & 7) + (lane >> 4) * 8;
    const int b_k = ((lane >> 3) & 1) * 8;
    const int t_r = (lane & 7) + ((lane >> 3) & 1) * 8;
    const int t_c = (lane >> 4) * 8;

    float cc[2][14][4];
    #pragma unroll
    for (int mi = 0; mi < 2; mi++)
        #pragma unroll
        for (int ni = 0; ni < 14; ni++)
            #pragma unroll
            for (int e = 0; e < 4; e++) cc[mi][ni][e] = 0.f;

    #pragma unroll
    for (int ksx = 0; ksx < 2; ksx++) {
        const int kk = ksx * 16;
        uint32_t af[2][4];
        #pragma unroll
        for (int mi = 0; mi < 2; mi++)
            ldsm_x4(af[mi], qs + (warp * 32 + mi * 16 + a_r) * AQS + kk + a_k);
        #pragma unroll
        for (int np = 0; np < 7; np++) {
            uint32_t r4[4];
            ldsm_x4(r4, ks + (np * 16 + b_n) * AQS + kk + b_k);
            uint32_t b0[2] = { r4[0], r4[1] };
            uint32_t b1[2] = { r4[2], r4[3] };
            mma_bf16(cc[0][2 * np],     af[0], b0);
            mma_bf16(cc[1][2 * np],     af[1], b0);
            mma_bf16(cc[0][2 * np + 1], af[0], b1);
            mma_bf16(cc[1][2 * np + 1], af[1], b1);
        }
    }

    float rsum[2][2] = {{0.f, 0.f}, {0.f, 0.f}};
    const float* gb = g_bias + h * NTOK * NTOK;
    #pragma unroll
    for (int mi = 0; mi < 2; mi++) {
        int r0 = warp * 32 + mi * 16 + gid;
        int r1 = r0 + 8;
        const float* b0p = gb + (r0 < NTOK ? r0 : NTOK - 1) * NTOK;
        const float* b1p = gb + (r1 < NTOK ? r1 : NTOK - 1) * NTOK;
        #pragma unroll
        for (int ni = 0; ni < 14; ni++) {
            int c0 = ni * 8 + 2 * tig;
            int c1 = c0 + 1;
            int cc0 = c0 < NTOK ? c0 : NTOK - 1;
            int cc1 = c1 < NTOK ? c1 : NTOK - 1;
            float e;
            e = (c0 < NTOK) ? __expf(cc[mi][ni][0] + b0p[cc0]) : 0.f; cc[mi][ni][0] = e; rsum[mi][0] += e;
            e = (c1 < NTOK) ? __expf(cc[mi][ni][1] + b0p[cc1]) : 0.f; cc[mi][ni][1] = e; rsum[mi][0] += e;
            e = (c0 < NTOK) ? __expf(cc[mi][ni][2] + b1p[cc0]) : 0.f; cc[mi][ni][2] = e; rsum[mi][1] += e;
            e = (c1 < NTOK) ? __expf(cc[mi][ni][3] + b1p[cc1]) : 0.f; cc[mi][ni][3] = e; rsum[mi][1] += e;
        }
    }
    float inv[2][2];
    #pragma unroll
    for (int mi = 0; mi < 2; mi++)
        #pragma unroll
        for (int hf = 0; hf < 2; hf++) {
            float s = rsum[mi][hf];
            s += __shfl_xor_sync(0xffffffffu, s, 1);
            s += __shfl_xor_sync(0xffffffffu, s, 2);
            inv[mi][hf] = 1.0f / s;
        }

    __syncthreads();   // all warps done reading qs/ks before ps overwrites them

    #pragma unroll
    for (int mi = 0; mi < 2; mi++) {
        int r0 = warp * 32 + mi * 16 + gid;
        #pragma unroll
        for (int ni = 0; ni < 14; ni++) {
            int col = ni * 8 + 2 * tig;
            *(uint32_t*)&ps[r0 * PSS + col] =
                pack_bf2(cc[mi][ni][0] * inv[mi][0], cc[mi][ni][1] * inv[mi][0]);
            *(uint32_t*)&ps[(r0 + 8) * PSS + col] =
                pack_bf2(cc[mi][ni][2] * inv[mi][1], cc[mi][ni][3] * inv[mi][1]);
        }
    }
    __syncwarp();

    float oo[2][4][4];
    #pragma unroll
    for (int mi = 0; mi < 2; mi++)
        #pragma unroll
        for (int ni = 0; ni < 4; ni++)
            #pragma unroll
            for (int e = 0; e < 4; e++) oo[mi][ni][e] = 0.f;

    #pragma unroll
    for (int k2 = 0; k2 < 7; k2++) {
        const int kk = k2 * 16;
        uint32_t af[2][4];
        #pragma unroll
        for (int mi = 0; mi < 2; mi++)
            ldsm_x4(af[mi], ps + (warp * 32 + mi * 16 + a_r) * PSS + kk + a_k);
        #pragma unroll
        for (int np = 0; np < 2; np++) {
            int n0 = np * 16;
            uint32_t r4[4];
            ldsm_x4_t(r4, vsr + (kk + t_r) * AQS + n0 + t_c);
            uint32_t b0[2] = { r4[0], r4[1] };
            uint32_t b1[2] = { r4[2], r4[3] };
            mma_bf16(oo[0][2 * np],     af[0], b0);
            mma_bf16(oo[1][2 * np],     af[1], b0);
            mma_bf16(oo[0][2 * np + 1], af[0], b1);
            mma_bf16(oo[1][2 * np + 1], af[1], b1);
        }
    }

    #pragma unroll
    for (int mi = 0; mi < 2; mi++) {
        #pragma unroll
        for (int hf = 0; hf < 2; hf++) {
            int row = warp * 32 + mi * 16 + gid + hf * 8;
            if (row < NTOK) {
                bf16* op = g_attn + ((size_t)w * NTOK + row) * CDIM + h * HD;
                #pragma unroll
                for (int ni = 0; ni < 4; ni++) {
                    int col = ni * 8 + 2 * tig;
                    *(uint32_t*)(op + col) =
                        pack_bf2(oo[mi][ni][hf * 2], oo[mi][ni][hf * 2 + 1]);
                }
            }
        }
    }
}

// ---------------------------------------------------------------------------
// launcher
// ---------------------------------------------------------------------------
extern "C" void kernel_launch(void* const* d_in, const int* in_sizes, int n_in,
                              void* d_out, int out_size) {
    const float* x          = (const float*)d_in[0];
    const float* norm1_w    = (const float*)d_in[1];
    const float* norm1_b    = (const float*)d_in[2];
    const float* qkv_w      = (const float*)d_in[3];
    const float* qkv_b      = (const float*)d_in[4];
    const float* bias_table = (const float*)d_in[5];
    const float* proj_w     = (const float*)d_in[6];
    const float* proj_b     = (const float*)d_in[7];
    const float* norm2_w    = (const float*)d_in[8];
    const float* norm2_b    = (const float*)d_in[9];
    const float* fc1_w      = (const float*)d_in[10];
    const float* fc1_b      = (const float*)d_in[11];
    const float* fc2_w      = (const float*)d_in[12];
    const float* fc2_b      = (const float*)d_in[13];
    const int*   rel_index  = (const int*)d_in[14];
    float* out = (float*)d_out;

    bf16 *p_xw, *p_qkv, *p_attn, *p_h;
    bf16 *p_wq, *p_wp, *p_w1, *p_w2;
    float *p_x2;
    cudaGetSymbolAddress((void**)&p_xw,   g_xw);
    cudaGetSymbolAddress((void**)&p_qkv,  g_qkv);
    cudaGetSymbolAddress((void**)&p_attn, g_attn);
    cudaGetSymbolAddress((void**)&p_x2,   g_x2);
    cudaGetSymbolAddress((void**)&p_h,    g_h);
    cudaGetSymbolAddress((void**)&p_wq,   g_wq);
    cudaGetSymbolAddress((void**)&p_wp,   g_wp);
    cudaGetSymbolAddress((void**)&p_w1,   g_w1);
    cudaGetSymbolAddress((void**)&p_w2,   g_w2);

    const int GEMM_SMEM = 3 * G_STAGE * (int)sizeof(bf16);   // 61440
    const int ATTN_SMEM = ATTN_ELEMS * (int)sizeof(bf16);    // 39680
    cudaFuncSetAttribute((const void*)qkv_ln_kernel,        cudaFuncAttributeMaxDynamicSharedMemorySize, QKV_SMEM);
    cudaFuncSetAttribute((const void*)gemm_kernel<1,128>,   cudaFuncAttributeMaxDynamicSharedMemorySize, GEMM_SMEM);
    cudaFuncSetAttribute((const void*)gemm_kernel<2,128>,   cudaFuncAttributeMaxDynamicSharedMemorySize, GEMM_SMEM);
    cudaFuncSetAttribute((const void*)gemm_kernel<3,512>,   cudaFuncAttributeMaxDynamicSharedMemorySize, GEMM_SMEM);
    cudaFuncSetAttribute((const void*)attn_kernel,          cudaFuncAttributeMaxDynamicSharedMemorySize, ATTN_SMEM);

    // 0) merged setup: weight conversion + bias gather
    setup_kernel<<<(CVT_UNITS + BIAS_UNITS + 255) / 256, 256>>>(
        qkv_w, proj_w, fc1_w, fc2_w, bias_table, rel_index);

    // 1) QKV gemm with fused LN1 + window partition (+ q scale), bf16 out
    qkv_ln_kernel<<<dim3(QKVN / 128, TOK / 128), 256, QKV_SMEM>>>(
        x, p_wq, norm1_w, norm1_b, qkv_b, p_qkv);

    // 2) window attention (bf16 tensor cores)
    attn_kernel<<<dim3(NWIN, NH), 128, ATTN_SMEM>>>();

    // 3) proj gemm + window reverse + residual(x) -> g_x2 (fp32) + fused LN2 -> g_xw (bf16)
    gemm_kernel<1,128><<<dim3(CDIM / 128, TOK / 128), 256, GEMM_SMEM>>>(
        p_attn, p_wp, proj_b, x, norm2_w, norm2_b, p_x2, CDIM);

    // 4) fc1 + exact GELU, bf16 out
    gemm_kernel<2,128><<<dim3(CH / 128, TOK / 128), 256, GEMM_SMEM>>>(
        p_xw, p_w1, fc1_b, nullptr, nullptr, nullptr, p_h, CH);

    // 5) fc2 + residual(g_x2) -> d_out (fp32)
    gemm_kernel<3,512><<<dim3(CDIM / 128, TOK / 128), 256, GEMM_SMEM>>>(
        p_h, p_w2, fc2_b, p_x2, nullptr, nullptr, out, CDIM);

    (void)in_sizes; (void)n_in; (void)out_size;
}

// round 12
// speedup vs baseline: 1.0722x; 1.0722x over previous
#include <cuda_runtime.h>
#include <cuda_bf16.h>
#include <math.h>
#include <stdint.h>

// ---------------------------------------------------------------------------
// Problem constants
// ---------------------------------------------------------------------------
#define TOK   50176      // 2*8*56*56
#define CDIM  128
#define CH    512
#define NWIN  512        // 2 * 4*8*8
#define NTOK  98         // 2*7*7
#define NH    4
#define HD    32
#define QKVN  384

typedef __nv_bfloat16  bf16;
typedef __nv_bfloat162 bf162;

// ---------------------------------------------------------------------------
// Scratch (device globals: allocation-free, graph-capture safe)
// ---------------------------------------------------------------------------
__device__ bf16  g_xw  [(size_t)TOK * CDIM];   // LN1 out (window order) / LN2 out (spatial)
__device__ bf16  g_qkv [(size_t)TOK * QKVN];   // qkv, window order
__device__ bf16  g_attn[(size_t)TOK * CDIM];   // attention out, window order
__device__ float g_x2  [(size_t)TOK * CDIM];   // x + proj (spatial, fp32)
__device__ bf16  g_h   [(size_t)TOK * CH];     // fc1 output
__device__ float g_bias[NH * NTOK * NTOK];     // gathered attention bias (fp32)
// bf16 weights
__device__ bf16  g_wq[QKVN * CDIM];
__device__ bf16  g_wp[CDIM * CDIM];
__device__ bf16  g_w1[CH * CDIM];
__device__ bf16  g_w2[CDIM * CH];

// ---------------------------------------------------------------------------
// index helpers
// ---------------------------------------------------------------------------
__device__ __forceinline__ long win_to_spatial(long row) {
    int w = (int)(row / NTOK);
    int n = (int)(row % NTOK);
    int b   = w >> 8;
    int rem = w & 255;
    int wdi = rem >> 6, whi = (rem >> 3) & 7, wwi = rem & 7;
    int zd = n / 49; int r2 = n % 49; int zh = r2 / 7, zw = r2 % 7;
    int d  = wdi * 2 + zd;
    int hh = whi * 7 + zh;
    int xx = wwi * 7 + zw;
    return (((long)(b * 8 + d) * 56) + hh) * 56 + xx;
}

__device__ __forceinline__ long spatial_to_win(long t) {
    int b  = (int)(t / 25088);
    int r  = (int)(t % 25088);
    int d  = r / 3136; r %= 3136;
    int hh = r / 56;
    int xx = r % 56;
    int widx = ((b * 4 + (d >> 1)) * 8 + hh / 7) * 8 + xx / 7;
    int n    = ((d & 1) * 7 + hh % 7) * 7 + xx % 7;
    return (long)widx * NTOK + n;
}

// ---------------------------------------------------------------------------
// async copy + ldmatrix + mma helpers
// ---------------------------------------------------------------------------
__device__ __forceinline__ void cp_async16(bf16* smem_dst, const bf16* gmem_src) {
    uint32_t s = (uint32_t)__cvta_generic_to_shared(smem_dst);
    asm volatile("cp.async.cg.shared.global [%0], [%1], 16;\n" :: "r"(s), "l"(gmem_src));
}
__device__ __forceinline__ void cp_commit() { asm volatile("cp.async.commit_group;\n"); }
template<int N>
__device__ __forceinline__ void cp_wait() { asm volatile("cp.async.wait_group %0;\n" :: "n"(N)); }

__device__ __forceinline__ void ldsm_x4(uint32_t r[4], const bf16* p) {
    uint32_t a = (uint32_t)__cvta_generic_to_shared(p);
    asm volatile("ldmatrix.sync.aligned.m8n8.x4.shared.b16 {%0,%1,%2,%3}, [%4];\n"
                 : "=r"(r[0]), "=r"(r[1]), "=r"(r[2]), "=r"(r[3]) : "r"(a));
}
__device__ __forceinline__ void ldsm_x4_t(uint32_t r[4], const bf16* p) {
    uint32_t a = (uint32_t)__cvta_generic_to_shared(p);
    asm volatile("ldmatrix.sync.aligned.m8n8.x4.trans.shared.b16 {%0,%1,%2,%3}, [%4];\n"
                 : "=r"(r[0]), "=r"(r[1]), "=r"(r[2]), "=r"(r[3]) : "r"(a));
}
__device__ __forceinline__ void mma_bf16(float c[4], const uint32_t a[4], const uint32_t b[2]) {
    asm volatile(
        "mma.sync.aligned.m16n8k16.row.col.f32.bf16.bf16.f32 "
        "{%0,%1,%2,%3}, {%4,%5,%6,%7}, {%8,%9}, {%0,%1,%2,%3};\n"
        : "+f"(c[0]), "+f"(c[1]), "+f"(c[2]), "+f"(c[3])
        : "r"(a[0]), "r"(a[1]), "r"(a[2]), "r"(a[3]), "r"(b[0]), "r"(b[1]));
}

__device__ __forceinline__ uint32_t pack_bf2(float a, float b) {
    bf162 p = __float22bfloat162_rn(make_float2(a, b));
    return *(uint32_t*)&p;
}

// ---------------------------------------------------------------------------
// merged setup: weight conversion fp32->bf16 (float4 units 0..49151)
//               + bias gather (units 49152..49152+38415)
// ---------------------------------------------------------------------------
#define CVT_UNITS  49152
#define BIAS_UNITS (NH * NTOK * NTOK)   // 38416
__global__ void setup_kernel(const float* __restrict__ wq,
                             const float* __restrict__ wp,
                             const float* __restrict__ w1,
                             const float* __restrict__ w2,
                             const float* __restrict__ bias_table,
                             const int* __restrict__ rel_index) {
    int i = blockIdx.x * blockDim.x + threadIdx.x;
    if (i < CVT_UNITS) {
        const float* src; bf16* dst; int off;
        if (i < 12288)      { src = wq; dst = g_wq; off = i; }
        else if (i < 16384) { src = wp; dst = g_wp; off = i - 12288; }
        else if (i < 32768) { src = w1; dst = g_w1; off = i - 16384; }
        else                { src = w2; dst = g_w2; off = i - 32768; }
        float4 v = *(const float4*)(src + off * 4);
        uint2 u = make_uint2(pack_bf2(v.x, v.y), pack_bf2(v.z, v.w));
        *(uint2*)(dst + off * 4) = u;
    } else {
        int j = i - CVT_UNITS;
        if (j < BIAS_UNITS) {
            int h = j / (NTOK * NTOK);
            int r = j % (NTOK * NTOK);
            g_bias[j] = bias_table[rel_index[r] * NH + h];
        }
    }
}

// ---------------------------------------------------------------------------
// LayerNorm over C=128 (fp32 in, bf16 out): one warp per token.
// PERMUTE=true: write window-partitioned order (for LN1).
// ---------------------------------------------------------------------------
template<bool PERMUTE>
__global__ __launch_bounds__(256)
void ln_kernel(const float* __restrict__ in,
               const float* __restrict__ gam,
               const float* __restrict__ bet,
               bf16* __restrict__ out) {
    int warp = threadIdx.x >> 5;
    int lane = threadIdx.x & 31;
    long t = (long)blockIdx.x * 8 + warp;
    const float4 v = *(const float4*)(in + t * CDIM + lane * 4);
    float s  = v.x + v.y + v.z + v.w;
    float sq = v.x * v.x + v.y * v.y + v.z * v.z + v.w * v.w;
    #pragma unroll
    for (int o = 16; o; o >>= 1) {
        s  += __shfl_xor_sync(0xffffffffu, s,  o);
        sq += __shfl_xor_sync(0xffffffffu, sq, o);
    }
    float mean = s * (1.0f / CDIM);
    float var  = sq * (1.0f / CDIM) - mean * mean;
    float rstd = rsqrtf(var + 1e-5f);
    const float4 g = *(const float4*)(gam + lane * 4);
    const float4 b = *(const float4*)(bet + lane * 4);
    uint2 u = make_uint2(pack_bf2((v.x - mean) * rstd * g.x + b.x,
                                  (v.y - mean) * rstd * g.y + b.y),
                         pack_bf2((v.z - mean) * rstd * g.z + b.z,
                                  (v.w - mean) * rstd * g.w + b.w));
    long orow = PERMUTE ? spatial_to_win(t) : t;
    *(uint2*)(out + orow * CDIM + lane * 4) = u;
}

// ---------------------------------------------------------------------------
// BF16 GEMM (R5 exact): 128x128 block, BK=32, 3-stage cp.async, warp 64x32.
// MODE 0: qkv  -> +bias; scale q-part (colBase==0); bf16 out [M,384]
// MODE 1: proj -> +bias; permute; += resid(x); fp32 g_x2  AND fused LN2 -> bf16 g_xw
// MODE 2: fc1  -> +bias; exact GELU; bf16 out [M,512]
// MODE 3: fc2  -> +bias; += resid(g_x2); fp32 out d_out
// ---------------------------------------------------------------------------
#define GS 40                  // smem row stride (halves): 32 + 8 pad
#define G_STAGE (256 * GS)     // As(128)+Ws(128) rows per stage
template<int MODE, int KT>
__global__ __launch_bounds__(256, 2)
void gemm_kernel(const bf16* __restrict__ A,
                 const bf16* __restrict__ Wt,
                 const float* __restrict__ bias,
                 const float* __restrict__ resid,
                 const float* __restrict__ gam,
                 const float* __restrict__ bet,
                 void* __restrict__ Cv,
                 int N) {
    extern __shared__ bf16 sm[];
    bf16* Asb[3] = { sm, sm + G_STAGE, sm + 2 * G_STAGE };
    bf16* Wsb[3] = { sm + 128 * GS, sm + G_STAGE + 128 * GS, sm + 2 * G_STAGE + 128 * GS };

    const int tid  = threadIdx.x;
    const int lane = tid & 31;
    const int warp = tid >> 5;
    const int warpM = warp >> 2;        // 0..1
    const int warpN = warp & 3;         // 0..3
    const int gid = lane >> 2;          // 0..7
    const int tig = lane & 3;           // 0..3

    const long rowBase = (long)blockIdx.y * 128;
    const int  colBase = blockIdx.x * 128;
    const int  K = KT;

    float cc[4][4][4];
    #pragma unroll
    for (int mi = 0; mi < 4; mi++)
        #pragma unroll
        for (int ni = 0; ni < 4; ni++)
            #pragma unroll
            for (int e = 0; e < 4; e++) cc[mi][ni][e] = 0.f;

    const int ld_row = tid >> 2;        // 0..63
    const int ld_kq  = (tid & 3) * 8;   // halves

    auto load_tile = [&](int buf, int k0) {
        #pragma unroll
        for (int r = 0; r < 2; r++) {
            int m = ld_row + r * 64;
            cp_async16(&Asb[buf][m * GS + ld_kq], A + (rowBase + m) * K + k0 + ld_kq);
        }
        #pragma unroll
        for (int r = 0; r < 2; r++) {
            int n = ld_row + r * 64;
            cp_async16(&Wsb[buf][n * GS + ld_kq], Wt + (long)(colBase + n) * K + k0 + ld_kq);
        }
    };

    constexpr int nk = KT / 32;
    load_tile(0, 0);  cp_commit();
    load_tile(1, 32); cp_commit();

    const int a_r = (lane & 7) + ((lane >> 3) & 1) * 8;
    const int a_k = (lane >> 4) * 8;
    const int b_n = (lane & 7) + (lane >> 4) * 8;
    const int b_k = ((lane >> 3) & 1) * 8;

    #pragma unroll
    for (int it = 0; it < nk; it++) {
        if (it < nk - 1) cp_wait<1>(); else cp_wait<0>();
        __syncthreads();
        if (it + 2 < nk) { load_tile((it + 2) % 3, (it + 2) * 32); cp_commit(); }

        const bf16* As = Asb[it % 3];
        const bf16* Ws = Wsb[it % 3];
        #pragma unroll
        for (int ks = 0; ks < 2; ks++) {
            const int kk = ks * 16;
            uint32_t af[4][4];
            uint32_t bf[4][2];
            #pragma unroll
            for (int mi = 0; mi < 4; mi++)
                ldsm_x4(af[mi], As + (warpM * 64 + mi * 16 + a_r) * GS + kk + a_k);
            #pragma unroll
            for (int np = 0; np < 2; np++) {
                uint32_t r4[4];
                ldsm_x4(r4, Ws + (warpN * 32 + np * 16 + b_n) * GS + kk + b_k);
                bf[2 * np][0] = r4[0]; bf[2 * np][1] = r4[1];
                bf[2 * np + 1][0] = r4[2]; bf[2 * np + 1][1] = r4[3];
            }
            #pragma unroll
            for (int mi = 0; mi < 4; mi++)
                #pragma unroll
                for (int ni = 0; ni < 4; ni++)
                    mma_bf16(cc[mi][ni], af[mi], bf[ni]);
        }
    }

    if (MODE == 1) {
        // fused: x2 = resid + proj_out (+bias), write fp32 g_x2;
        // then LayerNorm(x2) over full 128-col rows -> bf16 g_xw.
        __syncthreads();                 // all warps done with smem stages
        float* red = (float*)sm;         // [128][2] row sums
        if (tid < 128) { red[2 * tid] = 0.f; red[2 * tid + 1] = 0.f; }
        __syncthreads();

        long orows[4][2];
        float* C = (float*)Cv;
        #pragma unroll
        for (int mi = 0; mi < 4; mi++) {
            #pragma unroll
            for (int half = 0; half < 2; half++) {
                int rloc = warpM * 64 + mi * 16 + gid + half * 8;
                long orow = win_to_spatial(rowBase + rloc);
                orows[mi][half] = orow;
                float s = 0.f, sq = 0.f;
                #pragma unroll
                for (int ni = 0; ni < 4; ni++) {
                    int col = warpN * 32 + ni * 8 + 2 * tig;
                    const float2 r = *(const float2*)(resid + orow * CDIM + col);
                    float v0 = cc[mi][ni][half * 2 + 0] + bias[col]     + r.x;
                    float v1 = cc[mi][ni][half * 2 + 1] + bias[col + 1] + r.y;
                    cc[mi][ni][half * 2 + 0] = v0;
                    cc[mi][ni][half * 2 + 1] = v1;
                    *(float2*)(C + orow * CDIM + col) = make_float2(v0, v1);
                    s += v0 + v1; sq += v0 * v0 + v1 * v1;
                }
                s  += __shfl_xor_sync(0xffffffffu, s, 1);
                sq += __shfl_xor_sync(0xffffffffu, sq, 1);
                s  += __shfl_xor_sync(0xffffffffu, s, 2);
                sq += __shfl_xor_sync(0xffffffffu, sq, 2);
                if (tig == 0) {
                    atomicAdd(&red[2 * rloc],     s);
                    atomicAdd(&red[2 * rloc + 1], sq);
                }
            }
        }
        __syncthreads();
        #pragma unroll
        for (int mi = 0; mi < 4; mi++) {
            #pragma unroll
            for (int half = 0; half < 2; half++) {
                int rloc = warpM * 64 + mi * 16 + gid + half * 8;
                long orow = orows[mi][half];
                float mean = red[2 * rloc] * (1.0f / CDIM);
                float var  = red[2 * rloc + 1] * (1.0f / CDIM) - mean * mean;
                float rstd = rsqrtf(var + 1e-5f);
                #pragma unroll
                for (int ni = 0; ni < 4; ni++) {
                    int col = warpN * 32 + ni * 8 + 2 * tig;
                    float v0 = cc[mi][ni][half * 2 + 0];
                    float v1 = cc[mi][ni][half * 2 + 1];
                    float y0 = (v0 - mean) * rstd * gam[col]     + bet[col];
                    float y1 = (v1 - mean) * rstd * gam[col + 1] + bet[col + 1];
                    *(uint32_t*)(g_xw + orow * CDIM + col) = pack_bf2(y0, y1);
                }
            }
        }
        return;
    }

    // epilogue (MODE 0/2/3)
    #pragma unroll
    for (int mi = 0; mi < 4; mi++) {
        #pragma unroll
        for (int half = 0; half < 2; half++) {
            long row = rowBase + warpM * 64 + mi * 16 + gid + half * 8;
            #pragma unroll
            for (int ni = 0; ni < 4; ni++) {
                int col = colBase + warpN * 32 + ni * 8 + 2 * tig;
                float v0 = cc[mi][ni][half * 2 + 0] + bias[col];
                float v1 = cc[mi][ni][half * 2 + 1] + bias[col + 1];
                if (MODE == 0) {
                    if (colBase == 0) { v0 *= 0.17677669529663687f; v1 *= 0.17677669529663687f; }
                }
                if (MODE == 2) {
                    v0 = 0.5f * v0 * (1.0f + erff(v0 * 0.70710678118654752f));
                    v1 = 0.5f * v1 * (1.0f + erff(v1 * 0.70710678118654752f));
                }
                if (MODE == 3) {
                    float* C = (float*)Cv;
                    const float2 r = *(const float2*)(resid + row * CDIM + col);
                    *(float2*)(C + row * CDIM + col) = make_float2(v0 + r.x, v1 + r.y);
                } else {
                    bf16* C = (bf16*)Cv;
                    *(uint32_t*)(C + row * (long)N + col) = pack_bf2(v0, v1);
                }
            }
        }
    }
}

// ---------------------------------------------------------------------------
// BF16 tensor-core window attention (aliased smem, 4 CTAs/SM)
// ---------------------------------------------------------------------------
#define AQS 40
#define PSS 120
#define NPAD 112
#define ATTN_ELEMS (128 * PSS + NPAD * AQS)   // 19840 bf16 = 39680 B
__global__ __launch_bounds__(128, 4)
void attn_kernel() {
    extern __shared__ bf16 asm_[];
    bf16* qs  = asm_;                          // [128][40]   (aliased by ps later)
    bf16* ks  = asm_ + 128 * AQS;              // [112][40]   (aliased by ps later)
    bf16* ps  = asm_;                          // [128][120]
    bf16* vsr = asm_ + 128 * PSS;              // [112][40]

    const int w = blockIdx.x;
    const int h = blockIdx.y;
    const int tid  = threadIdx.x;
    const int warp = tid >> 5;
    const int lane = tid & 31;
    const int gid = lane >> 2;
    const int tig = lane & 3;

    const bf16* base = g_qkv + (size_t)w * NTOK * QKVN + h * HD;

    for (int i = tid; i < NTOK * 4; i += 128) {
        int m = i >> 2, c = (i & 3) * 8;
        *(uint4*)&qs [m * AQS + c] = *(const uint4*)(base + m * QKVN + c);
        *(uint4*)&ks [m * AQS + c] = *(const uint4*)(base + m * QKVN + CDIM + c);
        *(uint4*)&vsr[m * AQS + c] = *(const uint4*)(base + m * QKVN + 2 * CDIM + c);
    }
    const uint4 z4 = make_uint4(0, 0, 0, 0);
    for (int i = tid; i < 30 * 4; i += 128) {
        int m = 98 + (i >> 2), c = (i & 3) * 8;
        *(uint4*)&qs[m * AQS + c] = z4;
        if (m < NPAD) {
            *(uint4*)&ks [m * AQS + c] = z4;
            *(uint4*)&vsr[m * AQS + c] = z4;
        }
    }
    __syncthreads();

    const int a_r = (lane & 7) + ((lane >> 3) & 1) * 8;
    const int a_k = (lane >> 4) * 8;
    const int b_n = (lane & 7) + (lane >> 4) * 8;
    const int b_k = ((lane >> 3) & 1) * 8;
    const int t_r = (lane & 7) + ((lane >> 3) & 1) * 8;
    const int t_c = (lane >> 4) * 8;

    float cc[2][14][4];
    #pragma unroll
    for (int mi = 0; mi < 2; mi++)
        #pragma unroll
        for (int ni = 0; ni < 14; ni++)
            #pragma unroll
            for (int e = 0; e < 4; e++) cc[mi][ni][e] = 0.f;

    #pragma unroll
    for (int ksx = 0; ksx < 2; ksx++) {
        const int kk = ksx * 16;
        uint32_t af[2][4];
        #pragma unroll
        for (int mi = 0; mi < 2; mi++)
            ldsm_x4(af[mi], qs + (warp * 32 + mi * 16 + a_r) * AQS + kk + a_k);
        #pragma unroll
        for (int np = 0; np < 7; np++) {
            uint32_t r4[4];
            ldsm_x4(r4, ks + (np * 16 + b_n) * AQS + kk + b_k);
            uint32_t b0[2] = { r4[0], r4[1] };
            uint32_t b1[2] = { r4[2], r4[3] };
            mma_bf16(cc[0][2 * np],     af[0], b0);
            mma_bf16(cc[1][2 * np],     af[1], b0);
            mma_bf16(cc[0][2 * np + 1], af[0], b1);
            mma_bf16(cc[1][2 * np + 1], af[1], b1);
        }
    }

    float rsum[2][2] = {{0.f, 0.f}, {0.f, 0.f}};
    const float* gb = g_bias + h * NTOK * NTOK;
    #pragma unroll
    for (int mi = 0; mi < 2; mi++) {
        int r0 = warp * 32 + mi * 16 + gid;
        int r1 = r0 + 8;
        const float* b0p = gb + (r0 < NTOK ? r0 : NTOK - 1) * NTOK;
        const float* b1p = gb + (r1 < NTOK ? r1 : NTOK - 1) * NTOK;
        #pragma unroll
        for (int ni = 0; ni < 14; ni++) {
            int c0 = ni * 8 + 2 * tig;
            int c1 = c0 + 1;
            int cc0 = c0 < NTOK ? c0 : NTOK - 1;
            int cc1 = c1 < NTOK ? c1 : NTOK - 1;
            float e;
            e = (c0 < NTOK) ? __expf(cc[mi][ni][0] + b0p[cc0]) : 0.f; cc[mi][ni][0] = e; rsum[mi][0] += e;
            e = (c1 < NTOK) ? __expf(cc[mi][ni][1] + b0p[cc1]) : 0.f; cc[mi][ni][1] = e; rsum[mi][0] += e;
            e = (c0 < NTOK) ? __expf(cc[mi][ni][2] + b1p[cc0]) : 0.f; cc[mi][ni][2] = e; rsum[mi][1] += e;
            e = (c1 < NTOK) ? __expf(cc[mi][ni][3] + b1p[cc1]) : 0.f; cc[mi][ni][3] = e; rsum[mi][1] += e;
        }
    }
    float inv[2][2];
    #pragma unroll
    for (int mi = 0; mi < 2; mi++)
        #pragma unroll
        for (int hf = 0; hf < 2; hf++) {
            float s = rsum[mi][hf];
            s += __shfl_xor_sync(0xffffffffu, s, 1);
            s += __shfl_xor_sync(0xffffffffu, s, 2);
            inv[mi][hf] = 1.0f / s;
        }

    __syncthreads();   // all warps done reading qs/ks before ps overwrites them

    #pragma unroll
    for (int mi = 0; mi < 2; mi++) {
        int r0 = warp * 32 + mi * 16 + gid;
        #pragma unroll
        for (int ni = 0; ni < 14; ni++) {
            int col = ni * 8 + 2 * tig;
            *(uint32_t*)&ps[r0 * PSS + col] =
                pack_bf2(cc[mi][ni][0] * inv[mi][0], cc[mi][ni][1] * inv[mi][0]);
            *(uint32_t*)&ps[(r0 + 8) * PSS + col] =
                pack_bf2(cc[mi][ni][2] * inv[mi][1], cc[mi][ni][3] * inv[mi][1]);
        }
    }
    __syncwarp();

    float oo[2][4][4];
    #pragma unroll
    for (int mi = 0; mi < 2; mi++)
        #pragma unroll
        for (int ni = 0; ni < 4; ni++)
            #pragma unroll
            for (int e = 0; e < 4; e++) oo[mi][ni][e] = 0.f;

    #pragma unroll
    for (int k2 = 0; k2 < 7; k2++) {
        const int kk = k2 * 16;
        uint32_t af[2][4];
        #pragma unroll
        for (int mi = 0; mi < 2; mi++)
            ldsm_x4(af[mi], ps + (warp * 32 + mi * 16 + a_r) * PSS + kk + a_k);
        #pragma unroll
        for (int np = 0; np < 2; np++) {
            int n0 = np * 16;
            uint32_t r4[4];
            ldsm_x4_t(r4, vsr + (kk + t_r) * AQS + n0 + t_c);
            uint32_t b0[2] = { r4[0], r4[1] };
            uint32_t b1[2] = { r4[2], r4[3] };
            mma_bf16(oo[0][2 * np],     af[0], b0);
            mma_bf16(oo[1][2 * np],     af[1], b0);
            mma_bf16(oo[0][2 * np + 1], af[0], b1);
            mma_bf16(oo[1][2 * np + 1], af[1], b1);
        }
    }

    #pragma unroll
    for (int mi = 0; mi < 2; mi++) {
        #pragma unroll
        for (int hf = 0; hf < 2; hf++) {
            int row = warp * 32 + mi * 16 + gid + hf * 8;
            if (row < NTOK) {
                bf16* op = g_attn + ((size_t)w * NTOK + row) * CDIM + h * HD;
                #pragma unroll
                for (int ni = 0; ni < 4; ni++) {
                    int col = ni * 8 + 2 * tig;
                    *(uint32_t*)(op + col) =
                        pack_bf2(oo[mi][ni][hf * 2], oo[mi][ni][hf * 2 + 1]);
                }
            }
        }
    }
}

// ---------------------------------------------------------------------------
// launcher
// ---------------------------------------------------------------------------
extern "C" void kernel_launch(void* const* d_in, const int* in_sizes, int n_in,
                              void* d_out, int out_size) {
    const float* x          = (const float*)d_in[0];
    const float* norm1_w    = (const float*)d_in[1];
    const float* norm1_b    = (const float*)d_in[2];
    const float* qkv_w      = (const float*)d_in[3];
    const float* qkv_b      = (const float*)d_in[4];
    const float* bias_table = (const float*)d_in[5];
    const float* proj_w     = (const float*)d_in[6];
    const float* proj_b     = (const float*)d_in[7];
    const float* norm2_w    = (const float*)d_in[8];
    const float* norm2_b    = (const float*)d_in[9];
    const float* fc1_w      = (const float*)d_in[10];
    const float* fc1_b      = (const float*)d_in[11];
    const float* fc2_w      = (const float*)d_in[12];
    const float* fc2_b      = (const float*)d_in[13];
    const int*   rel_index  = (const int*)d_in[14];
    float* out = (float*)d_out;

    bf16 *p_xw, *p_qkv, *p_attn, *p_h;
    bf16 *p_wq, *p_wp, *p_w1, *p_w2;
    float *p_x2;
    cudaGetSymbolAddress((void**)&p_xw,   g_xw);
    cudaGetSymbolAddress((void**)&p_qkv,  g_qkv);
    cudaGetSymbolAddress((void**)&p_attn, g_attn);
    cudaGetSymbolAddress((void**)&p_x2,   g_x2);
    cudaGetSymbolAddress((void**)&p_h,    g_h);
    cudaGetSymbolAddress((void**)&p_wq,   g_wq);
    cudaGetSymbolAddress((void**)&p_wp,   g_wp);
    cudaGetSymbolAddress((void**)&p_w1,   g_w1);
    cudaGetSymbolAddress((void**)&p_w2,   g_w2);

    const int GEMM_SMEM = 3 * G_STAGE * (int)sizeof(bf16);   // 61440
    const int ATTN_SMEM = ATTN_ELEMS * (int)sizeof(bf16);    // 39680
    cudaFuncSetAttribute((const void*)gemm_kernel<0,128>, cudaFuncAttributeMaxDynamicSharedMemorySize, GEMM_SMEM);
    cudaFuncSetAttribute((const void*)gemm_kernel<1,128>, cudaFuncAttributeMaxDynamicSharedMemorySize, GEMM_SMEM);
    cudaFuncSetAttribute((const void*)gemm_kernel<2,128>, cudaFuncAttributeMaxDynamicSharedMemorySize, GEMM_SMEM);
    cudaFuncSetAttribute((const void*)gemm_kernel<3,512>, cudaFuncAttributeMaxDynamicSharedMemorySize, GEMM_SMEM);
    cudaFuncSetAttribute((const void*)attn_kernel,        cudaFuncAttributeMaxDynamicSharedMemorySize, ATTN_SMEM);

    // 0) merged setup: weight conversion + bias gather
    setup_kernel<<<(CVT_UNITS + BIAS_UNITS + 255) / 256, 256>>>(
        qkv_w, proj_w, fc1_w, fc2_w, bias_table, rel_index);

    // 1) LN1 + window partition (fp32 -> bf16)
    ln_kernel<true><<<TOK / 8, 256>>>(x, norm1_w, norm1_b, p_xw);

    // 2) QKV gemm (+ q scale), bf16 out
    gemm_kernel<0,128><<<dim3(QKVN / 128, TOK / 128), 256, GEMM_SMEM>>>(
        p_xw, p_wq, qkv_b, nullptr, nullptr, nullptr, p_qkv, QKVN);

    // 3) window attention (bf16 tensor cores)
    attn_kernel<<<dim3(NWIN, NH), 128, ATTN_SMEM>>>();

    // 4) proj gemm + window reverse + residual(x) -> g_x2 (fp32) + fused LN2 -> g_xw (bf16)
    gemm_kernel<1,128><<<dim3(CDIM / 128, TOK / 128), 256, GEMM_SMEM>>>(
        p_attn, p_wp, proj_b, x, norm2_w, norm2_b, p_x2, CDIM);

    // 5) fc1 + exact GELU, bf16 out
    gemm_kernel<2,128><<<dim3(CH / 128, TOK / 128), 256, GEMM_SMEM>>>(
        p_xw, p_w1, fc1_b, nullptr, nullptr, nullptr, p_h, CH);

    // 6) fc2 + residual(g_x2) -> d_out (fp32)
    gemm_kernel<3,512><<<dim3(CDIM / 128, TOK / 128), 256, GEMM_SMEM>>>(
        p_h, p_w2, fc2_b, p_x2, nullptr, nullptr, out, CDIM);

    (void)in_sizes; (void)n_in; (void)out_size;
}

// round 13
// speedup vs baseline: 1.1132x; 1.0382x over previous
#include <cuda_runtime.h>
#include <cuda_bf16.h>
#include <math.h>
#include <stdint.h>

// ---------------------------------------------------------------------------
// Problem constants
// ---------------------------------------------------------------------------
#define TOK   50176      // 2*8*56*56
#define CDIM  128
#define CH    512
#define NWIN  512        // 2 * 4*8*8
#define NTOK  98         // 2*7*7
#define NH    4
#define HD    32
#define QKVN  384
#define BSTR  112        // padded bias row stride

typedef __nv_bfloat16  bf16;
typedef __nv_bfloat162 bf162;

// ---------------------------------------------------------------------------
// Scratch (device globals: allocation-free, graph-capture safe)
// ---------------------------------------------------------------------------
__device__ bf16  g_xw  [(size_t)TOK * CDIM];   // LN1 out (window order) / LN2 out (spatial)
__device__ bf16  g_qkv [(size_t)TOK * QKVN];   // qkv, window order
__device__ bf16  g_attn[(size_t)TOK * CDIM];   // attention out, window order
__device__ float g_x2  [(size_t)TOK * CDIM];   // x + proj (spatial, fp32)
__device__ bf16  g_h   [(size_t)TOK * CH];     // fc1 output
__device__ float g_bias[NH * NTOK * BSTR];     // gathered attention bias, padded cols
// bf16 weights
__device__ bf16  g_wq[QKVN * CDIM];
__device__ bf16  g_wp[CDIM * CDIM];
__device__ bf16  g_w1[CH * CDIM];
__device__ bf16  g_w2[CDIM * CH];

// ---------------------------------------------------------------------------
// index helpers
// ---------------------------------------------------------------------------
__device__ __forceinline__ long win_to_spatial(long row) {
    int w = (int)(row / NTOK);
    int n = (int)(row % NTOK);
    int b   = w >> 8;
    int rem = w & 255;
    int wdi = rem >> 6, whi = (rem >> 3) & 7, wwi = rem & 7;
    int zd = n / 49; int r2 = n % 49; int zh = r2 / 7, zw = r2 % 7;
    int d  = wdi * 2 + zd;
    int hh = whi * 7 + zh;
    int xx = wwi * 7 + zw;
    return (((long)(b * 8 + d) * 56) + hh) * 56 + xx;
}

__device__ __forceinline__ long spatial_to_win(long t) {
    int b  = (int)(t / 25088);
    int r  = (int)(t % 25088);
    int d  = r / 3136; r %= 3136;
    int hh = r / 56;
    int xx = r % 56;
    int widx = ((b * 4 + (d >> 1)) * 8 + hh / 7) * 8 + xx / 7;
    int n    = ((d & 1) * 7 + hh % 7) * 7 + xx % 7;
    return (long)widx * NTOK + n;
}

// ---------------------------------------------------------------------------
// async copy + ldmatrix + mma helpers
// ---------------------------------------------------------------------------
__device__ __forceinline__ void cp_async16(bf16* smem_dst, const bf16* gmem_src) {
    uint32_t s = (uint32_t)__cvta_generic_to_shared(smem_dst);
    asm volatile("cp.async.cg.shared.global [%0], [%1], 16;\n" :: "r"(s), "l"(gmem_src));
}
__device__ __forceinline__ void cp_commit() { asm volatile("cp.async.commit_group;\n"); }
template<int N>
__device__ __forceinline__ void cp_wait() { asm volatile("cp.async.wait_group %0;\n" :: "n"(N)); }

__device__ __forceinline__ void ldsm_x4(uint32_t r[4], const bf16* p) {
    uint32_t a = (uint32_t)__cvta_generic_to_shared(p);
    asm volatile("ldmatrix.sync.aligned.m8n8.x4.shared.b16 {%0,%1,%2,%3}, [%4];\n"
                 : "=r"(r[0]), "=r"(r[1]), "=r"(r[2]), "=r"(r[3]) : "r"(a));
}
__device__ __forceinline__ void ldsm_x4_t(uint32_t r[4], const bf16* p) {
    uint32_t a = (uint32_t)__cvta_generic_to_shared(p);
    asm volatile("ldmatrix.sync.aligned.m8n8.x4.trans.shared.b16 {%0,%1,%2,%3}, [%4];\n"
                 : "=r"(r[0]), "=r"(r[1]), "=r"(r[2]), "=r"(r[3]) : "r"(a));
}
__device__ __forceinline__ void mma_bf16(float c[4], const uint32_t a[4], const uint32_t b[2]) {
    asm volatile(
        "mma.sync.aligned.m16n8k16.row.col.f32.bf16.bf16.f32 "
        "{%0,%1,%2,%3}, {%4,%5,%6,%7}, {%8,%9}, {%0,%1,%2,%3};\n"
        : "+f"(c[0]), "+f"(c[1]), "+f"(c[2]), "+f"(c[3])
        : "r"(a[0]), "r"(a[1]), "r"(a[2]), "r"(a[3]), "r"(b[0]), "r"(b[1]));
}

__device__ __forceinline__ uint32_t pack_bf2(float a, float b) {
    bf162 p = __float22bfloat162_rn(make_float2(a, b));
    return *(uint32_t*)&p;
}

// ---------------------------------------------------------------------------
// merged setup: weight conversion fp32->bf16 (float4 units 0..49151)
//               + padded bias gather (units 49152..)
// bias layout: [NH][98][112], cols 98..111 = -1e4 (exp -> exactly 0)
// ---------------------------------------------------------------------------
#define CVT_UNITS  49152
#define BIAS_UNITS (NH * NTOK * BSTR)   // 43904
__global__ void setup_kernel(const float* __restrict__ wq,
                             const float* __restrict__ wp,
                             const float* __restrict__ w1,
                             const float* __restrict__ w2,
                             const float* __restrict__ bias_table,
                             const int* __restrict__ rel_index) {
    int i = blockIdx.x * blockDim.x + threadIdx.x;
    if (i < CVT_UNITS) {
        const float* src; bf16* dst; int off;
        if (i < 12288)      { src = wq; dst = g_wq; off = i; }
        else if (i < 16384) { src = wp; dst = g_wp; off = i - 12288; }
        else if (i < 32768) { src = w1; dst = g_w1; off = i - 16384; }
        else                { src = w2; dst = g_w2; off = i - 32768; }
        float4 v = *(const float4*)(src + off * 4);
        uint2 u = make_uint2(pack_bf2(v.x, v.y), pack_bf2(v.z, v.w));
        *(uint2*)(dst + off * 4) = u;
    } else {
        int j = i - CVT_UNITS;
        if (j < BIAS_UNITS) {
            int h = j / (NTOK * BSTR);
            int r = j % (NTOK * BSTR);
            int n = r / BSTR;
            int m = r % BSTR;
            g_bias[j] = (m < NTOK) ? bias_table[rel_index[n * NTOK + m] * NH + h]
                                   : -10000.0f;
        }
    }
}

// ---------------------------------------------------------------------------
// LayerNorm over C=128 (fp32 in, bf16 out): one warp per token.
// PERMUTE=true: write window-partitioned order (for LN1).
// ---------------------------------------------------------------------------
template<bool PERMUTE>
__global__ __launch_bounds__(256)
void ln_kernel(const float* __restrict__ in,
               const float* __restrict__ gam,
               const float* __restrict__ bet,
               bf16* __restrict__ out) {
    int warp = threadIdx.x >> 5;
    int lane = threadIdx.x & 31;
    long t = (long)blockIdx.x * 8 + warp;
    const float4 v = *(const float4*)(in + t * CDIM + lane * 4);
    float s  = v.x + v.y + v.z + v.w;
    float sq = v.x * v.x + v.y * v.y + v.z * v.z + v.w * v.w;
    #pragma unroll
    for (int o = 16; o; o >>= 1) {
        s  += __shfl_xor_sync(0xffffffffu, s,  o);
        sq += __shfl_xor_sync(0xffffffffu, sq, o);
    }
    float mean = s * (1.0f / CDIM);
    float var  = sq * (1.0f / CDIM) - mean * mean;
    float rstd = rsqrtf(var + 1e-5f);
    const float4 g = *(const float4*)(gam + lane * 4);
    const float4 b = *(const float4*)(bet + lane * 4);
    uint2 u = make_uint2(pack_bf2((v.x - mean) * rstd * g.x + b.x,
                                  (v.y - mean) * rstd * g.y + b.y),
                         pack_bf2((v.z - mean) * rstd * g.z + b.z,
                                  (v.w - mean) * rstd * g.w + b.w));
    long orow = PERMUTE ? spatial_to_win(t) : t;
    *(uint2*)(out + orow * CDIM + lane * 4) = u;
}

// ---------------------------------------------------------------------------
// BF16 GEMM (R5 exact): 128x128 block, BK=32, 3-stage cp.async, warp 64x32.
// MODE 0: qkv  -> +bias; scale q-part (colBase==0); bf16 out [M,384]
// MODE 1: proj -> +bias; permute; += resid(x); fp32 g_x2  AND fused LN2 -> bf16 g_xw
// MODE 2: fc1  -> +bias; exact GELU; bf16 out [M,512]
// MODE 3: fc2  -> +bias; += resid(g_x2); fp32 out d_out
// ---------------------------------------------------------------------------
#define GS 40                  // smem row stride (halves): 32 + 8 pad
#define G_STAGE (256 * GS)     // As(128)+Ws(128) rows per stage
template<int MODE, int KT>
__global__ __launch_bounds__(256, 2)
void gemm_kernel(const bf16* __restrict__ A,
                 const bf16* __restrict__ Wt,
                 const float* __restrict__ bias,
                 const float* __restrict__ resid,
                 const float* __restrict__ gam,
                 const float* __restrict__ bet,
                 void* __restrict__ Cv,
                 int N) {
    extern __shared__ bf16 sm[];
    bf16* Asb[3] = { sm, sm + G_STAGE, sm + 2 * G_STAGE };
    bf16* Wsb[3] = { sm + 128 * GS, sm + G_STAGE + 128 * GS, sm + 2 * G_STAGE + 128 * GS };

    const int tid  = threadIdx.x;
    const int lane = tid & 31;
    const int warp = tid >> 5;
    const int warpM = warp >> 2;        // 0..1
    const int warpN = warp & 3;         // 0..3
    const int gid = lane >> 2;          // 0..7
    const int tig = lane & 3;           // 0..3

    const long rowBase = (long)blockIdx.y * 128;
    const int  colBase = blockIdx.x * 128;
    const int  K = KT;

    float cc[4][4][4];
    #pragma unroll
    for (int mi = 0; mi < 4; mi++)
        #pragma unroll
        for (int ni = 0; ni < 4; ni++)
            #pragma unroll
            for (int e = 0; e < 4; e++) cc[mi][ni][e] = 0.f;

    const int ld_row = tid >> 2;        // 0..63
    const int ld_kq  = (tid & 3) * 8;   // halves

    auto load_tile = [&](int buf, int k0) {
        #pragma unroll
        for (int r = 0; r < 2; r++) {
            int m = ld_row + r * 64;
            cp_async16(&Asb[buf][m * GS + ld_kq], A + (rowBase + m) * K + k0 + ld_kq);
        }
        #pragma unroll
        for (int r = 0; r < 2; r++) {
            int n = ld_row + r * 64;
            cp_async16(&Wsb[buf][n * GS + ld_kq], Wt + (long)(colBase + n) * K + k0 + ld_kq);
        }
    };

    constexpr int nk = KT / 32;
    load_tile(0, 0);  cp_commit();
    load_tile(1, 32); cp_commit();

    const int a_r = (lane & 7) + ((lane >> 3) & 1) * 8;
    const int a_k = (lane >> 4) * 8;
    const int b_n = (lane & 7) + (lane >> 4) * 8;
    const int b_k = ((lane >> 3) & 1) * 8;

    #pragma unroll
    for (int it = 0; it < nk; it++) {
        if (it < nk - 1) cp_wait<1>(); else cp_wait<0>();
        __syncthreads();
        if (it + 2 < nk) { load_tile((it + 2) % 3, (it + 2) * 32); cp_commit(); }

        const bf16* As = Asb[it % 3];
        const bf16* Ws = Wsb[it % 3];
        #pragma unroll
        for (int ks = 0; ks < 2; ks++) {
            const int kk = ks * 16;
            uint32_t af[4][4];
            uint32_t bf[4][2];
            #pragma unroll
            for (int mi = 0; mi < 4; mi++)
                ldsm_x4(af[mi], As + (warpM * 64 + mi * 16 + a_r) * GS + kk + a_k);
            #pragma unroll
            for (int np = 0; np < 2; np++) {
                uint32_t r4[4];
                ldsm_x4(r4, Ws + (warpN * 32 + np * 16 + b_n) * GS + kk + b_k);
                bf[2 * np][0] = r4[0]; bf[2 * np][1] = r4[1];
                bf[2 * np + 1][0] = r4[2]; bf[2 * np + 1][1] = r4[3];
            }
            #pragma unroll
            for (int mi = 0; mi < 4; mi++)
                #pragma unroll
                for (int ni = 0; ni < 4; ni++)
                    mma_bf16(cc[mi][ni], af[mi], bf[ni]);
        }
    }

    if (MODE == 1) {
        __syncthreads();                 // all warps done with smem stages
        float* red = (float*)sm;         // [128][2] row sums
        if (tid < 128) { red[2 * tid] = 0.f; red[2 * tid + 1] = 0.f; }
        __syncthreads();

        long orows[4][2];
        float* C = (float*)Cv;
        #pragma unroll
        for (int mi = 0; mi < 4; mi++) {
            #pragma unroll
            for (int half = 0; half < 2; half++) {
                int rloc = warpM * 64 + mi * 16 + gid + half * 8;
                long orow = win_to_spatial(rowBase + rloc);
                orows[mi][half] = orow;
                float s = 0.f, sq = 0.f;
                #pragma unroll
                for (int ni = 0; ni < 4; ni++) {
                    int col = warpN * 32 + ni * 8 + 2 * tig;
                    const float2 r = *(const float2*)(resid + orow * CDIM + col);
                    float v0 = cc[mi][ni][half * 2 + 0] + bias[col]     + r.x;
                    float v1 = cc[mi][ni][half * 2 + 1] + bias[col + 1] + r.y;
                    cc[mi][ni][half * 2 + 0] = v0;
                    cc[mi][ni][half * 2 + 1] = v1;
                    *(float2*)(C + orow * CDIM + col) = make_float2(v0, v1);
                    s += v0 + v1; sq += v0 * v0 + v1 * v1;
                }
                s  += __shfl_xor_sync(0xffffffffu, s, 1);
                sq += __shfl_xor_sync(0xffffffffu, sq, 1);
                s  += __shfl_xor_sync(0xffffffffu, s, 2);
                sq += __shfl_xor_sync(0xffffffffu, sq, 2);
                if (tig == 0) {
                    atomicAdd(&red[2 * rloc],     s);
                    atomicAdd(&red[2 * rloc + 1], sq);
                }
            }
        }
        __syncthreads();
        #pragma unroll
        for (int mi = 0; mi < 4; mi++) {
            #pragma unroll
            for (int half = 0; half < 2; half++) {
                int rloc = warpM * 64 + mi * 16 + gid + half * 8;
                long orow = orows[mi][half];
                float mean = red[2 * rloc] * (1.0f / CDIM);
                float var  = red[2 * rloc + 1] * (1.0f / CDIM) - mean * mean;
                float rstd = rsqrtf(var + 1e-5f);
                #pragma unroll
                for (int ni = 0; ni < 4; ni++) {
                    int col = warpN * 32 + ni * 8 + 2 * tig;
                    float v0 = cc[mi][ni][half * 2 + 0];
                    float v1 = cc[mi][ni][half * 2 + 1];
                    float y0 = (v0 - mean) * rstd * gam[col]     + bet[col];
                    float y1 = (v1 - mean) * rstd * gam[col + 1] + bet[col + 1];
                    *(uint32_t*)(g_xw + orow * CDIM + col) = pack_bf2(y0, y1);
                }
            }
        }
        return;
    }

    #pragma unroll
    for (int mi = 0; mi < 4; mi++) {
        #pragma unroll
        for (int half = 0; half < 2; half++) {
            long row = rowBase + warpM * 64 + mi * 16 + gid + half * 8;
            #pragma unroll
            for (int ni = 0; ni < 4; ni++) {
                int col = colBase + warpN * 32 + ni * 8 + 2 * tig;
                float v0 = cc[mi][ni][half * 2 + 0] + bias[col];
                float v1 = cc[mi][ni][half * 2 + 1] + bias[col + 1];
                if (MODE == 0) {
                    if (colBase == 0) { v0 *= 0.17677669529663687f; v1 *= 0.17677669529663687f; }
                }
                if (MODE == 2) {
                    v0 = 0.5f * v0 * (1.0f + erff(v0 * 0.70710678118654752f));
                    v1 = 0.5f * v1 * (1.0f + erff(v1 * 0.70710678118654752f));
                }
                if (MODE == 3) {
                    float* C = (float*)Cv;
                    const float2 r = *(const float2*)(resid + row * CDIM + col);
                    *(float2*)(C + row * CDIM + col) = make_float2(v0 + r.x, v1 + r.y);
                } else {
                    bf16* C = (bf16*)Cv;
                    *(uint32_t*)(C + row * (long)N + col) = pack_bf2(v0, v1);
                }
            }
        }
    }
}

// ---------------------------------------------------------------------------
// BF16 tensor-core window attention, FA2-style register P:
// S accumulator fragments are re-packed IN REGISTERS as A fragments for
// O = P*V (no P smem round-trip). Padded bias -> branch-free float2 loads.
// smem: qs[128][40], ks[112][40], vsr[112][40] = 28160 B. 4 CTAs/SM.
// ---------------------------------------------------------------------------
#define AQS 40
#define NPAD 112
#define ATTN_ELEMS ((128 + 2 * NPAD) * AQS)   // 14080 bf16 = 28160 B
__global__ __launch_bounds__(128, 4)
void attn_kernel() {
    extern __shared__ bf16 asm_[];
    bf16* qs  = asm_;                          // [128][40]
    bf16* ks  = asm_ + 128 * AQS;              // [112][40]
    bf16* vsr = asm_ + (128 + NPAD) * AQS;     // [112][40]

    const int w = blockIdx.x;
    const int h = blockIdx.y;
    const int tid  = threadIdx.x;
    const int warp = tid >> 5;
    const int lane = tid & 31;
    const int gid = lane >> 2;
    const int tig = lane & 3;

    const bf16* base = g_qkv + (size_t)w * NTOK * QKVN + h * HD;

    for (int i = tid; i < NTOK * 4; i += 128) {
        int m = i >> 2, c = (i & 3) * 8;
        *(uint4*)&qs [m * AQS + c] = *(const uint4*)(base + m * QKVN + c);
        *(uint4*)&ks [m * AQS + c] = *(const uint4*)(base + m * QKVN + CDIM + c);
        *(uint4*)&vsr[m * AQS + c] = *(const uint4*)(base + m * QKVN + 2 * CDIM + c);
    }
    const uint4 z4 = make_uint4(0, 0, 0, 0);
    for (int i = tid; i < 30 * 4; i += 128) {
        int m = 98 + (i >> 2), c = (i & 3) * 8;
        *(uint4*)&qs[m * AQS + c] = z4;
        if (m < NPAD) {
            *(uint4*)&ks [m * AQS + c] = z4;
            *(uint4*)&vsr[m * AQS + c] = z4;
        }
    }
    __syncthreads();

    const int a_r = (lane & 7) + ((lane >> 3) & 1) * 8;
    const int a_k = (lane >> 4) * 8;
    const int b_n = (lane & 7) + (lane >> 4) * 8;
    const int b_k = ((lane >> 3) & 1) * 8;
    const int t_r = (lane & 7) + ((lane >> 3) & 1) * 8;
    const int t_c = (lane >> 4) * 8;

    // ---- S = Q K^T : 32 rows x 112 cols, k=32 ----
    float cc[2][14][4];
    #pragma unroll
    for (int mi = 0; mi < 2; mi++)
        #pragma unroll
        for (int ni = 0; ni < 14; ni++)
            #pragma unroll
            for (int e = 0; e < 4; e++) cc[mi][ni][e] = 0.f;

    #pragma unroll
    for (int ksx = 0; ksx < 2; ksx++) {
        const int kk = ksx * 16;
        uint32_t af[2][4];
        #pragma unroll
        for (int mi = 0; mi < 2; mi++)
            ldsm_x4(af[mi], qs + (warp * 32 + mi * 16 + a_r) * AQS + kk + a_k);
        #pragma unroll
        for (int np = 0; np < 7; np++) {
            uint32_t r4[4];
            ldsm_x4(r4, ks + (np * 16 + b_n) * AQS + kk + b_k);
            uint32_t b0[2] = { r4[0], r4[1] };
            uint32_t b1[2] = { r4[2], r4[3] };
            mma_bf16(cc[0][2 * np],     af[0], b0);
            mma_bf16(cc[1][2 * np],     af[1], b0);
            mma_bf16(cc[0][2 * np + 1], af[0], b1);
            mma_bf16(cc[1][2 * np + 1], af[1], b1);
        }
    }

    // ---- softmax: branch-free with padded bias (pad cols -> exp = 0) ----
    float rsum[2][2] = {{0.f, 0.f}, {0.f, 0.f}};
    const float* gb = g_bias + h * NTOK * BSTR;
    #pragma unroll
    for (int mi = 0; mi < 2; mi++) {
        int r0 = warp * 32 + mi * 16 + gid;
        int r1 = r0 + 8;
        const float* b0p = gb + (r0 < NTOK ? r0 : NTOK - 1) * BSTR;
        const float* b1p = gb + (r1 < NTOK ? r1 : NTOK - 1) * BSTR;
        #pragma unroll
        for (int ni = 0; ni < 14; ni++) {
            int col = ni * 8 + 2 * tig;
            float2 bb0 = *(const float2*)(b0p + col);
            float2 bb1 = *(const float2*)(b1p + col);
            float e;
            e = __expf(cc[mi][ni][0] + bb0.x); cc[mi][ni][0] = e; rsum[mi][0] += e;
            e = __expf(cc[mi][ni][1] + bb0.y); cc[mi][ni][1] = e; rsum[mi][0] += e;
            e = __expf(cc[mi][ni][2] + bb1.x); cc[mi][ni][2] = e; rsum[mi][1] += e;
            e = __expf(cc[mi][ni][3] + bb1.y); cc[mi][ni][3] = e; rsum[mi][1] += e;
        }
    }
    float inv[2][2];
    #pragma unroll
    for (int mi = 0; mi < 2; mi++)
        #pragma unroll
        for (int hf = 0; hf < 2; hf++) {
            float s = rsum[mi][hf];
            s += __shfl_xor_sync(0xffffffffu, s, 1);
            s += __shfl_xor_sync(0xffffffffu, s, 2);
            inv[mi][hf] = 1.0f / s;
        }

    // ---- O = P V : P stays in registers (C-fragment == A-fragment layout) ----
    float oo[2][4][4];
    #pragma unroll
    for (int mi = 0; mi < 2; mi++)
        #pragma unroll
        for (int ni = 0; ni < 4; ni++)
            #pragma unroll
            for (int e = 0; e < 4; e++) oo[mi][ni][e] = 0.f;

    #pragma unroll
    for (int k2 = 0; k2 < 7; k2++) {
        const int kk = k2 * 16;
        uint32_t af[2][4];
        #pragma unroll
        for (int mi = 0; mi < 2; mi++) {
            // a0/a1: k in [0,8) -> S tile 2*k2; a2/a3: k in [8,16) -> tile 2*k2+1
            af[mi][0] = pack_bf2(cc[mi][2 * k2][0]     * inv[mi][0], cc[mi][2 * k2][1]     * inv[mi][0]);
            af[mi][1] = pack_bf2(cc[mi][2 * k2][2]     * inv[mi][1], cc[mi][2 * k2][3]     * inv[mi][1]);
            af[mi][2] = pack_bf2(cc[mi][2 * k2 + 1][0] * inv[mi][0], cc[mi][2 * k2 + 1][1] * inv[mi][0]);
            af[mi][3] = pack_bf2(cc[mi][2 * k2 + 1][2] * inv[mi][1], cc[mi][2 * k2 + 1][3] * inv[mi][1]);
        }
        #pragma unroll
        for (int np = 0; np < 2; np++) {
            int n0 = np * 16;
            uint32_t r4[4];
            ldsm_x4_t(r4, vsr + (kk + t_r) * AQS + n0 + t_c);
            uint32_t b0[2] = { r4[0], r4[1] };
            uint32_t b1[2] = { r4[2], r4[3] };
            mma_bf16(oo[0][2 * np],     af[0], b0);
            mma_bf16(oo[1][2 * np],     af[1], b0);
            mma_bf16(oo[0][2 * np + 1], af[0], b1);
            mma_bf16(oo[1][2 * np + 1], af[1], b1);
        }
    }

    #pragma unroll
    for (int mi = 0; mi < 2; mi++) {
        #pragma unroll
        for (int hf = 0; hf < 2; hf++) {
            int row = warp * 32 + mi * 16 + gid + hf * 8;
            if (row < NTOK) {
                bf16* op = g_attn + ((size_t)w * NTOK + row) * CDIM + h * HD;
                #pragma unroll
                for (int ni = 0; ni < 4; ni++) {
                    int col = ni * 8 + 2 * tig;
                    *(uint32_t*)(op + col) =
                        pack_bf2(oo[mi][ni][hf * 2], oo[mi][ni][hf * 2 + 1]);
                }
            }
        }
    }
}

// ---------------------------------------------------------------------------
// launcher
// ---------------------------------------------------------------------------
extern "C" void kernel_launch(void* const* d_in, const int* in_sizes, int n_in,
                              void* d_out, int out_size) {
    const float* x          = (const float*)d_in[0];
    const float* norm1_w    = (const float*)d_in[1];
    const float* norm1_b    = (const float*)d_in[2];
    const float* qkv_w      = (const float*)d_in[3];
    const float* qkv_b      = (const float*)d_in[4];
    const float* bias_table = (const float*)d_in[5];
    const float* proj_w     = (const float*)d_in[6];
    const float* proj_b     = (const float*)d_in[7];
    const float* norm2_w    = (const float*)d_in[8];
    const float* norm2_b    = (const float*)d_in[9];
    const float* fc1_w      = (const float*)d_in[10];
    const float* fc1_b      = (const float*)d_in[11];
    const float* fc2_w      = (const float*)d_in[12];
    const float* fc2_b      = (const float*)d_in[13];
    const int*   rel_index  = (const int*)d_in[14];
    float* out = (float*)d_out;

    bf16 *p_xw, *p_qkv, *p_attn, *p_h;
    bf16 *p_wq, *p_wp, *p_w1, *p_w2;
    float *p_x2;
    cudaGetSymbolAddress((void**)&p_xw,   g_xw);
    cudaGetSymbolAddress((void**)&p_qkv,  g_qkv);
    cudaGetSymbolAddress((void**)&p_attn, g_attn);
    cudaGetSymbolAddress((void**)&p_x2,   g_x2);
    cudaGetSymbolAddress((void**)&p_h,    g_h);
    cudaGetSymbolAddress((void**)&p_wq,   g_wq);
    cudaGetSymbolAddress((void**)&p_wp,   g_wp);
    cudaGetSymbolAddress((void**)&p_w1,   g_w1);
    cudaGetSymbolAddress((void**)&p_w2,   g_w2);

    const int GEMM_SMEM = 3 * G_STAGE * (int)sizeof(bf16);   // 61440
    const int ATTN_SMEM = ATTN_ELEMS * (int)sizeof(bf16);    // 28160
    cudaFuncSetAttribute((const void*)gemm_kernel<0,128>, cudaFuncAttributeMaxDynamicSharedMemorySize, GEMM_SMEM);
    cudaFuncSetAttribute((const void*)gemm_kernel<1,128>, cudaFuncAttributeMaxDynamicSharedMemorySize, GEMM_SMEM);
    cudaFuncSetAttribute((const void*)gemm_kernel<2,128>, cudaFuncAttributeMaxDynamicSharedMemorySize, GEMM_SMEM);
    cudaFuncSetAttribute((const void*)gemm_kernel<3,512>, cudaFuncAttributeMaxDynamicSharedMemorySize, GEMM_SMEM);
    cudaFuncSetAttribute((const void*)attn_kernel,        cudaFuncAttributeMaxDynamicSharedMemorySize, ATTN_SMEM);

    // 0) merged setup: weight conversion + padded bias gather
    setup_kernel<<<(CVT_UNITS + BIAS_UNITS + 255) / 256, 256>>>(
        qkv_w, proj_w, fc1_w, fc2_w, bias_table, rel_index);

    // 1) LN1 + window partition (fp32 -> bf16)
    ln_kernel<true><<<TOK / 8, 256>>>(x, norm1_w, norm1_b, p_xw);

    // 2) QKV gemm (+ q scale), bf16 out
    gemm_kernel<0,128><<<dim3(QKVN / 128, TOK / 128), 256, GEMM_SMEM>>>(
        p_xw, p_wq, qkv_b, nullptr, nullptr, nullptr, p_qkv, QKVN);

    // 3) window attention (bf16 tensor cores, register-P)
    attn_kernel<<<dim3(NWIN, NH), 128, ATTN_SMEM>>>();

    // 4) proj gemm + window reverse + residual(x) -> g_x2 (fp32) + fused LN2 -> g_xw (bf16)
    gemm_kernel<1,128><<<dim3(CDIM / 128, TOK / 128), 256, GEMM_SMEM>>>(
        p_attn, p_wp, proj_b, x, norm2_w, norm2_b, p_x2, CDIM);

    // 5) fc1 + exact GELU, bf16 out
    gemm_kernel<2,128><<<dim3(CH / 128, TOK / 128), 256, GEMM_SMEM>>>(
        p_xw, p_w1, fc1_b, nullptr, nullptr, nullptr, p_h, CH);

    // 6) fc2 + residual(g_x2) -> d_out (fp32)
    gemm_kernel<3,512><<<dim3(CDIM / 128, TOK / 128), 256, GEMM_SMEM>>>(
        p_h, p_w2, fc2_b, p_x2, nullptr, nullptr, out, CDIM);

    (void)in_sizes; (void)n_in; (void)out_size;
}

// round 14
// speedup vs baseline: 1.1286x; 1.0139x over previous
#include <cuda_runtime.h>
#include <cuda_bf16.h>
#include <math.h>
#include <stdint.h>

// ---------------------------------------------------------------------------
// Problem constants
// ---------------------------------------------------------------------------
#define TOK   50176      // 2*8*56*56
#define CDIM  128
#define CH    512
#define NWIN  512        // 2 * 4*8*8
#define NTOK  98         // 2*7*7
#define NH    4
#define HD    32
#define QKVN  384
#define BSTR  112        // padded bias row stride

typedef __nv_bfloat16  bf16;
typedef __nv_bfloat162 bf162;

// ---------------------------------------------------------------------------
// Scratch (device globals: allocation-free, graph-capture safe)
// ---------------------------------------------------------------------------
__device__ bf16  g_xw  [(size_t)TOK * CDIM];   // LN1 out (window order) / LN2 out (spatial)
__device__ bf16  g_qkv [(size_t)TOK * QKVN];   // qkv, window order
__device__ bf16  g_attn[(size_t)TOK * CDIM];   // attention out, window order
__device__ float g_x2  [(size_t)TOK * CDIM];   // x + proj (spatial, fp32)
__device__ bf16  g_h   [(size_t)TOK * CH];     // fc1 output
__device__ float g_bias[NH * NTOK * BSTR];     // gathered attention bias, padded cols
// bf16 weights
__device__ bf16  g_wq[QKVN * CDIM];
__device__ bf16  g_wp[CDIM * CDIM];
__device__ bf16  g_w1[CH * CDIM];
__device__ bf16  g_w2[CDIM * CH];

// ---------------------------------------------------------------------------
// index helpers
// ---------------------------------------------------------------------------
__device__ __forceinline__ long win_to_spatial(long row) {
    int w = (int)(row / NTOK);
    int n = (int)(row % NTOK);
    int b   = w >> 8;
    int rem = w & 255;
    int wdi = rem >> 6, whi = (rem >> 3) & 7, wwi = rem & 7;
    int zd = n / 49; int r2 = n % 49; int zh = r2 / 7, zw = r2 % 7;
    int d  = wdi * 2 + zd;
    int hh = whi * 7 + zh;
    int xx = wwi * 7 + zw;
    return (((long)(b * 8 + d) * 56) + hh) * 56 + xx;
}

__device__ __forceinline__ long spatial_to_win(long t) {
    int b  = (int)(t / 25088);
    int r  = (int)(t % 25088);
    int d  = r / 3136; r %= 3136;
    int hh = r / 56;
    int xx = r % 56;
    int widx = ((b * 4 + (d >> 1)) * 8 + hh / 7) * 8 + xx / 7;
    int n    = ((d & 1) * 7 + hh % 7) * 7 + xx % 7;
    return (long)widx * NTOK + n;
}

// ---------------------------------------------------------------------------
// async copy + ldmatrix + mma helpers
// ---------------------------------------------------------------------------
__device__ __forceinline__ void cp_async16(bf16* smem_dst, const bf16* gmem_src) {
    uint32_t s = (uint32_t)__cvta_generic_to_shared(smem_dst);
    asm volatile("cp.async.cg.shared.global [%0], [%1], 16;\n" :: "r"(s), "l"(gmem_src));
}
__device__ __forceinline__ void cp_commit() { asm volatile("cp.async.commit_group;\n"); }
template<int N>
__device__ __forceinline__ void cp_wait() { asm volatile("cp.async.wait_group %0;\n" :: "n"(N)); }

__device__ __forceinline__ void ldsm_x4(uint32_t r[4], const bf16* p) {
    uint32_t a = (uint32_t)__cvta_generic_to_shared(p);
    asm volatile("ldmatrix.sync.aligned.m8n8.x4.shared.b16 {%0,%1,%2,%3}, [%4];\n"
                 : "=r"(r[0]), "=r"(r[1]), "=r"(r[2]), "=r"(r[3]) : "r"(a));
}
__device__ __forceinline__ void ldsm_x4_t(uint32_t r[4], const bf16* p) {
    uint32_t a = (uint32_t)__cvta_generic_to_shared(p);
    asm volatile("ldmatrix.sync.aligned.m8n8.x4.trans.shared.b16 {%0,%1,%2,%3}, [%4];\n"
                 : "=r"(r[0]), "=r"(r[1]), "=r"(r[2]), "=r"(r[3]) : "r"(a));
}
__device__ __forceinline__ void mma_bf16(float c[4], const uint32_t a[4], const uint32_t b[2]) {
    asm volatile(
        "mma.sync.aligned.m16n8k16.row.col.f32.bf16.bf16.f32 "
        "{%0,%1,%2,%3}, {%4,%5,%6,%7}, {%8,%9}, {%0,%1,%2,%3};\n"
        : "+f"(c[0]), "+f"(c[1]), "+f"(c[2]), "+f"(c[3])
        : "r"(a[0]), "r"(a[1]), "r"(a[2]), "r"(a[3]), "r"(b[0]), "r"(b[1]));
}

__device__ __forceinline__ uint32_t pack_bf2(float a, float b) {
    bf162 p = __float22bfloat162_rn(make_float2(a, b));
    return *(uint32_t*)&p;
}

// ---------------------------------------------------------------------------
// merged setup: weight conversion fp32->bf16 (float4 units 0..49151)
//               + padded bias gather (units 49152..)
// bias layout: [NH][98][112], cols 98..111 = -1e4 (exp -> exactly 0)
// ---------------------------------------------------------------------------
#define CVT_UNITS  49152
#define BIAS_UNITS (NH * NTOK * BSTR)   // 43904
__global__ void setup_kernel(const float* __restrict__ wq,
                             const float* __restrict__ wp,
                             const float* __restrict__ w1,
                             const float* __restrict__ w2,
                             const float* __restrict__ bias_table,
                             const int* __restrict__ rel_index) {
    int i = blockIdx.x * blockDim.x + threadIdx.x;
    if (i < CVT_UNITS) {
        const float* src; bf16* dst; int off;
        if (i < 12288)      { src = wq; dst = g_wq; off = i; }
        else if (i < 16384) { src = wp; dst = g_wp; off = i - 12288; }
        else if (i < 32768) { src = w1; dst = g_w1; off = i - 16384; }
        else                { src = w2; dst = g_w2; off = i - 32768; }
        float4 v = *(const float4*)(src + off * 4);
        uint2 u = make_uint2(pack_bf2(v.x, v.y), pack_bf2(v.z, v.w));
        *(uint2*)(dst + off * 4) = u;
    } else {
        int j = i - CVT_UNITS;
        if (j < BIAS_UNITS) {
            int h = j / (NTOK * BSTR);
            int r = j % (NTOK * BSTR);
            int n = r / BSTR;
            int m = r % BSTR;
            g_bias[j] = (m < NTOK) ? bias_table[rel_index[n * NTOK + m] * NH + h]
                                   : -10000.0f;
        }
    }
}

// ---------------------------------------------------------------------------
// LayerNorm over C=128 (fp32 in, bf16 out): one warp per token.
// PERMUTE=true: write window-partitioned order (for LN1).
// ---------------------------------------------------------------------------
template<bool PERMUTE>
__global__ __launch_bounds__(256)
void ln_kernel(const float* __restrict__ in,
               const float* __restrict__ gam,
               const float* __restrict__ bet,
               bf16* __restrict__ out) {
    int warp = threadIdx.x >> 5;
    int lane = threadIdx.x & 31;
    long t = (long)blockIdx.x * 8 + warp;
    const float4 v = *(const float4*)(in + t * CDIM + lane * 4);
    float s  = v.x + v.y + v.z + v.w;
    float sq = v.x * v.x + v.y * v.y + v.z * v.z + v.w * v.w;
    #pragma unroll
    for (int o = 16; o; o >>= 1) {
        s  += __shfl_xor_sync(0xffffffffu, s,  o);
        sq += __shfl_xor_sync(0xffffffffu, sq, o);
    }
    float mean = s * (1.0f / CDIM);
    float var  = sq * (1.0f / CDIM) - mean * mean;
    float rstd = rsqrtf(var + 1e-5f);
    const float4 g = *(const float4*)(gam + lane * 4);
    const float4 b = *(const float4*)(bet + lane * 4);
    uint2 u = make_uint2(pack_bf2((v.x - mean) * rstd * g.x + b.x,
                                  (v.y - mean) * rstd * g.y + b.y),
                         pack_bf2((v.z - mean) * rstd * g.z + b.z,
                                  (v.w - mean) * rstd * g.w + b.w));
    long orow = PERMUTE ? spatial_to_win(t) : t;
    *(uint2*)(out + orow * CDIM + lane * 4) = u;
}

// ---------------------------------------------------------------------------
// BF16 GEMM (R5 exact): 128x128 block, BK=32, 3-stage cp.async, warp 64x32.
// MODE 0: qkv  -> +bias; scale q-part (colBase==0); bf16 out [M,384]
// MODE 1: proj -> +bias; permute; += resid(x); fp32 g_x2  AND fused LN2 -> bf16 g_xw
// MODE 2: fc1  -> +bias; exact GELU; bf16 out [M,512]
// MODE 3: fc2  -> +bias; += resid(g_x2); fp32 out d_out
// ---------------------------------------------------------------------------
#define GS 40                  // smem row stride (halves): 32 + 8 pad
#define G_STAGE (256 * GS)     // As(128)+Ws(128) rows per stage
template<int MODE, int KT>
__global__ __launch_bounds__(256, 2)
void gemm_kernel(const bf16* __restrict__ A,
                 const bf16* __restrict__ Wt,
                 const float* __restrict__ bias,
                 const float* __restrict__ resid,
                 const float* __restrict__ gam,
                 const float* __restrict__ bet,
                 void* __restrict__ Cv,
                 int N) {
    extern __shared__ bf16 sm[];
    bf16* Asb[3] = { sm, sm + G_STAGE, sm + 2 * G_STAGE };
    bf16* Wsb[3] = { sm + 128 * GS, sm + G_STAGE + 128 * GS, sm + 2 * G_STAGE + 128 * GS };

    const int tid  = threadIdx.x;
    const int lane = tid & 31;
    const int warp = tid >> 5;
    const int warpM = warp >> 2;        // 0..1
    const int warpN = warp & 3;         // 0..3
    const int gid = lane >> 2;          // 0..7
    const int tig = lane & 3;           // 0..3

    const long rowBase = (long)blockIdx.y * 128;
    const int  colBase = blockIdx.x * 128;
    const int  K = KT;

    float cc[4][4][4];
    #pragma unroll
    for (int mi = 0; mi < 4; mi++)
        #pragma unroll
        for (int ni = 0; ni < 4; ni++)
            #pragma unroll
            for (int e = 0; e < 4; e++) cc[mi][ni][e] = 0.f;

    const int ld_row = tid >> 2;        // 0..63
    const int ld_kq  = (tid & 3) * 8;   // halves

    auto load_tile = [&](int buf, int k0) {
        #pragma unroll
        for (int r = 0; r < 2; r++) {
            int m = ld_row + r * 64;
            cp_async16(&Asb[buf][m * GS + ld_kq], A + (rowBase + m) * K + k0 + ld_kq);
        }
        #pragma unroll
        for (int r = 0; r < 2; r++) {
            int n = ld_row + r * 64;
            cp_async16(&Wsb[buf][n * GS + ld_kq], Wt + (long)(colBase + n) * K + k0 + ld_kq);
        }
    };

    constexpr int nk = KT / 32;
    load_tile(0, 0);  cp_commit();
    load_tile(1, 32); cp_commit();

    const int a_r = (lane & 7) + ((lane >> 3) & 1) * 8;
    const int a_k = (lane >> 4) * 8;
    const int b_n = (lane & 7) + (lane >> 4) * 8;
    const int b_k = ((lane >> 3) & 1) * 8;

    #pragma unroll
    for (int it = 0; it < nk; it++) {
        if (it < nk - 1) cp_wait<1>(); else cp_wait<0>();
        __syncthreads();
        if (it + 2 < nk) { load_tile((it + 2) % 3, (it + 2) * 32); cp_commit(); }

        const bf16* As = Asb[it % 3];
        const bf16* Ws = Wsb[it % 3];
        #pragma unroll
        for (int ks = 0; ks < 2; ks++) {
            const int kk = ks * 16;
            uint32_t af[4][4];
            uint32_t bf[4][2];
            #pragma unroll
            for (int mi = 0; mi < 4; mi++)
                ldsm_x4(af[mi], As + (warpM * 64 + mi * 16 + a_r) * GS + kk + a_k);
            #pragma unroll
            for (int np = 0; np < 2; np++) {
                uint32_t r4[4];
                ldsm_x4(r4, Ws + (warpN * 32 + np * 16 + b_n) * GS + kk + b_k);
                bf[2 * np][0] = r4[0]; bf[2 * np][1] = r4[1];
                bf[2 * np + 1][0] = r4[2]; bf[2 * np + 1][1] = r4[3];
            }
            #pragma unroll
            for (int mi = 0; mi < 4; mi++)
                #pragma unroll
                for (int ni = 0; ni < 4; ni++)
                    mma_bf16(cc[mi][ni], af[mi], bf[ni]);
        }
    }

    if (MODE == 1) {
        __syncthreads();                 // all warps done with smem stages
        float* red = (float*)sm;         // [128][2] row sums
        if (tid < 128) { red[2 * tid] = 0.f; red[2 * tid + 1] = 0.f; }
        __syncthreads();

        long orows[4][2];
        float* C = (float*)Cv;
        #pragma unroll
        for (int mi = 0; mi < 4; mi++) {
            #pragma unroll
            for (int half = 0; half < 2; half++) {
                int rloc = warpM * 64 + mi * 16 + gid + half * 8;
                long orow = win_to_spatial(rowBase + rloc);
                orows[mi][half] = orow;
                float s = 0.f, sq = 0.f;
                #pragma unroll
                for (int ni = 0; ni < 4; ni++) {
                    int col = warpN * 32 + ni * 8 + 2 * tig;
                    const float2 r = *(const float2*)(resid + orow * CDIM + col);
                    float v0 = cc[mi][ni][half * 2 + 0] + bias[col]     + r.x;
                    float v1 = cc[mi][ni][half * 2 + 1] + bias[col + 1] + r.y;
                    cc[mi][ni][half * 2 + 0] = v0;
                    cc[mi][ni][half * 2 + 1] = v1;
                    *(float2*)(C + orow * CDIM + col) = make_float2(v0, v1);
                    s += v0 + v1; sq += v0 * v0 + v1 * v1;
                }
                s  += __shfl_xor_sync(0xffffffffu, s, 1);
                sq += __shfl_xor_sync(0xffffffffu, sq, 1);
                s  += __shfl_xor_sync(0xffffffffu, s, 2);
                sq += __shfl_xor_sync(0xffffffffu, sq, 2);
                if (tig == 0) {
                    atomicAdd(&red[2 * rloc],     s);
                    atomicAdd(&red[2 * rloc + 1], sq);
                }
            }
        }
        __syncthreads();
        #pragma unroll
        for (int mi = 0; mi < 4; mi++) {
            #pragma unroll
            for (int half = 0; half < 2; half++) {
                int rloc = warpM * 64 + mi * 16 + gid + half * 8;
                long orow = orows[mi][half];
                float mean = red[2 * rloc] * (1.0f / CDIM);
                float var  = red[2 * rloc + 1] * (1.0f / CDIM) - mean * mean;
                float rstd = rsqrtf(var + 1e-5f);
                #pragma unroll
                for (int ni = 0; ni < 4; ni++) {
                    int col = warpN * 32 + ni * 8 + 2 * tig;
                    float v0 = cc[mi][ni][half * 2 + 0];
                    float v1 = cc[mi][ni][half * 2 + 1];
                    float y0 = (v0 - mean) * rstd * gam[col]     + bet[col];
                    float y1 = (v1 - mean) * rstd * gam[col + 1] + bet[col + 1];
                    *(uint32_t*)(g_xw + orow * CDIM + col) = pack_bf2(y0, y1);
                }
            }
        }
        return;
    }

    #pragma unroll
    for (int mi = 0; mi < 4; mi++) {
        #pragma unroll
        for (int half = 0; half < 2; half++) {
            long row = rowBase + warpM * 64 + mi * 16 + gid + half * 8;
            #pragma unroll
            for (int ni = 0; ni < 4; ni++) {
                int col = colBase + warpN * 32 + ni * 8 + 2 * tig;
                float v0 = cc[mi][ni][half * 2 + 0] + bias[col];
                float v1 = cc[mi][ni][half * 2 + 1] + bias[col + 1];
                if (MODE == 0) {
                    if (colBase == 0) { v0 *= 0.17677669529663687f; v1 *= 0.17677669529663687f; }
                }
                if (MODE == 2) {
                    v0 = 0.5f * v0 * (1.0f + erff(v0 * 0.70710678118654752f));
                    v1 = 0.5f * v1 * (1.0f + erff(v1 * 0.70710678118654752f));
                }
                if (MODE == 3) {
                    float* C = (float*)Cv;
                    const float2 r = *(const float2*)(resid + row * CDIM + col);
                    *(float2*)(C + row * CDIM + col) = make_float2(v0 + r.x, v1 + r.y);
                } else {
                    bf16* C = (bf16*)Cv;
                    *(uint32_t*)(C + row * (long)N + col) = pack_bf2(v0, v1);
                }
            }
        }
    }
}

// ---------------------------------------------------------------------------
// BF16 tensor-core window attention, FA2-style register P + cp.async loads.
// Q pad rows (98..127) intentionally NOT zeroed: their S/P/O fragments are
// row-private and discarded by the row<NTOK store guard. K/V pads stay zero
// (they feed columns entering every row's softmax sum).
// smem: qs[128][40], ks[112][40], vsr[112][40] = 28160 B. 4 CTAs/SM.
// ---------------------------------------------------------------------------
#define AQS 40
#define NPAD 112
#define ATTN_ELEMS ((128 + 2 * NPAD) * AQS)   // 14080 bf16 = 28160 B
__global__ __launch_bounds__(128, 4)
void attn_kernel() {
    extern __shared__ bf16 asm_[];
    bf16* qs  = asm_;                          // [128][40]
    bf16* ks  = asm_ + 128 * AQS;              // [112][40]
    bf16* vsr = asm_ + (128 + NPAD) * AQS;     // [112][40]

    const int w = blockIdx.x;
    const int h = blockIdx.y;
    const int tid  = threadIdx.x;
    const int warp = tid >> 5;
    const int lane = tid & 31;
    const int gid = lane >> 2;
    const int tig = lane & 3;

    const bf16* base = g_qkv + (size_t)w * NTOK * QKVN + h * HD;

    // q/k/v tile loads via cp.async (1 instr per 16B, no reg round-trip)
    for (int i = tid; i < NTOK * 4; i += 128) {
        int m = i >> 2, c = (i & 3) * 8;
        cp_async16(&qs [m * AQS + c], base + m * QKVN + c);
        cp_async16(&ks [m * AQS + c], base + m * QKVN + CDIM + c);
        cp_async16(&vsr[m * AQS + c], base + m * QKVN + 2 * CDIM + c);
    }
    // zero K/V pad rows 98..111 (Q pads left uninitialized: rows discarded)
    const uint4 z4 = make_uint4(0, 0, 0, 0);
    if (tid < 14 * 4) {
        int m = 98 + (tid >> 2), c = (tid & 3) * 8;
        *(uint4*)&ks [m * AQS + c] = z4;
        *(uint4*)&vsr[m * AQS + c] = z4;
    }
    cp_commit();
    cp_wait<0>();
    __syncthreads();

    const int a_r = (lane & 7) + ((lane >> 3) & 1) * 8;
    const int a_k = (lane >> 4) * 8;
    const int b_n = (lane & 7) + (lane >> 4) * 8;
    const int b_k = ((lane >> 3) & 1) * 8;
    const int t_r = (lane & 7) + ((lane >> 3) & 1) * 8;
    const int t_c = (lane >> 4) * 8;

    // ---- S = Q K^T : 32 rows x 112 cols, k=32 ----
    float cc[2][14][4];
    #pragma unroll
    for (int mi = 0; mi < 2; mi++)
        #pragma unroll
        for (int ni = 0; ni < 14; ni++)
            #pragma unroll
            for (int e = 0; e < 4; e++) cc[mi][ni][e] = 0.f;

    #pragma unroll
    for (int ksx = 0; ksx < 2; ksx++) {
        const int kk = ksx * 16;
        uint32_t af[2][4];
        #pragma unroll
        for (int mi = 0; mi < 2; mi++)
            ldsm_x4(af[mi], qs + (warp * 32 + mi * 16 + a_r) * AQS + kk + a_k);
        #pragma unroll
        for (int np = 0; np < 7; np++) {
            uint32_t r4[4];
            ldsm_x4(r4, ks + (np * 16 + b_n) * AQS + kk + b_k);
            uint32_t b0[2] = { r4[0], r4[1] };
            uint32_t b1[2] = { r4[2], r4[3] };
            mma_bf16(cc[0][2 * np],     af[0], b0);
            mma_bf16(cc[1][2 * np],     af[1], b0);
            mma_bf16(cc[0][2 * np + 1], af[0], b1);
            mma_bf16(cc[1][2 * np + 1], af[1], b1);
        }
    }

    // ---- softmax: branch-free with padded bias (pad cols -> exp = 0) ----
    float rsum[2][2] = {{0.f, 0.f}, {0.f, 0.f}};
    const float* gb = g_bias + h * NTOK * BSTR;
    #pragma unroll
    for (int mi = 0; mi < 2; mi++) {
        int r0 = warp * 32 + mi * 16 + gid;
        int r1 = r0 + 8;
        const float* b0p = gb + (r0 < NTOK ? r0 : NTOK - 1) * BSTR;
        const float* b1p = gb + (r1 < NTOK ? r1 : NTOK - 1) * BSTR;
        #pragma unroll
        for (int ni = 0; ni < 14; ni++) {
            int col = ni * 8 + 2 * tig;
            float2 bb0 = *(const float2*)(b0p + col);
            float2 bb1 = *(const float2*)(b1p + col);
            float e;
            e = __expf(cc[mi][ni][0] + bb0.x); cc[mi][ni][0] = e; rsum[mi][0] += e;
            e = __expf(cc[mi][ni][1] + bb0.y); cc[mi][ni][1] = e; rsum[mi][0] += e;
            e = __expf(cc[mi][ni][2] + bb1.x); cc[mi][ni][2] = e; rsum[mi][1] += e;
            e = __expf(cc[mi][ni][3] + bb1.y); cc[mi][ni][3] = e; rsum[mi][1] += e;
        }
    }
    float inv[2][2];
    #pragma unroll
    for (int mi = 0; mi < 2; mi++)
        #pragma unroll
        for (int hf = 0; hf < 2; hf++) {
            float s = rsum[mi][hf];
            s += __shfl_xor_sync(0xffffffffu, s, 1);
            s += __shfl_xor_sync(0xffffffffu, s, 2);
            inv[mi][hf] = 1.0f / s;
        }

    // ---- O = P V : P stays in registers (C-fragment == A-fragment layout) ----
    float oo[2][4][4];
    #pragma unroll
    for (int mi = 0; mi < 2; mi++)
        #pragma unroll
        for (int ni = 0; ni < 4; ni++)
            #pragma unroll
            for (int e = 0; e < 4; e++) oo[mi][ni][e] = 0.f;

    #pragma unroll
    for (int k2 = 0; k2 < 7; k2++) {
        const int kk = k2 * 16;
        uint32_t af[2][4];
        #pragma unroll
        for (int mi = 0; mi < 2; mi++) {
            af[mi][0] = pack_bf2(cc[mi][2 * k2][0]     * inv[mi][0], cc[mi][2 * k2][1]     * inv[mi][0]);
            af[mi][1] = pack_bf2(cc[mi][2 * k2][2]     * inv[mi][1], cc[mi][2 * k2][3]     * inv[mi][1]);
            af[mi][2] = pack_bf2(cc[mi][2 * k2 + 1][0] * inv[mi][0], cc[mi][2 * k2 + 1][1] * inv[mi][0]);
            af[mi][3] = pack_bf2(cc[mi][2 * k2 + 1][2] * inv[mi][1], cc[mi][2 * k2 + 1][3] * inv[mi][1]);
        }
        #pragma unroll
        for (int np = 0; np < 2; np++) {
            int n0 = np * 16;
            uint32_t r4[4];
            ldsm_x4_t(r4, vsr + (kk + t_r) * AQS + n0 + t_c);
            uint32_t b0[2] = { r4[0], r4[1] };
            uint32_t b1[2] = { r4[2], r4[3] };
            mma_bf16(oo[0][2 * np],     af[0], b0);
            mma_bf16(oo[1][2 * np],     af[1], b0);
            mma_bf16(oo[0][2 * np + 1], af[0], b1);
            mma_bf16(oo[1][2 * np + 1], af[1], b1);
        }
    }

    #pragma unroll
    for (int mi = 0; mi < 2; mi++) {
        #pragma unroll
        for (int hf = 0; hf < 2; hf++) {
            int row = warp * 32 + mi * 16 + gid + hf * 8;
            if (row < NTOK) {
                bf16* op = g_attn + ((size_t)w * NTOK + row) * CDIM + h * HD;
                #pragma unroll
                for (int ni = 0; ni < 4; ni++) {
                    int col = ni * 8 + 2 * tig;
                    *(uint32_t*)(op + col) =
                        pack_bf2(oo[mi][ni][hf * 2], oo[mi][ni][hf * 2 + 1]);
                }
            }
        }
    }
}

// ---------------------------------------------------------------------------
// launcher
// ---------------------------------------------------------------------------
extern "C" void kernel_launch(void* const* d_in, const int* in_sizes, int n_in,
                              void* d_out, int out_size) {
    const float* x          = (const float*)d_in[0];
    const float* norm1_w    = (const float*)d_in[1];
    const float* norm1_b    = (const float*)d_in[2];
    const float* qkv_w      = (const float*)d_in[3];
    const float* qkv_b      = (const float*)d_in[4];
    const float* bias_table = (const float*)d_in[5];
    const float* proj_w     = (const float*)d_in[6];
    const float* proj_b     = (const float*)d_in[7];
    const float* norm2_w    = (const float*)d_in[8];
    const float* norm2_b    = (const float*)d_in[9];
    const float* fc1_w      = (const float*)d_in[10];
    const float* fc1_b      = (const float*)d_in[11];
    const float* fc2_w      = (const float*)d_in[12];
    const float* fc2_b      = (const float*)d_in[13];
    const int*   rel_index  = (const int*)d_in[14];
    float* out = (float*)d_out;

    bf16 *p_xw, *p_qkv, *p_attn, *p_h;
    bf16 *p_wq, *p_wp, *p_w1, *p_w2;
    float *p_x2;
    cudaGetSymbolAddress((void**)&p_xw,   g_xw);
    cudaGetSymbolAddress((void**)&p_qkv,  g_qkv);
    cudaGetSymbolAddress((void**)&p_attn, g_attn);
    cudaGetSymbolAddress((void**)&p_x2,   g_x2);
    cudaGetSymbolAddress((void**)&p_h,    g_h);
    cudaGetSymbolAddress((void**)&p_wq,   g_wq);
    cudaGetSymbolAddress((void**)&p_wp,   g_wp);
    cudaGetSymbolAddress((void**)&p_w1,   g_w1);
    cudaGetSymbolAddress((void**)&p_w2,   g_w2);

    const int GEMM_SMEM = 3 * G_STAGE * (int)sizeof(bf16);   // 61440
    const int ATTN_SMEM = ATTN_ELEMS * (int)sizeof(bf16);    // 28160
    cudaFuncSetAttribute((const void*)gemm_kernel<0,128>, cudaFuncAttributeMaxDynamicSharedMemorySize, GEMM_SMEM);
    cudaFuncSetAttribute((const void*)gemm_kernel<1,128>, cudaFuncAttributeMaxDynamicSharedMemorySize, GEMM_SMEM);
    cudaFuncSetAttribute((const void*)gemm_kernel<2,128>, cudaFuncAttributeMaxDynamicSharedMemorySize, GEMM_SMEM);
    cudaFuncSetAttribute((const void*)gemm_kernel<3,512>, cudaFuncAttributeMaxDynamicSharedMemorySize, GEMM_SMEM);
    cudaFuncSetAttribute((const void*)attn_kernel,        cudaFuncAttributeMaxDynamicSharedMemorySize, ATTN_SMEM);

    // 0) merged setup: weight conversion + padded bias gather
    setup_kernel<<<(CVT_UNITS + BIAS_UNITS + 255) / 256, 256>>>(
        qkv_w, proj_w, fc1_w, fc2_w, bias_table, rel_index);

    // 1) LN1 + window partition (fp32 -> bf16)
    ln_kernel<true><<<TOK / 8, 256>>>(x, norm1_w, norm1_b, p_xw);

    // 2) QKV gemm (+ q scale), bf16 out
    gemm_kernel<0,128><<<dim3(QKVN / 128, TOK / 128), 256, GEMM_SMEM>>>(
        p_xw, p_wq, qkv_b, nullptr, nullptr, nullptr, p_qkv, QKVN);

    // 3) window attention (bf16 tensor cores, register-P, cp.async loads)
    attn_kernel<<<dim3(NWIN, NH), 128, ATTN_SMEM>>>();

    // 4) proj gemm + window reverse + residual(x) -> g_x2 (fp32) + fused LN2 -> g_xw (bf16)
    gemm_kernel<1,128><<<dim3(CDIM / 128, TOK / 128), 256, GEMM_SMEM>>>(
        p_attn, p_wp, proj_b, x, norm2_w, norm2_b, p_x2, CDIM);

    // 5) fc1 + exact GELU, bf16 out
    gemm_kernel<2,128><<<dim3(CH / 128, TOK / 128), 256, GEMM_SMEM>>>(
        p_xw, p_w1, fc1_b, nullptr, nullptr, nullptr, p_h, CH);

    // 6) fc2 + residual(g_x2) -> d_out (fp32)
    gemm_kernel<3,512><<<dim3(CDIM / 128, TOK / 128), 256, GEMM_SMEM>>>(
        p_h, p_w2, fc2_b, p_x2, nullptr, nullptr, out, CDIM);

    (void)in_sizes; (void)n_in; (void)out_size;
}

// round 15
// speedup vs baseline: 1.1525x; 1.0212x over previous
#include <cuda_runtime.h>
#include <cuda_bf16.h>
#include <math.h>
#include <stdint.h>

// ---------------------------------------------------------------------------
// Problem constants
// ---------------------------------------------------------------------------
#define TOK   50176      // 2*8*56*56
#define CDIM  128
#define CH    512
#define NWIN  512        // 2 * 4*8*8
#define NTOK  98         // 2*7*7
#define NH    4
#define HD    32
#define QKVN  384
#define BSTR  112        // padded bias row stride

typedef __nv_bfloat16  bf16;
typedef __nv_bfloat162 bf162;

// ---------------------------------------------------------------------------
// Scratch (device globals: allocation-free, graph-capture safe)
// ---------------------------------------------------------------------------
__device__ bf16  g_xw  [(size_t)TOK * CDIM];   // LN1 out (window order) / LN2 out (spatial)
__device__ bf16  g_qkv [(size_t)TOK * QKVN];   // qkv, window order
__device__ bf16  g_attn[(size_t)TOK * CDIM];   // attention out, window order
__device__ float g_x2  [(size_t)TOK * CDIM];   // x + proj (spatial, fp32)
__device__ bf16  g_h   [(size_t)TOK * CH];     // fc1 output
__device__ float g_bias[NH * NTOK * BSTR];     // gathered attention bias, padded cols
// bf16 weights
__device__ bf16  g_wq[QKVN * CDIM];
__device__ bf16  g_wp[CDIM * CDIM];
__device__ bf16  g_w1[CH * CDIM];
__device__ bf16  g_w2[CDIM * CH];

// ---------------------------------------------------------------------------
// index helpers
// ---------------------------------------------------------------------------
__device__ __forceinline__ long win_to_spatial(long row) {
    int w = (int)(row / NTOK);
    int n = (int)(row % NTOK);
    int b   = w >> 8;
    int rem = w & 255;
    int wdi = rem >> 6, whi = (rem >> 3) & 7, wwi = rem & 7;
    int zd = n / 49; int r2 = n % 49; int zh = r2 / 7, zw = r2 % 7;
    int d  = wdi * 2 + zd;
    int hh = whi * 7 + zh;
    int xx = wwi * 7 + zw;
    return (((long)(b * 8 + d) * 56) + hh) * 56 + xx;
}

__device__ __forceinline__ long spatial_to_win(long t) {
    int b  = (int)(t / 25088);
    int r  = (int)(t % 25088);
    int d  = r / 3136; r %= 3136;
    int hh = r / 56;
    int xx = r % 56;
    int widx = ((b * 4 + (d >> 1)) * 8 + hh / 7) * 8 + xx / 7;
    int n    = ((d & 1) * 7 + hh % 7) * 7 + xx % 7;
    return (long)widx * NTOK + n;
}

// ---------------------------------------------------------------------------
// async copy + ldmatrix + mma helpers
// ---------------------------------------------------------------------------
__device__ __forceinline__ void cp_async16(bf16* smem_dst, const bf16* gmem_src) {
    uint32_t s = (uint32_t)__cvta_generic_to_shared(smem_dst);
    asm volatile("cp.async.cg.shared.global [%0], [%1], 16;\n" :: "r"(s), "l"(gmem_src));
}
__device__ __forceinline__ void cp_commit() { asm volatile("cp.async.commit_group;\n"); }
template<int N>
__device__ __forceinline__ void cp_wait() { asm volatile("cp.async.wait_group %0;\n" :: "n"(N)); }

__device__ __forceinline__ void ldsm_x4(uint32_t r[4], const bf16* p) {
    uint32_t a = (uint32_t)__cvta_generic_to_shared(p);
    asm volatile("ldmatrix.sync.aligned.m8n8.x4.shared.b16 {%0,%1,%2,%3}, [%4];\n"
                 : "=r"(r[0]), "=r"(r[1]), "=r"(r[2]), "=r"(r[3]) : "r"(a));
}
__device__ __forceinline__ void ldsm_x4_t(uint32_t r[4], const bf16* p) {
    uint32_t a = (uint32_t)__cvta_generic_to_shared(p);
    asm volatile("ldmatrix.sync.aligned.m8n8.x4.trans.shared.b16 {%0,%1,%2,%3}, [%4];\n"
                 : "=r"(r[0]), "=r"(r[1]), "=r"(r[2]), "=r"(r[3]) : "r"(a));
}
__device__ __forceinline__ void mma_bf16(float c[4], const uint32_t a[4], const uint32_t b[2]) {
    asm volatile(
        "mma.sync.aligned.m16n8k16.row.col.f32.bf16.bf16.f32 "
        "{%0,%1,%2,%3}, {%4,%5,%6,%7}, {%8,%9}, {%0,%1,%2,%3};\n"
        : "+f"(c[0]), "+f"(c[1]), "+f"(c[2]), "+f"(c[3])
        : "r"(a[0]), "r"(a[1]), "r"(a[2]), "r"(a[3]), "r"(b[0]), "r"(b[1]));
}

__device__ __forceinline__ uint32_t pack_bf2(float a, float b) {
    bf162 p = __float22bfloat162_rn(make_float2(a, b));
    return *(uint32_t*)&p;
}

// ---------------------------------------------------------------------------
// merged setup: weight conversion fp32->bf16 (float4 units 0..49151)
//               + padded bias gather (units 49152..)
// bias layout: [NH][98][112], cols 98..111 = -1e4 (exp -> exactly 0)
// ---------------------------------------------------------------------------
#define CVT_UNITS  49152
#define BIAS_UNITS (NH * NTOK * BSTR)   // 43904
__global__ void setup_kernel(const float* __restrict__ wq,
                             const float* __restrict__ wp,
                             const float* __restrict__ w1,
                             const float* __restrict__ w2,
                             const float* __restrict__ bias_table,
                             const int* __restrict__ rel_index) {
    int i = blockIdx.x * blockDim.x + threadIdx.x;
    if (i < CVT_UNITS) {
        const float* src; bf16* dst; int off;
        if (i < 12288)      { src = wq; dst = g_wq; off = i; }
        else if (i < 16384) { src = wp; dst = g_wp; off = i - 12288; }
        else if (i < 32768) { src = w1; dst = g_w1; off = i - 16384; }
        else                { src = w2; dst = g_w2; off = i - 32768; }
        float4 v = *(const float4*)(src + off * 4);
        uint2 u = make_uint2(pack_bf2(v.x, v.y), pack_bf2(v.z, v.w));
        *(uint2*)(dst + off * 4) = u;
    } else {
        int j = i - CVT_UNITS;
        if (j < BIAS_UNITS) {
            int h = j / (NTOK * BSTR);
            int r = j % (NTOK * BSTR);
            int n = r / BSTR;
            int m = r % BSTR;
            g_bias[j] = (m < NTOK) ? bias_table[rel_index[n * NTOK + m] * NH + h]
                                   : -10000.0f;
        }
    }
}

// ---------------------------------------------------------------------------
// LayerNorm over C=128 (fp32 in, bf16 out): one warp per token.
// PERMUTE=true: write window-partitioned order (for LN1).
// ---------------------------------------------------------------------------
template<bool PERMUTE>
__global__ __launch_bounds__(256)
void ln_kernel(const float* __restrict__ in,
               const float* __restrict__ gam,
               const float* __restrict__ bet,
               bf16* __restrict__ out) {
    int warp = threadIdx.x >> 5;
    int lane = threadIdx.x & 31;
    long t = (long)blockIdx.x * 8 + warp;
    const float4 v = *(const float4*)(in + t * CDIM + lane * 4);
    float s  = v.x + v.y + v.z + v.w;
    float sq = v.x * v.x + v.y * v.y + v.z * v.z + v.w * v.w;
    #pragma unroll
    for (int o = 16; o; o >>= 1) {
        s  += __shfl_xor_sync(0xffffffffu, s,  o);
        sq += __shfl_xor_sync(0xffffffffu, sq, o);
    }
    float mean = s * (1.0f / CDIM);
    float var  = sq * (1.0f / CDIM) - mean * mean;
    float rstd = rsqrtf(var + 1e-5f);
    const float4 g = *(const float4*)(gam + lane * 4);
    const float4 b = *(const float4*)(bet + lane * 4);
    uint2 u = make_uint2(pack_bf2((v.x - mean) * rstd * g.x + b.x,
                                  (v.y - mean) * rstd * g.y + b.y),
                         pack_bf2((v.z - mean) * rstd * g.z + b.z,
                                  (v.w - mean) * rstd * g.w + b.w));
    long orow = PERMUTE ? spatial_to_win(t) : t;
    *(uint2*)(out + orow * CDIM + lane * 4) = u;
}

// ---------------------------------------------------------------------------
// BF16 GEMM (R5 exact): 128x128 block, BK=32, 3-stage cp.async, warp 64x32.
// MODE 0: qkv  -> +bias; scale q-part (colBase==0); bf16 out [M,384]
// MODE 1: proj -> +bias; permute; += resid(x); fp32 g_x2  AND fused LN2 -> bf16 g_xw
// MODE 2: fc1  -> +bias; exact GELU; bf16 out [M,512]
// MODE 3: fc2  -> +bias; += resid(g_x2); fp32 out d_out
// ---------------------------------------------------------------------------
#define GS 40                  // smem row stride (halves): 32 + 8 pad
#define G_STAGE (256 * GS)     // As(128)+Ws(128) rows per stage
template<int MODE, int KT>
__global__ __launch_bounds__(256, 2)
void gemm_kernel(const bf16* __restrict__ A,
                 const bf16* __restrict__ Wt,
                 const float* __restrict__ bias,
                 const float* __restrict__ resid,
                 const float* __restrict__ gam,
                 const float* __restrict__ bet,
                 void* __restrict__ Cv,
                 int N) {
    extern __shared__ bf16 sm[];
    bf16* Asb[3] = { sm, sm + G_STAGE, sm + 2 * G_STAGE };
    bf16* Wsb[3] = { sm + 128 * GS, sm + G_STAGE + 128 * GS, sm + 2 * G_STAGE + 128 * GS };

    const int tid  = threadIdx.x;
    const int lane = tid & 31;
    const int warp = tid >> 5;
    const int warpM = warp >> 2;        // 0..1
    const int warpN = warp & 3;         // 0..3
    const int gid = lane >> 2;          // 0..7
    const int tig = lane & 3;           // 0..3

    const long rowBase = (long)blockIdx.y * 128;
    const int  colBase = blockIdx.x * 128;
    const int  K = KT;

    float cc[4][4][4];
    #pragma unroll
    for (int mi = 0; mi < 4; mi++)
        #pragma unroll
        for (int ni = 0; ni < 4; ni++)
            #pragma unroll
            for (int e = 0; e < 4; e++) cc[mi][ni][e] = 0.f;

    const int ld_row = tid >> 2;        // 0..63
    const int ld_kq  = (tid & 3) * 8;   // halves

    auto load_tile = [&](int buf, int k0) {
        #pragma unroll
        for (int r = 0; r < 2; r++) {
            int m = ld_row + r * 64;
            cp_async16(&Asb[buf][m * GS + ld_kq], A + (rowBase + m) * K + k0 + ld_kq);
        }
        #pragma unroll
        for (int r = 0; r < 2; r++) {
            int n = ld_row + r * 64;
            cp_async16(&Wsb[buf][n * GS + ld_kq], Wt + (long)(colBase + n) * K + k0 + ld_kq);
        }
    };

    constexpr int nk = KT / 32;
    load_tile(0, 0);  cp_commit();
    load_tile(1, 32); cp_commit();

    const int a_r = (lane & 7) + ((lane >> 3) & 1) * 8;
    const int a_k = (lane >> 4) * 8;
    const int b_n = (lane & 7) + (lane >> 4) * 8;
    const int b_k = ((lane >> 3) & 1) * 8;

    #pragma unroll
    for (int it = 0; it < nk; it++) {
        if (it < nk - 1) cp_wait<1>(); else cp_wait<0>();
        __syncthreads();
        if (it + 2 < nk) { load_tile((it + 2) % 3, (it + 2) * 32); cp_commit(); }

        const bf16* As = Asb[it % 3];
        const bf16* Ws = Wsb[it % 3];
        #pragma unroll
        for (int ks = 0; ks < 2; ks++) {
            const int kk = ks * 16;
            uint32_t af[4][4];
            uint32_t bf[4][2];
            #pragma unroll
            for (int mi = 0; mi < 4; mi++)
                ldsm_x4(af[mi], As + (warpM * 64 + mi * 16 + a_r) * GS + kk + a_k);
            #pragma unroll
            for (int np = 0; np < 2; np++) {
                uint32_t r4[4];
                ldsm_x4(r4, Ws + (warpN * 32 + np * 16 + b_n) * GS + kk + b_k);
                bf[2 * np][0] = r4[0]; bf[2 * np][1] = r4[1];
                bf[2 * np + 1][0] = r4[2]; bf[2 * np + 1][1] = r4[3];
            }
            #pragma unroll
            for (int mi = 0; mi < 4; mi++)
                #pragma unroll
                for (int ni = 0; ni < 4; ni++)
                    mma_bf16(cc[mi][ni], af[mi], bf[ni]);
        }
    }

    if (MODE == 1) {
        __syncthreads();                 // all warps done with smem stages
        float* red = (float*)sm;         // [128][2] row sums
        if (tid < 128) { red[2 * tid] = 0.f; red[2 * tid + 1] = 0.f; }
        __syncthreads();

        long orows[4][2];
        float* C = (float*)Cv;
        #pragma unroll
        for (int mi = 0; mi < 4; mi++) {
            #pragma unroll
            for (int half = 0; half < 2; half++) {
                int rloc = warpM * 64 + mi * 16 + gid + half * 8;
                long orow = win_to_spatial(rowBase + rloc);
                orows[mi][half] = orow;
                float s = 0.f, sq = 0.f;
                #pragma unroll
                for (int ni = 0; ni < 4; ni++) {
                    int col = warpN * 32 + ni * 8 + 2 * tig;
                    const float2 r = *(const float2*)(resid + orow * CDIM + col);
                    float v0 = cc[mi][ni][half * 2 + 0] + bias[col]     + r.x;
                    float v1 = cc[mi][ni][half * 2 + 1] + bias[col + 1] + r.y;
                    cc[mi][ni][half * 2 + 0] = v0;
                    cc[mi][ni][half * 2 + 1] = v1;
                    *(float2*)(C + orow * CDIM + col) = make_float2(v0, v1);
                    s += v0 + v1; sq += v0 * v0 + v1 * v1;
                }
                s  += __shfl_xor_sync(0xffffffffu, s, 1);
                sq += __shfl_xor_sync(0xffffffffu, sq, 1);
                s  += __shfl_xor_sync(0xffffffffu, s, 2);
                sq += __shfl_xor_sync(0xffffffffu, sq, 2);
                if (tig == 0) {
                    atomicAdd(&red[2 * rloc],     s);
                    atomicAdd(&red[2 * rloc + 1], sq);
                }
            }
        }
        __syncthreads();
        #pragma unroll
        for (int mi = 0; mi < 4; mi++) {
            #pragma unroll
            for (int half = 0; half < 2; half++) {
                int rloc = warpM * 64 + mi * 16 + gid + half * 8;
                long orow = orows[mi][half];
                float mean = red[2 * rloc] * (1.0f / CDIM);
                float var  = red[2 * rloc + 1] * (1.0f / CDIM) - mean * mean;
                float rstd = rsqrtf(var + 1e-5f);
                #pragma unroll
                for (int ni = 0; ni < 4; ni++) {
                    int col = warpN * 32 + ni * 8 + 2 * tig;
                    float v0 = cc[mi][ni][half * 2 + 0];
                    float v1 = cc[mi][ni][half * 2 + 1];
                    float y0 = (v0 - mean) * rstd * gam[col]     + bet[col];
                    float y1 = (v1 - mean) * rstd * gam[col + 1] + bet[col + 1];
                    *(uint32_t*)(g_xw + orow * CDIM + col) = pack_bf2(y0, y1);
                }
            }
        }
        return;
    }

    #pragma unroll
    for (int mi = 0; mi < 4; mi++) {
        #pragma unroll
        for (int half = 0; half < 2; half++) {
            long row = rowBase + warpM * 64 + mi * 16 + gid + half * 8;
            #pragma unroll
            for (int ni = 0; ni < 4; ni++) {
                int col = colBase + warpN * 32 + ni * 8 + 2 * tig;
                float v0 = cc[mi][ni][half * 2 + 0] + bias[col];
                float v1 = cc[mi][ni][half * 2 + 1] + bias[col + 1];
                if (MODE == 0) {
                    if (colBase == 0) { v0 *= 0.17677669529663687f; v1 *= 0.17677669529663687f; }
                }
                if (MODE == 2) {
                    v0 = 0.5f * v0 * (1.0f + erff(v0 * 0.70710678118654752f));
                    v1 = 0.5f * v1 * (1.0f + erff(v1 * 0.70710678118654752f));
                }
                if (MODE == 3) {
                    float* C = (float*)Cv;
                    const float2 r = *(const float2*)(resid + row * CDIM + col);
                    *(float2*)(C + row * CDIM + col) = make_float2(v0 + r.x, v1 + r.y);
                } else {
                    bf16* C = (bf16*)Cv;
                    *(uint32_t*)(C + row * (long)N + col) = pack_bf2(v0, v1);
                }
            }
        }
    }
}

// ---------------------------------------------------------------------------
// BF16 tensor-core window attention v3: 7 warps (224 thr), ONE 16-row tile
// per warp (rows 0..111; the all-pad tile 112..127 is eliminated).
// Register-P (FA2), padded bias, cp.async loads. smem 28160 B.
// Per-warp work halves vs v2 -> ~90 regs -> 3 CTAs/SM (21 warps).
// ---------------------------------------------------------------------------
#define AQS 40
#define NPAD 112
#define ATTN_ELEMS ((128 + 2 * NPAD) * AQS)   // 14080 bf16 = 28160 B
#define ATHREADS 224
__global__ __launch_bounds__(ATHREADS, 3)
void attn_kernel() {
    extern __shared__ bf16 asm_[];
    bf16* qs  = asm_;                          // [128][40] (rows 112..127 unused)
    bf16* ks  = asm_ + 128 * AQS;              // [112][40]
    bf16* vsr = asm_ + (128 + NPAD) * AQS;     // [112][40]

    const int w = blockIdx.x;
    const int h = blockIdx.y;
    const int tid  = threadIdx.x;
    const int warp = tid >> 5;                 // 0..6, owns rows [16w, 16w+16)
    const int lane = tid & 31;
    const int gid = lane >> 2;
    const int tig = lane & 3;

    const bf16* base = g_qkv + (size_t)w * NTOK * QKVN + h * HD;

    // q/k/v tile loads via cp.async
    for (int i = tid; i < NTOK * 4; i += ATHREADS) {
        int m = i >> 2, c = (i & 3) * 8;
        cp_async16(&qs [m * AQS + c], base + m * QKVN + c);
        cp_async16(&ks [m * AQS + c], base + m * QKVN + CDIM + c);
        cp_async16(&vsr[m * AQS + c], base + m * QKVN + 2 * CDIM + c);
    }
    // zero K/V pad rows 98..111 (Q pads 98..111 left garbage: rows discarded)
    const uint4 z4 = make_uint4(0, 0, 0, 0);
    if (tid < 14 * 4) {
        int m = 98 + (tid >> 2), c = (tid & 3) * 8;
        *(uint4*)&ks [m * AQS + c] = z4;
        *(uint4*)&vsr[m * AQS + c] = z4;
    }
    cp_commit();
    cp_wait<0>();
    __syncthreads();

    const int a_r = (lane & 7) + ((lane >> 3) & 1) * 8;
    const int a_k = (lane >> 4) * 8;
    const int b_n = (lane & 7) + (lane >> 4) * 8;
    const int b_k = ((lane >> 3) & 1) * 8;
    const int t_r = (lane & 7) + ((lane >> 3) & 1) * 8;
    const int t_c = (lane >> 4) * 8;

    // ---- S = Q K^T : 16 rows x 112 cols, k=32 ----
    float cc[14][4];
    #pragma unroll
    for (int ni = 0; ni < 14; ni++)
        #pragma unroll
        for (int e = 0; e < 4; e++) cc[ni][e] = 0.f;

    #pragma unroll
    for (int ksx = 0; ksx < 2; ksx++) {
        const int kk = ksx * 16;
        uint32_t af[4];
        ldsm_x4(af, qs + (warp * 16 + a_r) * AQS + kk + a_k);
        #pragma unroll
        for (int np = 0; np < 7; np++) {
            uint32_t r4[4];
            ldsm_x4(r4, ks + (np * 16 + b_n) * AQS + kk + b_k);
            uint32_t b0[2] = { r4[0], r4[1] };
            uint32_t b1[2] = { r4[2], r4[3] };
            mma_bf16(cc[2 * np],     af, b0);
            mma_bf16(cc[2 * np + 1], af, b1);
        }
    }

    // ---- softmax: branch-free with padded bias (pad cols -> exp = 0) ----
    float rsum[2] = { 0.f, 0.f };
    const float* gb = g_bias + h * NTOK * BSTR;
    {
        int r0 = warp * 16 + gid;
        int r1 = r0 + 8;
        const float* b0p = gb + (r0 < NTOK ? r0 : NTOK - 1) * BSTR;
        const float* b1p = gb + (r1 < NTOK ? r1 : NTOK - 1) * BSTR;
        #pragma unroll
        for (int ni = 0; ni < 14; ni++) {
            int col = ni * 8 + 2 * tig;
            float2 bb0 = *(const float2*)(b0p + col);
            float2 bb1 = *(const float2*)(b1p + col);
            float e;
            e = __expf(cc[ni][0] + bb0.x); cc[ni][0] = e; rsum[0] += e;
            e = __expf(cc[ni][1] + bb0.y); cc[ni][1] = e; rsum[0] += e;
            e = __expf(cc[ni][2] + bb1.x); cc[ni][2] = e; rsum[1] += e;
            e = __expf(cc[ni][3] + bb1.y); cc[ni][3] = e; rsum[1] += e;
        }
    }
    float inv[2];
    #pragma unroll
    for (int hf = 0; hf < 2; hf++) {
        float s = rsum[hf];
        s += __shfl_xor_sync(0xffffffffu, s, 1);
        s += __shfl_xor_sync(0xffffffffu, s, 2);
        inv[hf] = 1.0f / s;
    }

    // ---- O = P V : 16 rows x 32 cols, k=112; P in registers ----
    float oo[4][4];
    #pragma unroll
    for (int ni = 0; ni < 4; ni++)
        #pragma unroll
        for (int e = 0; e < 4; e++) oo[ni][e] = 0.f;

    #pragma unroll
    for (int k2 = 0; k2 < 7; k2++) {
        const int kk = k2 * 16;
        uint32_t af[4];
        af[0] = pack_bf2(cc[2 * k2][0]     * inv[0], cc[2 * k2][1]     * inv[0]);
        af[1] = pack_bf2(cc[2 * k2][2]     * inv[1], cc[2 * k2][3]     * inv[1]);
        af[2] = pack_bf2(cc[2 * k2 + 1][0] * inv[0], cc[2 * k2 + 1][1] * inv[0]);
        af[3] = pack_bf2(cc[2 * k2 + 1][2] * inv[1], cc[2 * k2 + 1][3] * inv[1]);
        #pragma unroll
        for (int np = 0; np < 2; np++) {
            int n0 = np * 16;
            uint32_t r4[4];
            ldsm_x4_t(r4, vsr + (kk + t_r) * AQS + n0 + t_c);
            uint32_t b0[2] = { r4[0], r4[1] };
            uint32_t b1[2] = { r4[2], r4[3] };
            mma_bf16(oo[2 * np],     af, b0);
            mma_bf16(oo[2 * np + 1], af, b1);
        }
    }

    #pragma unroll
    for (int hf = 0; hf < 2; hf++) {
        int row = warp * 16 + gid + hf * 8;
        if (row < NTOK) {
            bf16* op = g_attn + ((size_t)w * NTOK + row) * CDIM + h * HD;
            #pragma unroll
            for (int ni = 0; ni < 4; ni++) {
                int col = ni * 8 + 2 * tig;
                *(uint32_t*)(op + col) = pack_bf2(oo[ni][hf * 2], oo[ni][hf * 2 + 1]);
            }
        }
    }
}

// ---------------------------------------------------------------------------
// launcher
// ---------------------------------------------------------------------------
extern "C" void kernel_launch(void* const* d_in, const int* in_sizes, int n_in,
                              void* d_out, int out_size) {
    const float* x          = (const float*)d_in[0];
    const float* norm1_w    = (const float*)d_in[1];
    const float* norm1_b    = (const float*)d_in[2];
    const float* qkv_w      = (const float*)d_in[3];
    const float* qkv_b      = (const float*)d_in[4];
    const float* bias_table = (const float*)d_in[5];
    const float* proj_w     = (const float*)d_in[6];
    const float* proj_b     = (const float*)d_in[7];
    const float* norm2_w    = (const float*)d_in[8];
    const float* norm2_b    = (const float*)d_in[9];
    const float* fc1_w      = (const float*)d_in[10];
    const float* fc1_b      = (const float*)d_in[11];
    const float* fc2_w      = (const float*)d_in[12];
    const float* fc2_b      = (const float*)d_in[13];
    const int*   rel_index  = (const int*)d_in[14];
    float* out = (float*)d_out;

    bf16 *p_xw, *p_qkv, *p_attn, *p_h;
    bf16 *p_wq, *p_wp, *p_w1, *p_w2;
    float *p_x2;
    cudaGetSymbolAddress((void**)&p_xw,   g_xw);
    cudaGetSymbolAddress((void**)&p_qkv,  g_qkv);
    cudaGetSymbolAddress((void**)&p_attn, g_attn);
    cudaGetSymbolAddress((void**)&p_x2,   g_x2);
    cudaGetSymbolAddress((void**)&p_h,    g_h);
    cudaGetSymbolAddress((void**)&p_wq,   g_wq);
    cudaGetSymbolAddress((void**)&p_wp,   g_wp);
    cudaGetSymbolAddress((void**)&p_w1,   g_w1);
    cudaGetSymbolAddress((void**)&p_w2,   g_w2);

    const int GEMM_SMEM = 3 * G_STAGE * (int)sizeof(bf16);   // 61440
    const int ATTN_SMEM = ATTN_ELEMS * (int)sizeof(bf16);    // 28160
    cudaFuncSetAttribute((const void*)gemm_kernel<0,128>, cudaFuncAttributeMaxDynamicSharedMemorySize, GEMM_SMEM);
    cudaFuncSetAttribute((const void*)gemm_kernel<1,128>, cudaFuncAttributeMaxDynamicSharedMemorySize, GEMM_SMEM);
    cudaFuncSetAttribute((const void*)gemm_kernel<2,128>, cudaFuncAttributeMaxDynamicSharedMemorySize, GEMM_SMEM);
    cudaFuncSetAttribute((const void*)gemm_kernel<3,512>, cudaFuncAttributeMaxDynamicSharedMemorySize, GEMM_SMEM);
    cudaFuncSetAttribute((const void*)attn_kernel,        cudaFuncAttributeMaxDynamicSharedMemorySize, ATTN_SMEM);

    // 0) merged setup: weight conversion + padded bias gather
    setup_kernel<<<(CVT_UNITS + BIAS_UNITS + 255) / 256, 256>>>(
        qkv_w, proj_w, fc1_w, fc2_w, bias_table, rel_index);

    // 1) LN1 + window partition (fp32 -> bf16)
    ln_kernel<true><<<TOK / 8, 256>>>(x, norm1_w, norm1_b, p_xw);

    // 2) QKV gemm (+ q scale), bf16 out
    gemm_kernel<0,128><<<dim3(QKVN / 128, TOK / 128), 256, GEMM_SMEM>>>(
        p_xw, p_wq, qkv_b, nullptr, nullptr, nullptr, p_qkv, QKVN);

    // 3) window attention (7-warp, register-P, cp.async)
    attn_kernel<<<dim3(NWIN, NH), ATHREADS, ATTN_SMEM>>>();

    // 4) proj gemm + window reverse + residual(x) -> g_x2 (fp32) + fused LN2 -> g_xw (bf16)
    gemm_kernel<1,128><<<dim3(CDIM / 128, TOK / 128), 256, GEMM_SMEM>>>(
        p_attn, p_wp, proj_b, x, norm2_w, norm2_b, p_x2, CDIM);

    // 5) fc1 + exact GELU, bf16 out
    gemm_kernel<2,128><<<dim3(CH / 128, TOK / 128), 256, GEMM_SMEM>>>(
        p_xw, p_w1, fc1_b, nullptr, nullptr, nullptr, p_h, CH);

    // 6) fc2 + residual(g_x2) -> d_out (fp32)
    gemm_kernel<3,512><<<dim3(CDIM / 128, TOK / 128), 256, GEMM_SMEM>>>(
        p_h, p_w2, fc2_b, p_x2, nullptr, nullptr, out, CDIM);

    (void)in_sizes; (void)n_in; (void)out_size;
}

// round 16
// speedup vs baseline: 1.1947x; 1.0366x over previous
#include <cuda_runtime.h>
#include <cuda_bf16.h>
#include <math.h>
#include <stdint.h>

// ---------------------------------------------------------------------------
// Problem constants
// ---------------------------------------------------------------------------
#define TOK   50176      // 2*8*56*56
#define CDIM  128
#define CH    512
#define NWIN  512        // 2 * 4*8*8
#define NTOK  98         // 2*7*7
#define NH    4
#define HD    32
#define QKVN  384
#define BSTR  112        // padded bias row stride

typedef __nv_bfloat16  bf16;
typedef __nv_bfloat162 bf162;

// ---------------------------------------------------------------------------
// Scratch (device globals: allocation-free, graph-capture safe)
// ---------------------------------------------------------------------------
__device__ bf16  g_xw  [(size_t)TOK * CDIM];   // LN1 out (window order) / LN2 out (spatial)
__device__ bf16  g_qkv [(size_t)TOK * QKVN];   // qkv, window order
__device__ bf16  g_attn[(size_t)TOK * CDIM];   // attention out, window order
__device__ float g_x2  [(size_t)TOK * CDIM];   // x + proj (spatial, fp32)
__device__ bf16  g_h   [(size_t)TOK * CH];     // fc1 output
__device__ bf16  g_bias[NH * NTOK * BSTR];     // gathered attention bias (bf16), padded
// bf16 weights
__device__ bf16  g_wq[QKVN * CDIM];
__device__ bf16  g_wp[CDIM * CDIM];
__device__ bf16  g_w1[CH * CDIM];
__device__ bf16  g_w2[CDIM * CH];

// ---------------------------------------------------------------------------
// index helpers
// ---------------------------------------------------------------------------
__device__ __forceinline__ long win_to_spatial(long row) {
    int w = (int)(row / NTOK);
    int n = (int)(row % NTOK);
    int b   = w >> 8;
    int rem = w & 255;
    int wdi = rem >> 6, whi = (rem >> 3) & 7, wwi = rem & 7;
    int zd = n / 49; int r2 = n % 49; int zh = r2 / 7, zw = r2 % 7;
    int d  = wdi * 2 + zd;
    int hh = whi * 7 + zh;
    int xx = wwi * 7 + zw;
    return (((long)(b * 8 + d) * 56) + hh) * 56 + xx;
}

__device__ __forceinline__ long spatial_to_win(long t) {
    int b  = (int)(t / 25088);
    int r  = (int)(t % 25088);
    int d  = r / 3136; r %= 3136;
    int hh = r / 56;
    int xx = r % 56;
    int widx = ((b * 4 + (d >> 1)) * 8 + hh / 7) * 8 + xx / 7;
    int n    = ((d & 1) * 7 + hh % 7) * 7 + xx % 7;
    return (long)widx * NTOK + n;
}

// ---------------------------------------------------------------------------
// async copy + ldmatrix + mma helpers
// ---------------------------------------------------------------------------
__device__ __forceinline__ void cp_async16(bf16* smem_dst, const bf16* gmem_src) {
    uint32_t s = (uint32_t)__cvta_generic_to_shared(smem_dst);
    asm volatile("cp.async.cg.shared.global [%0], [%1], 16;\n" :: "r"(s), "l"(gmem_src));
}
__device__ __forceinline__ void cp_commit() { asm volatile("cp.async.commit_group;\n"); }
template<int N>
__device__ __forceinline__ void cp_wait() { asm volatile("cp.async.wait_group %0;\n" :: "n"(N)); }

__device__ __forceinline__ void ldsm_x4(uint32_t r[4], const bf16* p) {
    uint32_t a = (uint32_t)__cvta_generic_to_shared(p);
    asm volatile("ldmatrix.sync.aligned.m8n8.x4.shared.b16 {%0,%1,%2,%3}, [%4];\n"
                 : "=r"(r[0]), "=r"(r[1]), "=r"(r[2]), "=r"(r[3]) : "r"(a));
}
__device__ __forceinline__ void ldsm_x4_t(uint32_t r[4], const bf16* p) {
    uint32_t a = (uint32_t)__cvta_generic_to_shared(p);
    asm volatile("ldmatrix.sync.aligned.m8n8.x4.trans.shared.b16 {%0,%1,%2,%3}, [%4];\n"
                 : "=r"(r[0]), "=r"(r[1]), "=r"(r[2]), "=r"(r[3]) : "r"(a));
}
__device__ __forceinline__ void mma_bf16(float c[4], const uint32_t a[4], const uint32_t b[2]) {
    asm volatile(
        "mma.sync.aligned.m16n8k16.row.col.f32.bf16.bf16.f32 "
        "{%0,%1,%2,%3}, {%4,%5,%6,%7}, {%8,%9}, {%0,%1,%2,%3};\n"
        : "+f"(c[0]), "+f"(c[1]), "+f"(c[2]), "+f"(c[3])
        : "r"(a[0]), "r"(a[1]), "r"(a[2]), "r"(a[3]), "r"(b[0]), "r"(b[1]));
}

__device__ __forceinline__ uint32_t pack_bf2(float a, float b) {
    bf162 p = __float22bfloat162_rn(make_float2(a, b));
    return *(uint32_t*)&p;
}

// ---------------------------------------------------------------------------
// merged setup+LN1 kernel, 256 threads/block:
//   blocks [0, LN_BLOCKS)          : LN1 + window partition (8 tokens/block)
//   blocks [LN_BLOCKS, ..)         : weight cvt (float4 units) + bias gather
// bias layout: [NH][98][112] bf16, cols 98..111 = -1e4 (exp -> exactly 0)
// ---------------------------------------------------------------------------
#define LN_BLOCKS  (TOK / 8)            // 6272
#define CVT_UNITS  49152
#define BIAS_UNITS (NH * NTOK * BSTR)   // 43904
#define SETUP_BLOCKS ((CVT_UNITS + BIAS_UNITS + 255) / 256)
__global__ __launch_bounds__(256)
void setup_ln1_kernel(const float* __restrict__ x,
                      const float* __restrict__ gam,
                      const float* __restrict__ bet,
                      const float* __restrict__ wq,
                      const float* __restrict__ wp,
                      const float* __restrict__ w1,
                      const float* __restrict__ w2,
                      const float* __restrict__ bias_table,
                      const int* __restrict__ rel_index) {
    if (blockIdx.x < LN_BLOCKS) {
        // ---- LN1 + window partition: one warp per token ----
        int warp = threadIdx.x >> 5;
        int lane = threadIdx.x & 31;
        long t = (long)blockIdx.x * 8 + warp;
        const float4 v = *(const float4*)(x + t * CDIM + lane * 4);
        float s  = v.x + v.y + v.z + v.w;
        float sq = v.x * v.x + v.y * v.y + v.z * v.z + v.w * v.w;
        #pragma unroll
        for (int o = 16; o; o >>= 1) {
            s  += __shfl_xor_sync(0xffffffffu, s,  o);
            sq += __shfl_xor_sync(0xffffffffu, sq, o);
        }
        float mean = s * (1.0f / CDIM);
        float var  = sq * (1.0f / CDIM) - mean * mean;
        float rstd = rsqrtf(var + 1e-5f);
        const float4 g = *(const float4*)(gam + lane * 4);
        const float4 b = *(const float4*)(bet + lane * 4);
        uint2 u = make_uint2(pack_bf2((v.x - mean) * rstd * g.x + b.x,
                                      (v.y - mean) * rstd * g.y + b.y),
                             pack_bf2((v.z - mean) * rstd * g.z + b.z,
                                      (v.w - mean) * rstd * g.w + b.w));
        long orow = spatial_to_win(t);
        *(uint2*)(g_xw + orow * CDIM + lane * 4) = u;
    } else {
        int i = (blockIdx.x - LN_BLOCKS) * blockDim.x + threadIdx.x;
        if (i < CVT_UNITS) {
            const float* src; bf16* dst; int off;
            if (i < 12288)      { src = wq; dst = g_wq; off = i; }
            else if (i < 16384) { src = wp; dst = g_wp; off = i - 12288; }
            else if (i < 32768) { src = w1; dst = g_w1; off = i - 16384; }
            else                { src = w2; dst = g_w2; off = i - 32768; }
            float4 v = *(const float4*)(src + off * 4);
            uint2 u = make_uint2(pack_bf2(v.x, v.y), pack_bf2(v.z, v.w));
            *(uint2*)(dst + off * 4) = u;
        } else {
            int j = i - CVT_UNITS;
            if (j < BIAS_UNITS) {
                int h = j / (NTOK * BSTR);
                int r = j % (NTOK * BSTR);
                int n = r / BSTR;
                int m = r % BSTR;
                float bv = (m < NTOK) ? bias_table[rel_index[n * NTOK + m] * NH + h]
                                      : -10000.0f;
                g_bias[j] = __float2bfloat16(bv);
            }
        }
    }
}

// ---------------------------------------------------------------------------
// BF16 GEMM (R5 exact): 128x128 block, BK=32, 3-stage cp.async, warp 64x32.
// MODE 0: qkv  -> +bias; scale q-part (colBase==0); bf16 out [M,384]
// MODE 1: proj -> +bias; permute; += resid(x); fp32 g_x2  AND fused LN2 -> bf16 g_xw
// MODE 2: fc1  -> +bias; exact GELU; bf16 out [M,512]
// MODE 3: fc2  -> +bias; += resid(g_x2); fp32 out d_out
// ---------------------------------------------------------------------------
#define GS 40                  // smem row stride (halves): 32 + 8 pad
#define G_STAGE (256 * GS)     // As(128)+Ws(128) rows per stage
template<int MODE, int KT>
__global__ __launch_bounds__(256, 2)
void gemm_kernel(const bf16* __restrict__ A,
                 const bf16* __restrict__ Wt,
                 const float* __restrict__ bias,
                 const float* __restrict__ resid,
                 const float* __restrict__ gam,
                 const float* __restrict__ bet,
                 void* __restrict__ Cv,
                 int N) {
    extern __shared__ bf16 sm[];
    bf16* Asb[3] = { sm, sm + G_STAGE, sm + 2 * G_STAGE };
    bf16* Wsb[3] = { sm + 128 * GS, sm + G_STAGE + 128 * GS, sm + 2 * G_STAGE + 128 * GS };

    const int tid  = threadIdx.x;
    const int lane = tid & 31;
    const int warp = tid >> 5;
    const int warpM = warp >> 2;        // 0..1
    const int warpN = warp & 3;         // 0..3
    const int gid = lane >> 2;          // 0..7
    const int tig = lane & 3;           // 0..3

    const long rowBase = (long)blockIdx.y * 128;
    const int  colBase = blockIdx.x * 128;
    const int  K = KT;

    float cc[4][4][4];
    #pragma unroll
    for (int mi = 0; mi < 4; mi++)
        #pragma unroll
        for (int ni = 0; ni < 4; ni++)
            #pragma unroll
            for (int e = 0; e < 4; e++) cc[mi][ni][e] = 0.f;

    const int ld_row = tid >> 2;        // 0..63
    const int ld_kq  = (tid & 3) * 8;   // halves

    auto load_tile = [&](int buf, int k0) {
        #pragma unroll
        for (int r = 0; r < 2; r++) {
            int m = ld_row + r * 64;
            cp_async16(&Asb[buf][m * GS + ld_kq], A + (rowBase + m) * K + k0 + ld_kq);
        }
        #pragma unroll
        for (int r = 0; r < 2; r++) {
            int n = ld_row + r * 64;
            cp_async16(&Wsb[buf][n * GS + ld_kq], Wt + (long)(colBase + n) * K + k0 + ld_kq);
        }
    };

    constexpr int nk = KT / 32;
    load_tile(0, 0);  cp_commit();
    load_tile(1, 32); cp_commit();

    const int a_r = (lane & 7) + ((lane >> 3) & 1) * 8;
    const int a_k = (lane >> 4) * 8;
    const int b_n = (lane & 7) + (lane >> 4) * 8;
    const int b_k = ((lane >> 3) & 1) * 8;

    #pragma unroll
    for (int it = 0; it < nk; it++) {
        if (it < nk - 1) cp_wait<1>(); else cp_wait<0>();
        __syncthreads();
        if (it + 2 < nk) { load_tile((it + 2) % 3, (it + 2) * 32); cp_commit(); }

        const bf16* As = Asb[it % 3];
        const bf16* Ws = Wsb[it % 3];
        #pragma unroll
        for (int ks = 0; ks < 2; ks++) {
            const int kk = ks * 16;
            uint32_t af[4][4];
            uint32_t bf[4][2];
            #pragma unroll
            for (int mi = 0; mi < 4; mi++)
                ldsm_x4(af[mi], As + (warpM * 64 + mi * 16 + a_r) * GS + kk + a_k);
            #pragma unroll
            for (int np = 0; np < 2; np++) {
                uint32_t r4[4];
                ldsm_x4(r4, Ws + (warpN * 32 + np * 16 + b_n) * GS + kk + b_k);
                bf[2 * np][0] = r4[0]; bf[2 * np][1] = r4[1];
                bf[2 * np + 1][0] = r4[2]; bf[2 * np + 1][1] = r4[3];
            }
            #pragma unroll
            for (int mi = 0; mi < 4; mi++)
                #pragma unroll
                for (int ni = 0; ni < 4; ni++)
                    mma_bf16(cc[mi][ni], af[mi], bf[ni]);
        }
    }

    if (MODE == 1) {
        __syncthreads();                 // all warps done with smem stages
        float* red = (float*)sm;         // [128][2] row sums
        if (tid < 128) { red[2 * tid] = 0.f; red[2 * tid + 1] = 0.f; }
        __syncthreads();

        long orows[4][2];
        float* C = (float*)Cv;
        #pragma unroll
        for (int mi = 0; mi < 4; mi++) {
            #pragma unroll
            for (int half = 0; half < 2; half++) {
                int rloc = warpM * 64 + mi * 16 + gid + half * 8;
                long orow = win_to_spatial(rowBase + rloc);
                orows[mi][half] = orow;
                float s = 0.f, sq = 0.f;
                #pragma unroll
                for (int ni = 0; ni < 4; ni++) {
                    int col = warpN * 32 + ni * 8 + 2 * tig;
                    const float2 r = *(const float2*)(resid + orow * CDIM + col);
                    float v0 = cc[mi][ni][half * 2 + 0] + bias[col]     + r.x;
                    float v1 = cc[mi][ni][half * 2 + 1] + bias[col + 1] + r.y;
                    cc[mi][ni][half * 2 + 0] = v0;
                    cc[mi][ni][half * 2 + 1] = v1;
                    *(float2*)(C + orow * CDIM + col) = make_float2(v0, v1);
                    s += v0 + v1; sq += v0 * v0 + v1 * v1;
                }
                s  += __shfl_xor_sync(0xffffffffu, s, 1);
                sq += __shfl_xor_sync(0xffffffffu, sq, 1);
                s  += __shfl_xor_sync(0xffffffffu, s, 2);
                sq += __shfl_xor_sync(0xffffffffu, sq, 2);
                if (tig == 0) {
                    atomicAdd(&red[2 * rloc],     s);
                    atomicAdd(&red[2 * rloc + 1], sq);
                }
            }
        }
        __syncthreads();
        #pragma unroll
        for (int mi = 0; mi < 4; mi++) {
            #pragma unroll
            for (int half = 0; half < 2; half++) {
                int rloc = warpM * 64 + mi * 16 + gid + half * 8;
                long orow = orows[mi][half];
                float mean = red[2 * rloc] * (1.0f / CDIM);
                float var  = red[2 * rloc + 1] * (1.0f / CDIM) - mean * mean;
                float rstd = rsqrtf(var + 1e-5f);
                #pragma unroll
                for (int ni = 0; ni < 4; ni++) {
                    int col = warpN * 32 + ni * 8 + 2 * tig;
                    float v0 = cc[mi][ni][half * 2 + 0];
                    float v1 = cc[mi][ni][half * 2 + 1];
                    float y0 = (v0 - mean) * rstd * gam[col]     + bet[col];
                    float y1 = (v1 - mean) * rstd * gam[col + 1] + bet[col + 1];
                    *(uint32_t*)(g_xw + orow * CDIM + col) = pack_bf2(y0, y1);
                }
            }
        }
        return;
    }

    #pragma unroll
    for (int mi = 0; mi < 4; mi++) {
        #pragma unroll
        for (int half = 0; half < 2; half++) {
            long row = rowBase + warpM * 64 + mi * 16 + gid + half * 8;
            #pragma unroll
            for (int ni = 0; ni < 4; ni++) {
                int col = colBase + warpN * 32 + ni * 8 + 2 * tig;
                float v0 = cc[mi][ni][half * 2 + 0] + bias[col];
                float v1 = cc[mi][ni][half * 2 + 1] + bias[col + 1];
                if (MODE == 0) {
                    if (colBase == 0) { v0 *= 0.17677669529663687f; v1 *= 0.17677669529663687f; }
                }
                if (MODE == 2) {
                    v0 = 0.5f * v0 * (1.0f + erff(v0 * 0.70710678118654752f));
                    v1 = 0.5f * v1 * (1.0f + erff(v1 * 0.70710678118654752f));
                }
                if (MODE == 3) {
                    float* C = (float*)Cv;
                    const float2 r = *(const float2*)(resid + row * CDIM + col);
                    *(float2*)(C + row * CDIM + col) = make_float2(v0 + r.x, v1 + r.y);
                } else {
                    bf16* C = (bf16*)Cv;
                    *(uint32_t*)(C + row * (long)N + col) = pack_bf2(v0, v1);
                }
            }
        }
    }
}

// ---------------------------------------------------------------------------
// BF16 tensor-core window attention v3.1: 7 warps (224 thr), one 16-row tile
// per warp; register-P (FA2); bf16 padded bias; cp.async loads.
// smem 28160 B, 3 CTAs/SM.
// ---------------------------------------------------------------------------
#define AQS 40
#define NPAD 112
#define ATTN_ELEMS ((128 + 2 * NPAD) * AQS)   // 14080 bf16 = 28160 B
#define ATHREADS 224
__global__ __launch_bounds__(ATHREADS, 3)
void attn_kernel() {
    extern __shared__ bf16 asm_[];
    bf16* qs  = asm_;                          // [128][40] (rows 112..127 unused)
    bf16* ks  = asm_ + 128 * AQS;              // [112][40]
    bf16* vsr = asm_ + (128 + NPAD) * AQS;     // [112][40]

    const int w = blockIdx.x;
    const int h = blockIdx.y;
    const int tid  = threadIdx.x;
    const int warp = tid >> 5;                 // 0..6, owns rows [16w, 16w+16)
    const int lane = tid & 31;
    const int gid = lane >> 2;
    const int tig = lane & 3;

    const bf16* base = g_qkv + (size_t)w * NTOK * QKVN + h * HD;

    for (int i = tid; i < NTOK * 4; i += ATHREADS) {
        int m = i >> 2, c = (i & 3) * 8;
        cp_async16(&qs [m * AQS + c], base + m * QKVN + c);
        cp_async16(&ks [m * AQS + c], base + m * QKVN + CDIM + c);
        cp_async16(&vsr[m * AQS + c], base + m * QKVN + 2 * CDIM + c);
    }
    const uint4 z4 = make_uint4(0, 0, 0, 0);
    if (tid < 14 * 4) {
        int m = 98 + (tid >> 2), c = (tid & 3) * 8;
        *(uint4*)&ks [m * AQS + c] = z4;
        *(uint4*)&vsr[m * AQS + c] = z4;
    }
    cp_commit();
    cp_wait<0>();
    __syncthreads();

    const int a_r = (lane & 7) + ((lane >> 3) & 1) * 8;
    const int a_k = (lane >> 4) * 8;
    const int b_n = (lane & 7) + (lane >> 4) * 8;
    const int b_k = ((lane >> 3) & 1) * 8;
    const int t_r = (lane & 7) + ((lane >> 3) & 1) * 8;
    const int t_c = (lane >> 4) * 8;

    // ---- S = Q K^T : 16 rows x 112 cols, k=32 ----
    float cc[14][4];
    #pragma unroll
    for (int ni = 0; ni < 14; ni++)
        #pragma unroll
        for (int e = 0; e < 4; e++) cc[ni][e] = 0.f;

    #pragma unroll
    for (int ksx = 0; ksx < 2; ksx++) {
        const int kk = ksx * 16;
        uint32_t af[4];
        ldsm_x4(af, qs + (warp * 16 + a_r) * AQS + kk + a_k);
        #pragma unroll
        for (int np = 0; np < 7; np++) {
            uint32_t r4[4];
            ldsm_x4(r4, ks + (np * 16 + b_n) * AQS + kk + b_k);
            uint32_t b0[2] = { r4[0], r4[1] };
            uint32_t b1[2] = { r4[2], r4[3] };
            mma_bf16(cc[2 * np],     af, b0);
            mma_bf16(cc[2 * np + 1], af, b1);
        }
    }

    // ---- softmax: branch-free with padded bf16 bias (pad cols -> exp = 0) ----
    float rsum[2] = { 0.f, 0.f };
    const bf16* gb = g_bias + h * NTOK * BSTR;
    {
        int r0 = warp * 16 + gid;
        int r1 = r0 + 8;
        const bf16* b0p = gb + (r0 < NTOK ? r0 : NTOK - 1) * BSTR;
        const bf16* b1p = gb + (r1 < NTOK ? r1 : NTOK - 1) * BSTR;
        #pragma unroll
        for (int ni = 0; ni < 14; ni++) {
            int col = ni * 8 + 2 * tig;
            float2 bb0 = __bfloat1622float2(*(const bf162*)(b0p + col));
            float2 bb1 = __bfloat1622float2(*(const bf162*)(b1p + col));
            float e;
            e = __expf(cc[ni][0] + bb0.x); cc[ni][0] = e; rsum[0] += e;
            e = __expf(cc[ni][1] + bb0.y); cc[ni][1] = e; rsum[0] += e;
            e = __expf(cc[ni][2] + bb1.x); cc[ni][2] = e; rsum[1] += e;
            e = __expf(cc[ni][3] + bb1.y); cc[ni][3] = e; rsum[1] += e;
        }
    }
    float inv[2];
    #pragma unroll
    for (int hf = 0; hf < 2; hf++) {
        float s = rsum[hf];
        s += __shfl_xor_sync(0xffffffffu, s, 1);
        s += __shfl_xor_sync(0xffffffffu, s, 2);
        inv[hf] = 1.0f / s;
    }

    // ---- O = P V : 16 rows x 32 cols, k=112; P in registers ----
    float oo[4][4];
    #pragma unroll
    for (int ni = 0; ni < 4; ni++)
        #pragma unroll
        for (int e = 0; e < 4; e++) oo[ni][e] = 0.f;

    #pragma unroll
    for (int k2 = 0; k2 < 7; k2++) {
        const int kk = k2 * 16;
        uint32_t af[4];
        af[0] = pack_bf2(cc[2 * k2][0]     * inv[0], cc[2 * k2][1]     * inv[0]);
        af[1] = pack_bf2(cc[2 * k2][2]     * inv[1], cc[2 * k2][3]     * inv[1]);
        af[2] = pack_bf2(cc[2 * k2 + 1][0] * inv[0], cc[2 * k2 + 1][1] * inv[0]);
        af[3] = pack_bf2(cc[2 * k2 + 1][2] * inv[1], cc[2 * k2 + 1][3] * inv[1]);
        #pragma unroll
        for (int np = 0; np < 2; np++) {
            int n0 = np * 16;
            uint32_t r4[4];
            ldsm_x4_t(r4, vsr + (kk + t_r) * AQS + n0 + t_c);
            uint32_t b0[2] = { r4[0], r4[1] };
            uint32_t b1[2] = { r4[2], r4[3] };
            mma_bf16(oo[2 * np],     af, b0);
            mma_bf16(oo[2 * np + 1], af, b1);
        }
    }

    #pragma unroll
    for (int hf = 0; hf < 2; hf++) {
        int row = warp * 16 + gid + hf * 8;
        if (row < NTOK) {
            bf16* op = g_attn + ((size_t)w * NTOK + row) * CDIM + h * HD;
            #pragma unroll
            for (int ni = 0; ni < 4; ni++) {
                int col = ni * 8 + 2 * tig;
                *(uint32_t*)(op + col) = pack_bf2(oo[ni][hf * 2], oo[ni][hf * 2 + 1]);
            }
        }
    }
}

// ---------------------------------------------------------------------------
// launcher
// ---------------------------------------------------------------------------
extern "C" void kernel_launch(void* const* d_in, const int* in_sizes, int n_in,
                              void* d_out, int out_size) {
    const float* x          = (const float*)d_in[0];
    const float* norm1_w    = (const float*)d_in[1];
    const float* norm1_b    = (const float*)d_in[2];
    const float* qkv_w      = (const float*)d_in[3];
    const float* qkv_b      = (const float*)d_in[4];
    const float* bias_table = (const float*)d_in[5];
    const float* proj_w     = (const float*)d_in[6];
    const float* proj_b     = (const float*)d_in[7];
    const float* norm2_w    = (const float*)d_in[8];
    const float* norm2_b    = (const float*)d_in[9];
    const float* fc1_w      = (const float*)d_in[10];
    const float* fc1_b      = (const float*)d_in[11];
    const float* fc2_w      = (const float*)d_in[12];
    const float* fc2_b      = (const float*)d_in[13];
    const int*   rel_index  = (const int*)d_in[14];
    float* out = (float*)d_out;

    bf16 *p_xw, *p_qkv, *p_attn, *p_h;
    bf16 *p_wq, *p_wp, *p_w1, *p_w2;
    float *p_x2;
    cudaGetSymbolAddress((void**)&p_xw,   g_xw);
    cudaGetSymbolAddress((void**)&p_qkv,  g_qkv);
    cudaGetSymbolAddress((void**)&p_attn, g_attn);
    cudaGetSymbolAddress((void**)&p_x2,   g_x2);
    cudaGetSymbolAddress((void**)&p_h,    g_h);
    cudaGetSymbolAddress((void**)&p_wq,   g_wq);
    cudaGetSymbolAddress((void**)&p_wp,   g_wp);
    cudaGetSymbolAddress((void**)&p_w1,   g_w1);
    cudaGetSymbolAddress((void**)&p_w2,   g_w2);

    const int GEMM_SMEM = 3 * G_STAGE * (int)sizeof(bf16);   // 61440
    const int ATTN_SMEM = ATTN_ELEMS * (int)sizeof(bf16);    // 28160
    cudaFuncSetAttribute((const void*)gemm_kernel<0,128>, cudaFuncAttributeMaxDynamicSharedMemorySize, GEMM_SMEM);
    cudaFuncSetAttribute((const void*)gemm_kernel<1,128>, cudaFuncAttributeMaxDynamicSharedMemorySize, GEMM_SMEM);
    cudaFuncSetAttribute((const void*)gemm_kernel<2,128>, cudaFuncAttributeMaxDynamicSharedMemorySize, GEMM_SMEM);
    cudaFuncSetAttribute((const void*)gemm_kernel<3,512>, cudaFuncAttributeMaxDynamicSharedMemorySize, GEMM_SMEM);
    cudaFuncSetAttribute((const void*)attn_kernel,        cudaFuncAttributeMaxDynamicSharedMemorySize, ATTN_SMEM);

    // 0) merged setup + LN1 (independent prologue work in one launch)
    setup_ln1_kernel<<<LN_BLOCKS + SETUP_BLOCKS, 256>>>(
        x, norm1_w, norm1_b, qkv_w, proj_w, fc1_w, fc2_w, bias_table, rel_index);

    // 1) QKV gemm (+ q scale), bf16 out
    gemm_kernel<0,128><<<dim3(QKVN / 128, TOK / 128), 256, GEMM_SMEM>>>(
        p_xw, p_wq, qkv_b, nullptr, nullptr, nullptr, p_qkv, QKVN);

    // 2) window attention (7-warp, register-P, cp.async, bf16 bias)
    attn_kernel<<<dim3(NWIN, NH), ATHREADS, ATTN_SMEM>>>();

    // 3) proj gemm + window reverse + residual(x) -> g_x2 (fp32) + fused LN2 -> g_xw (bf16)
    gemm_kernel<1,128><<<dim3(CDIM / 128, TOK / 128), 256, GEMM_SMEM>>>(
        p_attn, p_wp, proj_b, x, norm2_w, norm2_b, p_x2, CDIM);

    // 4) fc1 + exact GELU, bf16 out
    gemm_kernel<2,128><<<dim3(CH / 128, TOK / 128), 256, GEMM_SMEM>>>(
        p_xw, p_w1, fc1_b, nullptr, nullptr, nullptr, p_h, CH);

    // 5) fc2 + residual(g_x2) -> d_out (fp32)
    gemm_kernel<3,512><<<dim3(CDIM / 128, TOK / 128), 256, GEMM_SMEM>>>(
        p_h, p_w2, fc2_b, p_x2, nullptr, nullptr, out, CDIM);

    (void)in_sizes; (void)n_in; (void)out_size;
}

// round 17
// speedup vs baseline: 1.2224x; 1.0232x over previous
#include <cuda_runtime.h>
#include <cuda_bf16.h>
#include <math.h>
#include <stdint.h>

// ---------------------------------------------------------------------------
// Problem constants
// ---------------------------------------------------------------------------
#define TOK   50176      // 2*8*56*56
#define CDIM  128
#define CH    512
#define NWIN  512        // 2 * 4*8*8
#define NTOK  98         // 2*7*7
#define NH    4
#define HD    32
#define QKVN  384
#define BSTR  112        // padded bias row stride

typedef __nv_bfloat16  bf16;
typedef __nv_bfloat162 bf162;

// ---------------------------------------------------------------------------
// Scratch (device globals: allocation-free, graph-capture safe)
// ---------------------------------------------------------------------------
__device__ bf16  g_xw  [(size_t)TOK * CDIM];   // LN1 out (window order) / LN2 out (spatial)
__device__ bf16  g_qkv [(size_t)TOK * QKVN];   // qkv, window order
__device__ bf16  g_attn[(size_t)TOK * CDIM];   // attention out, window order
__device__ float g_x2  [(size_t)TOK * CDIM];   // x + proj (spatial, fp32)
__device__ bf16  g_h   [(size_t)TOK * CH];     // fc1 output
__device__ bf16  g_bias[NH * NTOK * BSTR];     // gathered attention bias (bf16), padded
// bf16 weights
__device__ bf16  g_wq[QKVN * CDIM];
__device__ bf16  g_wp[CDIM * CDIM];
__device__ bf16  g_w1[CH * CDIM];
__device__ bf16  g_w2[CDIM * CH];

// ---------------------------------------------------------------------------
// index helpers (int32: all indices < 2^25, div-by-const -> mul/shift)
// ---------------------------------------------------------------------------
__device__ __forceinline__ int win_to_spatial(int row) {
    int w = row / NTOK;
    int n = row % NTOK;
    int b   = w >> 8;
    int rem = w & 255;
    int wdi = rem >> 6, whi = (rem >> 3) & 7, wwi = rem & 7;
    int zd = n / 49; int r2 = n % 49; int zh = r2 / 7, zw = r2 % 7;
    int d  = wdi * 2 + zd;
    int hh = whi * 7 + zh;
    int xx = wwi * 7 + zw;
    return ((b * 8 + d) * 56 + hh) * 56 + xx;
}

__device__ __forceinline__ int spatial_to_win(int t) {
    int b  = t / 25088;
    int r  = t % 25088;
    int d  = r / 3136; r %= 3136;
    int hh = r / 56;
    int xx = r % 56;
    int widx = ((b * 4 + (d >> 1)) * 8 + hh / 7) * 8 + xx / 7;
    int n    = ((d & 1) * 7 + hh % 7) * 7 + xx % 7;
    return widx * NTOK + n;
}

// ---------------------------------------------------------------------------
// async copy + ldmatrix + mma helpers
// ---------------------------------------------------------------------------
__device__ __forceinline__ void cp_async16(bf16* smem_dst, const bf16* gmem_src) {
    uint32_t s = (uint32_t)__cvta_generic_to_shared(smem_dst);
    asm volatile("cp.async.cg.shared.global [%0], [%1], 16;\n" :: "r"(s), "l"(gmem_src));
}
__device__ __forceinline__ void cp_commit() { asm volatile("cp.async.commit_group;\n"); }
template<int N>
__device__ __forceinline__ void cp_wait() { asm volatile("cp.async.wait_group %0;\n" :: "n"(N)); }

__device__ __forceinline__ void ldsm_x4(uint32_t r[4], const bf16* p) {
    uint32_t a = (uint32_t)__cvta_generic_to_shared(p);
    asm volatile("ldmatrix.sync.aligned.m8n8.x4.shared.b16 {%0,%1,%2,%3}, [%4];\n"
                 : "=r"(r[0]), "=r"(r[1]), "=r"(r[2]), "=r"(r[3]) : "r"(a));
}
__device__ __forceinline__ void ldsm_x4_t(uint32_t r[4], const bf16* p) {
    uint32_t a = (uint32_t)__cvta_generic_to_shared(p);
    asm volatile("ldmatrix.sync.aligned.m8n8.x4.trans.shared.b16 {%0,%1,%2,%3}, [%4];\n"
                 : "=r"(r[0]), "=r"(r[1]), "=r"(r[2]), "=r"(r[3]) : "r"(a));
}
__device__ __forceinline__ void mma_bf16(float c[4], const uint32_t a[4], const uint32_t b[2]) {
    asm volatile(
        "mma.sync.aligned.m16n8k16.row.col.f32.bf16.bf16.f32 "
        "{%0,%1,%2,%3}, {%4,%5,%6,%7}, {%8,%9}, {%0,%1,%2,%3};\n"
        : "+f"(c[0]), "+f"(c[1]), "+f"(c[2]), "+f"(c[3])
        : "r"(a[0]), "r"(a[1]), "r"(a[2]), "r"(a[3]), "r"(b[0]), "r"(b[1]));
}

__device__ __forceinline__ uint32_t pack_bf2(float a, float b) {
    bf162 p = __float22bfloat162_rn(make_float2(a, b));
    return *(uint32_t*)&p;
}

// ---------------------------------------------------------------------------
// merged setup+LN1 kernel, 256 threads/block:
//   blocks [0, LN_BLOCKS)  : LN1 + window partition (8 tokens/block)
//   blocks [LN_BLOCKS, ..) : weight cvt (float4 units) + bias gather
// bias layout: [NH][98][112] bf16, cols 98..111 = -1e4 (exp -> exactly 0)
// ---------------------------------------------------------------------------
#define LN_BLOCKS  (TOK / 8)            // 6272
#define CVT_UNITS  49152
#define BIAS_UNITS (NH * NTOK * BSTR)   // 43904
#define SETUP_BLOCKS ((CVT_UNITS + BIAS_UNITS + 255) / 256)
__global__ __launch_bounds__(256)
void setup_ln1_kernel(const float* __restrict__ x,
                      const float* __restrict__ gam,
                      const float* __restrict__ bet,
                      const float* __restrict__ wq,
                      const float* __restrict__ wp,
                      const float* __restrict__ w1,
                      const float* __restrict__ w2,
                      const float* __restrict__ bias_table,
                      const int* __restrict__ rel_index) {
    if (blockIdx.x < LN_BLOCKS) {
        int warp = threadIdx.x >> 5;
        int lane = threadIdx.x & 31;
        int t = blockIdx.x * 8 + warp;
        const float4 v = *(const float4*)(x + (long)t * CDIM + lane * 4);
        float s  = v.x + v.y + v.z + v.w;
        float sq = v.x * v.x + v.y * v.y + v.z * v.z + v.w * v.w;
        #pragma unroll
        for (int o = 16; o; o >>= 1) {
            s  += __shfl_xor_sync(0xffffffffu, s,  o);
            sq += __shfl_xor_sync(0xffffffffu, sq, o);
        }
        float mean = s * (1.0f / CDIM);
        float var  = sq * (1.0f / CDIM) - mean * mean;
        float rstd = rsqrtf(var + 1e-5f);
        const float4 g = *(const float4*)(gam + lane * 4);
        const float4 b = *(const float4*)(bet + lane * 4);
        uint2 u = make_uint2(pack_bf2((v.x - mean) * rstd * g.x + b.x,
                                      (v.y - mean) * rstd * g.y + b.y),
                             pack_bf2((v.z - mean) * rstd * g.z + b.z,
                                      (v.w - mean) * rstd * g.w + b.w));
        int orow = spatial_to_win(t);
        *(uint2*)(g_xw + (long)orow * CDIM + lane * 4) = u;
    } else {
        int i = (blockIdx.x - LN_BLOCKS) * blockDim.x + threadIdx.x;
        if (i < CVT_UNITS) {
            const float* src; bf16* dst; int off;
            if (i < 12288)      { src = wq; dst = g_wq; off = i; }
            else if (i < 16384) { src = wp; dst = g_wp; off = i - 12288; }
            else if (i < 32768) { src = w1; dst = g_w1; off = i - 16384; }
            else                { src = w2; dst = g_w2; off = i - 32768; }
            float4 v = *(const float4*)(src + off * 4);
            uint2 u = make_uint2(pack_bf2(v.x, v.y), pack_bf2(v.z, v.w));
            *(uint2*)(dst + off * 4) = u;
        } else {
            int j = i - CVT_UNITS;
            if (j < BIAS_UNITS) {
                int h = j / (NTOK * BSTR);
                int r = j % (NTOK * BSTR);
                int n = r / BSTR;
                int m = r % BSTR;
                float bv = (m < NTOK) ? bias_table[rel_index[n * NTOK + m] * NH + h]
                                      : -10000.0f;
                g_bias[j] = __float2bfloat16(bv);
            }
        }
    }
}

// ---------------------------------------------------------------------------
// BF16 GEMM: 128x128 block, BK=32, 3-stage cp.async, warp 64x32.
// MODE 0: qkv  -> +bias; scale q-part (colBase==0); bf16 out [M,384]
// MODE 1: proj -> +bias; permute; += resid(x); fp32 g_x2  AND fused LN2 -> bf16 g_xw
//                (LN2 reduction via addressed smem partials, NO atomics)
// MODE 2: fc1  -> +bias; exact GELU; bf16 out [M,512]
// MODE 3: fc2  -> +bias; += resid(g_x2); fp32 out d_out
// ---------------------------------------------------------------------------
#define GS 40                  // smem row stride (halves): 32 + 8 pad
#define G_STAGE (256 * GS)     // As(128)+Ws(128) rows per stage
template<int MODE, int KT>
__global__ __launch_bounds__(256, 2)
void gemm_kernel(const bf16* __restrict__ A,
                 const bf16* __restrict__ Wt,
                 const float* __restrict__ bias,
                 const float* __restrict__ resid,
                 const float* __restrict__ gam,
                 const float* __restrict__ bet,
                 void* __restrict__ Cv,
                 int N) {
    extern __shared__ bf16 sm[];
    bf16* Asb[3] = { sm, sm + G_STAGE, sm + 2 * G_STAGE };
    bf16* Wsb[3] = { sm + 128 * GS, sm + G_STAGE + 128 * GS, sm + 2 * G_STAGE + 128 * GS };

    const int tid  = threadIdx.x;
    const int lane = tid & 31;
    const int warp = tid >> 5;
    const int warpM = warp >> 2;        // 0..1
    const int warpN = warp & 3;         // 0..3
    const int gid = lane >> 2;          // 0..7
    const int tig = lane & 3;           // 0..3

    const int rowBase = blockIdx.y * 128;
    const int colBase = blockIdx.x * 128;
    const int K = KT;

    float cc[4][4][4];
    #pragma unroll
    for (int mi = 0; mi < 4; mi++)
        #pragma unroll
        for (int ni = 0; ni < 4; ni++)
            #pragma unroll
            for (int e = 0; e < 4; e++) cc[mi][ni][e] = 0.f;

    const int ld_row = tid >> 2;        // 0..63
    const int ld_kq  = (tid & 3) * 8;   // halves

    auto load_tile = [&](int buf, int k0) {
        #pragma unroll
        for (int r = 0; r < 2; r++) {
            int m = ld_row + r * 64;
            cp_async16(&Asb[buf][m * GS + ld_kq], A + (long)(rowBase + m) * K + k0 + ld_kq);
        }
        #pragma unroll
        for (int r = 0; r < 2; r++) {
            int n = ld_row + r * 64;
            cp_async16(&Wsb[buf][n * GS + ld_kq], Wt + (long)(colBase + n) * K + k0 + ld_kq);
        }
    };

    constexpr int nk = KT / 32;
    load_tile(0, 0);  cp_commit();
    load_tile(1, 32); cp_commit();

    const int a_r = (lane & 7) + ((lane >> 3) & 1) * 8;
    const int a_k = (lane >> 4) * 8;
    const int b_n = (lane & 7) + (lane >> 4) * 8;
    const int b_k = ((lane >> 3) & 1) * 8;

    #pragma unroll
    for (int it = 0; it < nk; it++) {
        if (it < nk - 1) cp_wait<1>(); else cp_wait<0>();
        __syncthreads();
        if (it + 2 < nk) { load_tile((it + 2) % 3, (it + 2) * 32); cp_commit(); }

        const bf16* As = Asb[it % 3];
        const bf16* Ws = Wsb[it % 3];
        #pragma unroll
        for (int ks = 0; ks < 2; ks++) {
            const int kk = ks * 16;
            uint32_t af[4][4];
            uint32_t bf[4][2];
            #pragma unroll
            for (int mi = 0; mi < 4; mi++)
                ldsm_x4(af[mi], As + (warpM * 64 + mi * 16 + a_r) * GS + kk + a_k);
            #pragma unroll
            for (int np = 0; np < 2; np++) {
                uint32_t r4[4];
                ldsm_x4(r4, Ws + (warpN * 32 + np * 16 + b_n) * GS + kk + b_k);
                bf[2 * np][0] = r4[0]; bf[2 * np][1] = r4[1];
                bf[2 * np + 1][0] = r4[2]; bf[2 * np + 1][1] = r4[3];
            }
            #pragma unroll
            for (int mi = 0; mi < 4; mi++)
                #pragma unroll
                for (int ni = 0; ni < 4; ni++)
                    mma_bf16(cc[mi][ni], af[mi], bf[ni]);
        }
    }

    if (MODE == 1) {
        // fused: x2 = resid + proj_out (+bias) -> fp32 g_x2 (spatial);
        // LN2(x2) -> bf16 g_xw. Cross-warp reduction via addressed partials:
        // red[row][warpN] = (s, sq); every slot written exactly once, no atomics.
        __syncthreads();                 // all warps done with smem stages
        float* red = (float*)sm;         // [128][4][2] = 4KB

        int orows[4][2];
        float* C = (float*)Cv;
        #pragma unroll
        for (int mi = 0; mi < 4; mi++) {
            #pragma unroll
            for (int half = 0; half < 2; half++) {
                int rloc = warpM * 64 + mi * 16 + gid + half * 8;
                int orow = win_to_spatial(rowBase + rloc);
                orows[mi][half] = orow;
                float s = 0.f, sq = 0.f;
                #pragma unroll
                for (int ni = 0; ni < 4; ni++) {
                    int col = warpN * 32 + ni * 8 + 2 * tig;
                    const float2 r = *(const float2*)(resid + (long)orow * CDIM + col);
                    float v0 = cc[mi][ni][half * 2 + 0] + bias[col]     + r.x;
                    float v1 = cc[mi][ni][half * 2 + 1] + bias[col + 1] + r.y;
                    cc[mi][ni][half * 2 + 0] = v0;
                    cc[mi][ni][half * 2 + 1] = v1;
                    *(float2*)(C + (long)orow * CDIM + col) = make_float2(v0, v1);
                    s += v0 + v1; sq += v0 * v0 + v1 * v1;
                }
                s  += __shfl_xor_sync(0xffffffffu, s, 1);
                sq += __shfl_xor_sync(0xffffffffu, sq, 1);
                s  += __shfl_xor_sync(0xffffffffu, s, 2);
                sq += __shfl_xor_sync(0xffffffffu, sq, 2);
                if (tig == 0)
                    *(float2*)&red[(rloc * 4 + warpN) * 2] = make_float2(s, sq);
            }
        }
        __syncthreads();
        #pragma unroll
        for (int mi = 0; mi < 4; mi++) {
            #pragma unroll
            for (int half = 0; half < 2; half++) {
                int rloc = warpM * 64 + mi * 16 + gid + half * 8;
                int orow = orows[mi][half];
                const float2 p0 = *(const float2*)&red[(rloc * 4 + 0) * 2];
                const float2 p1 = *(const float2*)&red[(rloc * 4 + 1) * 2];
                const float2 p2 = *(const float2*)&red[(rloc * 4 + 2) * 2];
                const float2 p3 = *(const float2*)&red[(rloc * 4 + 3) * 2];
                float s  = (p0.x + p1.x) + (p2.x + p3.x);
                float sq = (p0.y + p1.y) + (p2.y + p3.y);
                float mean = s * (1.0f / CDIM);
                float var  = sq * (1.0f / CDIM) - mean * mean;
                float rstd = rsqrtf(var + 1e-5f);
                #pragma unroll
                for (int ni = 0; ni < 4; ni++) {
                    int col = warpN * 32 + ni * 8 + 2 * tig;
                    float v0 = cc[mi][ni][half * 2 + 0];
                    float v1 = cc[mi][ni][half * 2 + 1];
                    float y0 = (v0 - mean) * rstd * gam[col]     + bet[col];
                    float y1 = (v1 - mean) * rstd * gam[col + 1] + bet[col + 1];
                    *(uint32_t*)(g_xw + (long)orow * CDIM + col) = pack_bf2(y0, y1);
                }
            }
        }
        return;
    }

    #pragma unroll
    for (int mi = 0; mi < 4; mi++) {
        #pragma unroll
        for (int half = 0; half < 2; half++) {
            int row = rowBase + warpM * 64 + mi * 16 + gid + half * 8;
            #pragma unroll
            for (int ni = 0; ni < 4; ni++) {
                int col = colBase + warpN * 32 + ni * 8 + 2 * tig;
                float v0 = cc[mi][ni][half * 2 + 0] + bias[col];
                float v1 = cc[mi][ni][half * 2 + 1] + bias[col + 1];
                if (MODE == 0) {
                    if (colBase == 0) { v0 *= 0.17677669529663687f; v1 *= 0.17677669529663687f; }
                }
                if (MODE == 2) {
                    v0 = 0.5f * v0 * (1.0f + erff(v0 * 0.70710678118654752f));
                    v1 = 0.5f * v1 * (1.0f + erff(v1 * 0.70710678118654752f));
                }
                if (MODE == 3) {
                    float* C = (float*)Cv;
                    const float2 r = *(const float2*)(resid + (long)row * CDIM + col);
                    *(float2*)(C + (long)row * CDIM + col) = make_float2(v0 + r.x, v1 + r.y);
                } else {
                    bf16* C = (bf16*)Cv;
                    *(uint32_t*)(C + (long)row * N + col) = pack_bf2(v0, v1);
                }
            }
        }
    }
}

// ---------------------------------------------------------------------------
// BF16 tensor-core window attention v3.1: 7 warps (224 thr), one 16-row tile
// per warp; register-P (FA2); bf16 padded bias; cp.async loads.
// smem 28160 B, 3 CTAs/SM.
// ---------------------------------------------------------------------------
#define AQS 40
#define NPAD 112
#define ATTN_ELEMS ((128 + 2 * NPAD) * AQS)   // 14080 bf16 = 28160 B
#define ATHREADS 224
__global__ __launch_bounds__(ATHREADS, 3)
void attn_kernel() {
    extern __shared__ bf16 asm_[];
    bf16* qs  = asm_;                          // [128][40] (rows 112..127 unused)
    bf16* ks  = asm_ + 128 * AQS;              // [112][40]
    bf16* vsr = asm_ + (128 + NPAD) * AQS;     // [112][40]

    const int w = blockIdx.x;
    const int h = blockIdx.y;
    const int tid  = threadIdx.x;
    const int warp = tid >> 5;                 // 0..6, owns rows [16w, 16w+16)
    const int lane = tid & 31;
    const int gid = lane >> 2;
    const int tig = lane & 3;

    const bf16* base = g_qkv + (size_t)w * NTOK * QKVN + h * HD;

    for (int i = tid; i < NTOK * 4; i += ATHREADS) {
        int m = i >> 2, c = (i & 3) * 8;
        cp_async16(&qs [m * AQS + c], base + m * QKVN + c);
        cp_async16(&ks [m * AQS + c], base + m * QKVN + CDIM + c);
        cp_async16(&vsr[m * AQS + c], base + m * QKVN + 2 * CDIM + c);
    }
    const uint4 z4 = make_uint4(0, 0, 0, 0);
    if (tid < 14 * 4) {
        int m = 98 + (tid >> 2), c = (tid & 3) * 8;
        *(uint4*)&ks [m * AQS + c] = z4;
        *(uint4*)&vsr[m * AQS + c] = z4;
    }
    cp_commit();
    cp_wait<0>();
    __syncthreads();

    const int a_r = (lane & 7) + ((lane >> 3) & 1) * 8;
    const int a_k = (lane >> 4) * 8;
    const int b_n = (lane & 7) + (lane >> 4) * 8;
    const int b_k = ((lane >> 3) & 1) * 8;
    const int t_r = (lane & 7) + ((lane >> 3) & 1) * 8;
    const int t_c = (lane >> 4) * 8;

    // ---- S = Q K^T : 16 rows x 112 cols, k=32 ----
    float cc[14][4];
    #pragma unroll
    for (int ni = 0; ni < 14; ni++)
        #pragma unroll
        for (int e = 0; e < 4; e++) cc[ni][e] = 0.f;

    #pragma unroll
    for (int ksx = 0; ksx < 2; ksx++) {
        const int kk = ksx * 16;
        uint32_t af[4];
        ldsm_x4(af, qs + (warp * 16 + a_r) * AQS + kk + a_k);
        #pragma unroll
        for (int np = 0; np < 7; np++) {
            uint32_t r4[4];
            ldsm_x4(r4, ks + (np * 16 + b_n) * AQS + kk + b_k);
            uint32_t b0[2] = { r4[0], r4[1] };
            uint32_t b1[2] = { r4[2], r4[3] };
            mma_bf16(cc[2 * np],     af, b0);
            mma_bf16(cc[2 * np + 1], af, b1);
        }
    }

    // ---- softmax: branch-free with padded bf16 bias (pad cols -> exp = 0) ----
    float rsum[2] = { 0.f, 0.f };
    const bf16* gb = g_bias + h * NTOK * BSTR;
    {
        int r0 = warp * 16 + gid;
        int r1 = r0 + 8;
        const bf16* b0p = gb + (r0 < NTOK ? r0 : NTOK - 1) * BSTR;
        const bf16* b1p = gb + (r1 < NTOK ? r1 : NTOK - 1) * BSTR;
        #pragma unroll
        for (int ni = 0; ni < 14; ni++) {
            int col = ni * 8 + 2 * tig;
            float2 bb0 = __bfloat1622float2(*(const bf162*)(b0p + col));
            float2 bb1 = __bfloat1622float2(*(const bf162*)(b1p + col));
            float e;
            e = __expf(cc[ni][0] + bb0.x); cc[ni][0] = e; rsum[0] += e;
            e = __expf(cc[ni][1] + bb0.y); cc[ni][1] = e; rsum[0] += e;
            e = __expf(cc[ni][2] + bb1.x); cc[ni][2] = e; rsum[1] += e;
            e = __expf(cc[ni][3] + bb1.y); cc[ni][3] = e; rsum[1] += e;
        }
    }
    float inv[2];
    #pragma unroll
    for (int hf = 0; hf < 2; hf++) {
        float s = rsum[hf];
        s += __shfl_xor_sync(0xffffffffu, s, 1);
        s += __shfl_xor_sync(0xffffffffu, s, 2);
        inv[hf] = 1.0f / s;
    }

    // ---- O = P V : 16 rows x 32 cols, k=112; P in registers ----
    float oo[4][4];
    #pragma unroll
    for (int ni = 0; ni < 4; ni++)
        #pragma unroll
        for (int e = 0; e < 4; e++) oo[ni][e] = 0.f;

    #pragma unroll
    for (int k2 = 0; k2 < 7; k2++) {
        const int kk = k2 * 16;
        uint32_t af[4];
        af[0] = pack_bf2(cc[2 * k2][0]     * inv[0], cc[2 * k2][1]     * inv[0]);
        af[1] = pack_bf2(cc[2 * k2][2]     * inv[1], cc[2 * k2][3]     * inv[1]);
        af[2] = pack_bf2(cc[2 * k2 + 1][0] * inv[0], cc[2 * k2 + 1][1] * inv[0]);
        af[3] = pack_bf2(cc[2 * k2 + 1][2] * inv[1], cc[2 * k2 + 1][3] * inv[1]);
        #pragma unroll
        for (int np = 0; np < 2; np++) {
            int n0 = np * 16;
            uint32_t r4[4];
            ldsm_x4_t(r4, vsr + (kk + t_r) * AQS + n0 + t_c);
            uint32_t b0[2] = { r4[0], r4[1] };
            uint32_t b1[2] = { r4[2], r4[3] };
            mma_bf16(oo[2 * np],     af, b0);
            mma_bf16(oo[2 * np + 1], af, b1);
        }
    }

    #pragma unroll
    for (int hf = 0; hf < 2; hf++) {
        int row = warp * 16 + gid + hf * 8;
        if (row < NTOK) {
            bf16* op = g_attn + ((size_t)w * NTOK + row) * CDIM + h * HD;
            #pragma unroll
            for (int ni = 0; ni < 4; ni++) {
                int col = ni * 8 + 2 * tig;
                *(uint32_t*)(op + col) = pack_bf2(oo[ni][hf * 2], oo[ni][hf * 2 + 1]);
            }
        }
    }
}

// ---------------------------------------------------------------------------
// launcher
// ---------------------------------------------------------------------------
extern "C" void kernel_launch(void* const* d_in, const int* in_sizes, int n_in,
                              void* d_out, int out_size) {
    const float* x          = (const float*)d_in[0];
    const float* norm1_w    = (const float*)d_in[1];
    const float* norm1_b    = (const float*)d_in[2];
    const float* qkv_w      = (const float*)d_in[3];
    const float* qkv_b      = (const float*)d_in[4];
    const float* bias_table = (const float*)d_in[5];
    const float* proj_w     = (const float*)d_in[6];
    const float* proj_b     = (const float*)d_in[7];
    const float* norm2_w    = (const float*)d_in[8];
    const float* norm2_b    = (const float*)d_in[9];
    const float* fc1_w      = (const float*)d_in[10];
    const float* fc1_b      = (const float*)d_in[11];
    const float* fc2_w      = (const float*)d_in[12];
    const float* fc2_b      = (const float*)d_in[13];
    const int*   rel_index  = (const int*)d_in[14];
    float* out = (float*)d_out;

    bf16 *p_xw, *p_qkv, *p_attn, *p_h;
    bf16 *p_wq, *p_wp, *p_w1, *p_w2;
    float *p_x2;
    cudaGetSymbolAddress((void**)&p_xw,   g_xw);
    cudaGetSymbolAddress((void**)&p_qkv,  g_qkv);
    cudaGetSymbolAddress((void**)&p_attn, g_attn);
    cudaGetSymbolAddress((void**)&p_x2,   g_x2);
    cudaGetSymbolAddress((void**)&p_h,    g_h);
    cudaGetSymbolAddress((void**)&p_wq,   g_wq);
    cudaGetSymbolAddress((void**)&p_wp,   g_wp);
    cudaGetSymbolAddress((void**)&p_w1,   g_w1);
    cudaGetSymbolAddress((void**)&p_w2,   g_w2);

    const int GEMM_SMEM = 3 * G_STAGE * (int)sizeof(bf16);   // 61440
    const int ATTN_SMEM = ATTN_ELEMS * (int)sizeof(bf16);    // 28160
    cudaFuncSetAttribute((const void*)gemm_kernel<0,128>, cudaFuncAttributeMaxDynamicSharedMemorySize, GEMM_SMEM);
    cudaFuncSetAttribute((const void*)gemm_kernel<1,128>, cudaFuncAttributeMaxDynamicSharedMemorySize, GEMM_SMEM);
    cudaFuncSetAttribute((const void*)gemm_kernel<2,128>, cudaFuncAttributeMaxDynamicSharedMemorySize, GEMM_SMEM);
    cudaFuncSetAttribute((const void*)gemm_kernel<3,512>, cudaFuncAttributeMaxDynamicSharedMemorySize, GEMM_SMEM);
    cudaFuncSetAttribute((const void*)attn_kernel,        cudaFuncAttributeMaxDynamicSharedMemorySize, ATTN_SMEM);

    // 0) merged setup + LN1
    setup_ln1_kernel<<<LN_BLOCKS + SETUP_BLOCKS, 256>>>(
        x, norm1_w, norm1_b, qkv_w, proj_w, fc1_w, fc2_w, bias_table, rel_index);

    // 1) QKV gemm (+ q scale), bf16 out
    gemm_kernel<0,128><<<dim3(QKVN / 128, TOK / 128), 256, GEMM_SMEM>>>(
        p_xw, p_wq, qkv_b, nullptr, nullptr, nullptr, p_qkv, QKVN);

    // 2) window attention (7-warp, register-P, cp.async, bf16 bias)
    attn_kernel<<<dim3(NWIN, NH), ATHREADS, ATTN_SMEM>>>();

    // 3) proj gemm + window reverse + residual(x) -> g_x2 (fp32) + fused LN2 -> g_xw (bf16)
    gemm_kernel<1,128><<<dim3(CDIM / 128, TOK / 128), 256, GEMM_SMEM>>>(
        p_attn, p_wp, proj_b, x, norm2_w, norm2_b, p_x2, CDIM);

    // 4) fc1 + exact GELU, bf16 out
    gemm_kernel<2,128><<<dim3(CH / 128, TOK / 128), 256, GEMM_SMEM>>>(
        p_xw, p_w1, fc1_b, nullptr, nullptr, nullptr, p_h, CH);

    // 5) fc2 + residual(g_x2) -> d_out (fp32)
    gemm_kernel<3,512><<<dim3(CDIM / 128, TOK / 128), 256, GEMM_SMEM>>>(
        p_h, p_w2, fc2_b, p_x2, nullptr, nullptr, out, CDIM);

    (void)in_sizes; (void)n_in; (void)out_size;
}